// round 2
// baseline (speedup 1.0000x reference)
#include <cuda_runtime.h>
#include <math.h>

// ---------------- problem constants ----------------
#define RESV   32
#define L_TOT  (RESV*RESV*RESV)      // 32768
#define BATCH  2
#define CDIM   288
#define QKV_N  (3*CDIM)              // 864
#define NROWS  (BATCH*L_TOT)         // 65536
#define HB     4
#define HDIM   24
#define NWIN   16                    // tokens per window
#define TBIAS  63                    // rel table rows per branch
#define PDIM   6

// scratch (no cudaMalloc allowed)
__device__ float g_qkv[(size_t)NROWS * QKV_N];   // (B*L, 864)
__device__ float g_y  [(size_t)NROWS * CDIM];    // att + lcm
__device__ float g_bias[3 * HB * NWIN * NWIN];   // (branch, head, n, m)

__constant__ int c_Dsp[3] = {2, 2, 2};
__constant__ int c_Hsp[3] = {2, 2, 4};
__constant__ int c_Wsp[3] = {4, 4, 2};

// ---------------- SGEMM: C = A(MxK) * B(KxN) (+bias) ----------------
// Exact-fit tiles: BM=128, BN=96, BK=32; M%128==0, N%96==0, K%32==0 for both GEMMs.
#define BM 128
#define BN 96
#define BK 32

__global__ __launch_bounds__(256)
void sgemm_kernel(const float* __restrict__ A, const float* __restrict__ Bm,
                  float* __restrict__ C, const float* __restrict__ bias,
                  int M, int N, int K) {
    __shared__ float As[BK][BM + 5];   // transposed, padded (conflict-free stores)
    __shared__ float Bs[BK][BN];

    const int tid = threadIdx.x;
    const int tx = tid & 15;           // 0..15 -> 6 cols
    const int ty = tid >> 4;           // 0..15 -> 8 rows
    const int m0 = blockIdx.y * BM;
    const int n0 = blockIdx.x * BN;

    const int a_row = tid >> 3;        // 0..31
    const int a_k4  = (tid & 7) * 4;   // 0,4,...,28

    float acc[8][6];
#pragma unroll
    for (int i = 0; i < 8; i++)
#pragma unroll
        for (int j = 0; j < 6; j++) acc[i][j] = 0.0f;

    for (int k0 = 0; k0 < K; k0 += BK) {
        // load A tile (128x32), store transposed
#pragma unroll
        for (int j = 0; j < 4; j++) {
            int m = a_row + 32 * j;
            float4 av = *(const float4*)(A + (size_t)(m0 + m) * K + k0 + a_k4);
            As[a_k4 + 0][m] = av.x;
            As[a_k4 + 1][m] = av.y;
            As[a_k4 + 2][m] = av.z;
            As[a_k4 + 3][m] = av.w;
        }
        // load B tile (32x96)
#pragma unroll
        for (int j = 0; j < 3; j++) {
            int v  = tid + 256 * j;        // 0..767
            int br = v / 24;
            int bc = (v - br * 24) * 4;
            float4 bv = *(const float4*)(Bm + (size_t)(k0 + br) * N + n0 + bc);
            *(float4*)(&Bs[br][bc]) = bv;
        }
        __syncthreads();

#pragma unroll
        for (int k = 0; k < BK; k++) {
            float a[8], b[6];
#pragma unroll
            for (int i = 0; i < 8; i++) a[i] = As[k][ty * 8 + i];
#pragma unroll
            for (int j = 0; j < 6; j++) b[j] = Bs[k][tx * 6 + j];
#pragma unroll
            for (int i = 0; i < 8; i++)
#pragma unroll
                for (int j = 0; j < 6; j++) acc[i][j] = fmaf(a[i], b[j], acc[i][j]);
        }
        __syncthreads();
    }

    // epilogue
    float bv[6];
#pragma unroll
    for (int j = 0; j < 6; j++) bv[j] = bias ? bias[n0 + tx * 6 + j] : 0.0f;
#pragma unroll
    for (int i = 0; i < 8; i++) {
        float* crow = C + (size_t)(m0 + ty * 8 + i) * N + n0 + tx * 6;
#pragma unroll
        for (int j = 0; j < 6; j++) crow[j] = acc[i][j] + bv[j];
    }
}

// ---------------- RPE-bias MLP (tiny) ----------------
__device__ __forceinline__ void ln_relu6(float* h, const float* g, const float* b) {
    float m = 0.f;
#pragma unroll
    for (int j = 0; j < 6; j++) m += h[j];
    m *= (1.0f / 6.0f);
    float v = 0.f;
#pragma unroll
    for (int j = 0; j < 6; j++) { float d = h[j] - m; v += d * d; }
    v *= (1.0f / 6.0f);
    float inv = rsqrtf(v + 1e-5f);
#pragma unroll
    for (int j = 0; j < 6; j++) {
        float t = (h[j] - m) * inv * g[j] + b[j];
        h[j] = t > 0.f ? t : 0.f;
    }
}

__global__ void biasmlp_kernel(const float* __restrict__ rpe,
                               const float* __restrict__ pw, const float* __restrict__ pb,
                               const float* __restrict__ g1, const float* __restrict__ be1,
                               const float* __restrict__ w1, const float* __restrict__ b1,
                               const float* __restrict__ g2, const float* __restrict__ be2,
                               const float* __restrict__ w2, const float* __restrict__ b2,
                               const float* __restrict__ g3, const float* __restrict__ be3,
                               const float* __restrict__ w3, const float* __restrict__ b3,
                               const int* __restrict__ relidx,
                               float* __restrict__ biasb) {
    int bi = blockIdx.x;
    int t = threadIdx.x;
    __shared__ float p[TBIAS][HB];

    if (t < TBIAS) {
        float h[6], tmp[6];
        const float* r = rpe + (bi * TBIAS + t) * 3;
        float r0 = r[0], r1 = r[1], r2 = r[2];
#pragma unroll
        for (int j = 0; j < 6; j++)
            h[j] = pb[bi * 6 + j]
                 + r0 * pw[(bi * 3 + 0) * 6 + j]
                 + r1 * pw[(bi * 3 + 1) * 6 + j]
                 + r2 * pw[(bi * 3 + 2) * 6 + j];

        // block 1
        ln_relu6(h, g1 + bi * 6, be1 + bi * 6);
#pragma unroll
        for (int j = 0; j < 6; j++) {
            float s = b1[bi * 6 + j];
#pragma unroll
            for (int i = 0; i < 6; i++) s += h[i] * w1[(bi * 6 + i) * 6 + j];
            tmp[j] = s;
        }
#pragma unroll
        for (int j = 0; j < 6; j++) h[j] = tmp[j];

        // block 2
        ln_relu6(h, g2 + bi * 6, be2 + bi * 6);
#pragma unroll
        for (int j = 0; j < 6; j++) {
            float s = b2[bi * 6 + j];
#pragma unroll
            for (int i = 0; i < 6; i++) s += h[i] * w2[(bi * 6 + i) * 6 + j];
            tmp[j] = s;
        }
#pragma unroll
        for (int j = 0; j < 6; j++) h[j] = tmp[j];

        // block 3 (6 -> HB)
        ln_relu6(h, g3 + bi * 6, be3 + bi * 6);
#pragma unroll
        for (int j = 0; j < HB; j++) {
            float s = b3[bi * HB + j];
#pragma unroll
            for (int i = 0; i < 6; i++) s += h[i] * w3[(bi * 6 + i) * HB + j];
            p[t][j] = s;
        }
    }
    __syncthreads();

    for (int i = t; i < HB * NWIN * NWIN; i += blockDim.x) {
        int hb = i >> 8;
        int nm = i & 255;
        biasb[bi * (HB * NWIN * NWIN) + i] = p[relidx[bi * 256 + nm]][hb];
    }
}

// ---------------- windowed attention ----------------
// One block per (window, batch, branch); 64 threads = (head, n). q in regs, k/v in smem.
__global__ __launch_bounds__(64)
void attn_kernel(const float* __restrict__ qkv, const float* __restrict__ biasb,
                 float* __restrict__ y) {
    const int bi = blockIdx.z;
    const int b  = blockIdx.y;
    const int Dsp = c_Dsp[bi], Hsp = c_Hsp[bi], Wsp = c_Wsp[bi];
    const int nH = RESV / Hsp, nW = RESV / Wsp;
    int widx = blockIdx.x;
    int wblk = widx % nW; int tmp = widx / nW;
    int hblk = tmp % nH;  int dblk = tmp / nH;

    const int t  = threadIdx.x;       // 0..63
    const int hb = t >> 4;
    const int n  = t & 15;
    const int HW = Hsp * Wsp;
    int dd = n / HW; int r = n - dd * HW;
    int hh = r / Wsp; int ww = r - hh * Wsp;
    int l = ((dblk * Dsp + dd) * RESV + hblk * Hsp + hh) * RESV + wblk * Wsp + ww;

    size_t rowbase = ((size_t)b * L_TOT + l) * QKV_N + bi * 96 + hb * HDIM;

    __shared__ float sk[64][25];
    __shared__ float sv[64][25];
    float q[HDIM];
    const float scale = 0.2041241452319315f;  // 24^-0.5

    const float4* qp = (const float4*)(qkv + rowbase);
    const float4* kp = (const float4*)(qkv + rowbase + CDIM);
    const float4* vp = (const float4*)(qkv + rowbase + 2 * CDIM);
#pragma unroll
    for (int j = 0; j < 6; j++) {
        float4 a = qp[j];
        q[4*j+0] = a.x * scale; q[4*j+1] = a.y * scale;
        q[4*j+2] = a.z * scale; q[4*j+3] = a.w * scale;
        float4 kk = kp[j];
        sk[t][4*j+0] = kk.x; sk[t][4*j+1] = kk.y; sk[t][4*j+2] = kk.z; sk[t][4*j+3] = kk.w;
        float4 vv = vp[j];
        sv[t][4*j+0] = vv.x; sv[t][4*j+1] = vv.y; sv[t][4*j+2] = vv.z; sv[t][4*j+3] = vv.w;
    }
    __syncthreads();

    const float* brow = biasb + (((size_t)bi * HB + hb) * NWIN + n) * NWIN;
    float lg[NWIN];
    float mx = -1e30f;
#pragma unroll
    for (int m = 0; m < NWIN; m++) {
        float s = brow[m];
        const float* kr = sk[hb * 16 + m];
#pragma unroll
        for (int e = 0; e < HDIM; e++) s = fmaf(q[e], kr[e], s);
        lg[m] = s;
        mx = fmaxf(mx, s);
    }
    float sum = 0.f;
#pragma unroll
    for (int m = 0; m < NWIN; m++) { lg[m] = expf(lg[m] - mx); sum += lg[m]; }
    float inv = 1.0f / sum;

    float o[HDIM];
#pragma unroll
    for (int e = 0; e < HDIM; e++) o[e] = 0.f;
#pragma unroll
    for (int m = 0; m < NWIN; m++) {
        float w = lg[m] * inv;
        const float* vr = sv[hb * 16 + m];
#pragma unroll
        for (int e = 0; e < HDIM; e++) o[e] = fmaf(w, vr[e], o[e]);
    }

    float* yp = y + ((size_t)b * L_TOT + l) * CDIM + bi * 96 + hb * HDIM;
#pragma unroll
    for (int e = 0; e < HDIM; e++) yp[e] = o[e];
}

// ---------------- depthwise 3x3x3 conv over v, accumulate into y ----------------
__global__ __launch_bounds__(CDIM)
void conv_kernel(const float* __restrict__ qkv, const float* __restrict__ cw,
                 const float* __restrict__ cb, float* __restrict__ y) {
    const int c = threadIdx.x;       // 0..287
    const int h = blockIdx.x, d = blockIdx.y, b = blockIdx.z;

    float wt[27];
#pragma unroll
    for (int j = 0; j < 27; j++) wt[j] = cw[c * 27 + j];
    const float bias = cb[c];

    for (int w = 0; w < RESV; w++) {
        float acc = bias;
#pragma unroll
        for (int kd = 0; kd < 3; kd++) {
            int dd = d + kd - 1;
            if (dd < 0 || dd >= RESV) continue;
#pragma unroll
            for (int kh = 0; kh < 3; kh++) {
                int hh = h + kh - 1;
                if (hh < 0 || hh >= RESV) continue;
#pragma unroll
                for (int kw = 0; kw < 3; kw++) {
                    int ww = w + kw - 1;
                    if (ww < 0 || ww >= RESV) continue;
                    size_t l = ((size_t)dd * RESV + hh) * RESV + ww;
                    acc = fmaf(wt[(kd * 3 + kh) * 3 + kw],
                               qkv[((size_t)b * L_TOT + l) * QKV_N + 2 * CDIM + c], acc);
                }
            }
        }
        size_t l = ((size_t)d * RESV + h) * RESV + w;
        size_t idx = ((size_t)b * L_TOT + l) * CDIM + c;
        y[idx] += acc;
    }
}

// ---------------- launch ----------------
extern "C" void kernel_launch(void* const* d_in, const int* in_sizes, int n_in,
                              void* d_out, int out_size) {
    const float* x      = (const float*)d_in[0];
    const float* w_qkv  = (const float*)d_in[4];
    const float* w_proj = (const float*)d_in[5];
    const float* b_proj = (const float*)d_in[6];
    const float* conv_w = (const float*)d_in[7];
    const float* conv_b = (const float*)d_in[8];
    const float* pos_w  = (const float*)d_in[9];
    const float* pos_b  = (const float*)d_in[10];
    const float* ln1g   = (const float*)d_in[11];
    const float* ln1b   = (const float*)d_in[12];
    const float* lin1w  = (const float*)d_in[13];
    const float* lin1b  = (const float*)d_in[14];
    const float* ln2g   = (const float*)d_in[15];
    const float* ln2b   = (const float*)d_in[16];
    const float* lin2w  = (const float*)d_in[17];
    const float* lin2b  = (const float*)d_in[18];
    const float* ln3g   = (const float*)d_in[19];
    const float* ln3b   = (const float*)d_in[20];
    const float* lin3w  = (const float*)d_in[21];
    const float* lin3b  = (const float*)d_in[22];
    const float* rpe    = (const float*)d_in[23];
    const int*   relidx = (const int*)d_in[24];
    float* out = (float*)d_out;

    float *qkvp, *yp, *bp;
    cudaGetSymbolAddress((void**)&qkvp, g_qkv);
    cudaGetSymbolAddress((void**)&yp,   g_y);
    cudaGetSymbolAddress((void**)&bp,   g_bias);

    // 1) qkv = x @ w_qkv
    sgemm_kernel<<<dim3(QKV_N / BN, NROWS / BM), 256>>>(x, w_qkv, qkvp, nullptr,
                                                        NROWS, QKV_N, CDIM);
    // 2) RPE bias tables
    biasmlp_kernel<<<3, 64>>>(rpe, pos_w, pos_b,
                              ln1g, ln1b, lin1w, lin1b,
                              ln2g, ln2b, lin2w, lin2b,
                              ln3g, ln3b, lin3w, lin3b,
                              relidx, bp);
    // 3) windowed attention -> y
    attn_kernel<<<dim3(2048, BATCH, 3), 64>>>(qkvp, bp, yp);
    // 4) depthwise conv(v) += y
    conv_kernel<<<dim3(RESV, RESV, BATCH), CDIM>>>(qkvp, conv_w, conv_b, yp);
    // 5) out = y @ w_proj + b_proj
    sgemm_kernel<<<dim3(CDIM / BN, NROWS / BM), 256>>>(yp, w_proj, out, b_proj,
                                                       NROWS, CDIM, CDIM);
}

// round 4
// speedup vs baseline: 2.6904x; 2.6904x over previous
#include <cuda_runtime.h>
#include <math.h>
#include <stdint.h>

// ---------------- problem constants ----------------
#define RESV   32
#define L_TOT  (RESV*RESV*RESV)      // 32768
#define BATCH  2
#define CDIM   288
#define QKV_N  (3*CDIM)              // 864
#define NROWS  (BATCH*L_TOT)         // 65536
#define HB     4
#define HDIM   24
#define NWIN   16
#define TBIAS  63

// scratch (no cudaMalloc allowed)
__device__ float g_qkv [(size_t)NROWS * QKV_N];         // (B*L, 864)
__device__ float g_y   [(size_t)NROWS * CDIM];          // attention output
__device__ float g_vc  [(size_t)BATCH * CDIM * L_TOT];  // v, channel-major [b][c][l]
__device__ float g_lcm [(size_t)BATCH * CDIM * L_TOT];  // conv output, channel-major
__device__ float g_wqkvT[(size_t)QKV_N * CDIM];         // w_qkv^T  (864, 288)
__device__ float g_wprojT[(size_t)CDIM * CDIM];         // w_proj^T (288, 288)
__device__ float g_bias[3 * HB * NWIN * NWIN];

__constant__ int c_Dsp[3] = {2, 2, 2};
__constant__ int c_Hsp[3] = {2, 2, 4};
__constant__ int c_Wsp[3] = {4, 4, 2};

// ==================== tf32 helpers ====================
__device__ __forceinline__ uint32_t f2tf32(float f) {
    uint32_t r;
    asm("cvt.rna.tf32.f32 %0, %1;" : "=r"(r) : "f"(f));
    return r;
}

__device__ __forceinline__ void mma8(float* d,
                                     uint32_t a0, uint32_t a1, uint32_t a2, uint32_t a3,
                                     uint32_t b0, uint32_t b1) {
    asm volatile("mma.sync.aligned.m16n8k8.row.col.f32.tf32.tf32.f32 "
                 "{%0,%1,%2,%3}, {%4,%5,%6,%7}, {%8,%9}, {%0,%1,%2,%3};"
                 : "+f"(d[0]), "+f"(d[1]), "+f"(d[2]), "+f"(d[3])
                 : "r"(a0), "r"(a1), "r"(a2), "r"(a3), "r"(b0), "r"(b1));
}

// ==================== mma.sync tf32 GEMM ====================
// C[M, N] = A[M, 288] * Bt[N, 288]^T ; BM=128, BN=96, BK=32, 9 K-chunks.
// HAS_LCM: A' = A + lcm^T (lcm channel-major). HAS_VC: write v cols transposed
// into vc (channel-major). HAS_BIAS: add bias on C.
//
// smem float offsets (stride 36 = 4 mod 32 -> conflict-free fragment LDS)
#define OFF_A0  0
#define OFF_A1  4608          // 128*36
#define OFF_B0  9216
#define OFF_B1  12672         // + 96*36
#define OFF_LS0 16128
#define OFF_LS1 20352         // + 32*132
#define SMEM_G1 (16128 * 4)   // 64512 B
#define SMEM_G2 (24576 * 4)   // 98304 B

template<bool HAS_LCM, bool HAS_VC, bool HAS_BIAS>
__global__ __launch_bounds__(256)
void gemm_mma(const float* __restrict__ A, const float* __restrict__ Bt,
              float* __restrict__ C, int ldc, const float* __restrict__ bias,
              const float* __restrict__ lcm, float* __restrict__ vc) {
    extern __shared__ float smf[];
    const int tid  = threadIdx.x;
    const int lane = tid & 31, warp = tid >> 5;
    const int wm = warp & 3, wn = warp >> 2;      // warp tile: rows wm*32, cols wn*48
    const int m0 = blockIdx.y * 128, n0 = blockIdx.x * 96;
    const int bb = m0 >> 15;                       // batch
    const int l0 = m0 & (L_TOT - 1);               // l offset within batch

    float acc[2][6][4];
#pragma unroll
    for (int mt = 0; mt < 2; mt++)
#pragma unroll
        for (int nt = 0; nt < 6; nt++)
#pragma unroll
            for (int r = 0; r < 4; r++) acc[mt][nt][r] = 0.0f;

    float4 ra[4], rb[3], rl[4];

    // ---- global loads for chunk `k0` into registers ----
#define G_LOADS(K0) do { \
        if (HAS_LCM) { \
            _Pragma("unroll") \
            for (int i = 0; i < 4; i++) { \
                int idx = tid + i * 256; int cc = idx >> 5, l4 = (idx & 31) * 4; \
                rl[i] = *(const float4*)(lcm + ((size_t)bb * CDIM + (K0) + cc) * L_TOT + l0 + l4); \
            } \
        } \
        _Pragma("unroll") \
        for (int i = 0; i < 4; i++) { \
            int idx = tid + i * 256; int m = idx >> 3, k4 = idx & 7; \
            ra[i] = *(const float4*)(A + (size_t)(m0 + m) * CDIM + (K0) + k4 * 4); \
        } \
        _Pragma("unroll") \
        for (int i = 0; i < 3; i++) { \
            int idx = tid + i * 256; int n = idx >> 3, k4 = idx & 7; \
            rb[i] = *(const float4*)(Bt + (size_t)(n0 + n) * CDIM + (K0) + k4 * 4); \
        } \
    } while (0)

    // ---- store staged registers into smem buffer `BUF` ----
#define S_STORES(BUF) do { \
        float* As_ = smf + ((BUF) ? OFF_A1 : OFF_A0); \
        float* Bs_ = smf + ((BUF) ? OFF_B1 : OFF_B0); \
        float* LS_ = smf + ((BUF) ? OFF_LS1 : OFF_LS0); \
        if (HAS_LCM) { \
            _Pragma("unroll") \
            for (int i = 0; i < 4; i++) { \
                int idx = tid + i * 256; int cc = idx >> 5, l4 = (idx & 31) * 4; \
                *(float4*)(LS_ + cc * 132 + l4) = rl[i]; \
            } \
            __syncthreads(); \
        } \
        _Pragma("unroll") \
        for (int i = 0; i < 4; i++) { \
            int idx = tid + i * 256; int m = idx >> 3, k4 = idx & 7; \
            float4 v = ra[i]; \
            if (HAS_LCM) { \
                v.x += LS_[(k4 * 4 + 0) * 132 + m]; \
                v.y += LS_[(k4 * 4 + 1) * 132 + m]; \
                v.z += LS_[(k4 * 4 + 2) * 132 + m]; \
                v.w += LS_[(k4 * 4 + 3) * 132 + m]; \
            } \
            uint4 u = make_uint4(f2tf32(v.x), f2tf32(v.y), f2tf32(v.z), f2tf32(v.w)); \
            *(uint4*)(As_ + m * 36 + k4 * 4) = u; \
        } \
        _Pragma("unroll") \
        for (int i = 0; i < 3; i++) { \
            int idx = tid + i * 256; int n = idx >> 3, k4 = idx & 7; \
            float4 v = rb[i]; \
            uint4 u = make_uint4(f2tf32(v.x), f2tf32(v.y), f2tf32(v.z), f2tf32(v.w)); \
            *(uint4*)(Bs_ + n * 36 + k4 * 4) = u; \
        } \
    } while (0)

    // prologue: chunk 0 -> buf 0
    G_LOADS(0);
    S_STORES(0);
    __syncthreads();

    const int qr = lane >> 2, qc = lane & 3;

#pragma unroll 1
    for (int ch = 0; ch < 9; ch++) {
        const int cur = ch & 1;
        if (ch < 8) G_LOADS((ch + 1) * 32);

        // compute from buf cur
        const float* As = smf + (cur ? OFF_A1 : OFF_A0);
        const float* Bs = smf + (cur ? OFF_B1 : OFF_B0);
#pragma unroll
        for (int s = 0; s < 4; s++) {
            const int k = s * 8;
            uint32_t af[2][4];
#pragma unroll
            for (int mt = 0; mt < 2; mt++) {
                int r0 = (wm * 32 + mt * 16 + qr) * 36 + k + qc;
                af[mt][0] = __float_as_uint(As[r0]);
                af[mt][1] = __float_as_uint(As[r0 + 8 * 36]);
                af[mt][2] = __float_as_uint(As[r0 + 4]);
                af[mt][3] = __float_as_uint(As[r0 + 8 * 36 + 4]);
            }
            uint32_t bf[6][2];
#pragma unroll
            for (int nt = 0; nt < 6; nt++) {
                int c0 = (wn * 48 + nt * 8 + qr) * 36 + k + qc;
                bf[nt][0] = __float_as_uint(Bs[c0]);
                bf[nt][1] = __float_as_uint(Bs[c0 + 4]);
            }
#pragma unroll
            for (int mt = 0; mt < 2; mt++)
#pragma unroll
                for (int nt = 0; nt < 6; nt++)
                    mma8(acc[mt][nt], af[mt][0], af[mt][1], af[mt][2], af[mt][3],
                         bf[nt][0], bf[nt][1]);
        }

        if (ch < 8) {
            S_STORES(cur ^ 1);
            __syncthreads();
        }
    }
#undef G_LOADS
#undef S_STORES

    // ==================== epilogue ====================
    __syncthreads();                 // all compute done; stage overlaps A buffers
    float* stg = smf;                // [128][100]
#pragma unroll
    for (int mt = 0; mt < 2; mt++) {
        int r0 = wm * 32 + mt * 16 + qr;
#pragma unroll
        for (int nt = 0; nt < 6; nt++) {
            int c0 = wn * 48 + nt * 8 + 2 * qc;
            stg[r0 * 100 + c0]           = acc[mt][nt][0];
            stg[r0 * 100 + c0 + 1]       = acc[mt][nt][1];
            stg[(r0 + 8) * 100 + c0]     = acc[mt][nt][2];
            stg[(r0 + 8) * 100 + c0 + 1] = acc[mt][nt][3];
        }
    }
    __syncthreads();

    // coalesced C writes: 128 rows x 24 float4
#pragma unroll
    for (int i = 0; i < 12; i++) {
        int idx = tid + i * 256;
        int r = idx / 24, q = idx - r * 24;
        float4 o = *(const float4*)(stg + r * 100 + q * 4);
        if (HAS_BIAS) {
            const float* bp = bias + n0 + q * 4;
            o.x += bp[0]; o.y += bp[1]; o.z += bp[2]; o.w += bp[3];
        }
        *(float4*)(C + (size_t)(m0 + r) * ldc + n0 + q * 4) = o;
    }

    if (HAS_VC && n0 >= 2 * CDIM) {
        const int s = tid & 3;
#pragma unroll
        for (int j0 = 0; j0 < 96; j0 += 64) {
            int j = j0 + (tid >> 2);
            if (j < 96) {
                int cg = n0 + j - 2 * CDIM;
                float* vp = vc + ((size_t)bb * CDIM + cg) * L_TOT + l0 + s * 32;
#pragma unroll
                for (int i8 = 0; i8 < 8; i8++) {
                    int r = s * 32 + i8 * 4;
                    float4 o;
                    o.x = stg[(r + 0) * 100 + j];
                    o.y = stg[(r + 1) * 100 + j];
                    o.z = stg[(r + 2) * 100 + j];
                    o.w = stg[(r + 3) * 100 + j];
                    *(float4*)(vp + i8 * 4) = o;
                }
            }
        }
    }
}

// ==================== weight transpose ====================
__global__ void transpose_kernel(const float* __restrict__ in, float* __restrict__ out,
                                 int R, int Cc) {   // in (R, Cc) -> out (Cc, R)
    __shared__ float t[32][33];
    int bx = blockIdx.x * 32, by = blockIdx.y * 32;
    int x = threadIdx.x, y = threadIdx.y;
#pragma unroll
    for (int j = 0; j < 4; j++) t[y + 8 * j][x] = in[(size_t)(by + y + 8 * j) * Cc + bx + x];
    __syncthreads();
#pragma unroll
    for (int j = 0; j < 4; j++) out[(size_t)(bx + y + 8 * j) * R + by + x] = t[x][y + 8 * j];
}

// ==================== RPE-bias MLP ====================
__device__ __forceinline__ void ln_relu6(float* h, const float* g, const float* b) {
    float m = 0.f;
#pragma unroll
    for (int j = 0; j < 6; j++) m += h[j];
    m *= (1.0f / 6.0f);
    float v = 0.f;
#pragma unroll
    for (int j = 0; j < 6; j++) { float d = h[j] - m; v += d * d; }
    v *= (1.0f / 6.0f);
    float inv = rsqrtf(v + 1e-5f);
#pragma unroll
    for (int j = 0; j < 6; j++) {
        float t = (h[j] - m) * inv * g[j] + b[j];
        h[j] = t > 0.f ? t : 0.f;
    }
}

__global__ void biasmlp_kernel(const float* __restrict__ rpe,
                               const float* __restrict__ pw, const float* __restrict__ pb,
                               const float* __restrict__ g1, const float* __restrict__ be1,
                               const float* __restrict__ w1, const float* __restrict__ b1,
                               const float* __restrict__ g2, const float* __restrict__ be2,
                               const float* __restrict__ w2, const float* __restrict__ b2,
                               const float* __restrict__ g3, const float* __restrict__ be3,
                               const float* __restrict__ w3, const float* __restrict__ b3,
                               const int* __restrict__ relidx,
                               float* __restrict__ biasb) {
    int bi = blockIdx.x;
    int t = threadIdx.x;
    __shared__ float p[TBIAS][HB];

    if (t < TBIAS) {
        float h[6], tmp[6];
        const float* r = rpe + (bi * TBIAS + t) * 3;
        float r0 = r[0], r1 = r[1], r2 = r[2];
#pragma unroll
        for (int j = 0; j < 6; j++)
            h[j] = pb[bi * 6 + j]
                 + r0 * pw[(bi * 3 + 0) * 6 + j]
                 + r1 * pw[(bi * 3 + 1) * 6 + j]
                 + r2 * pw[(bi * 3 + 2) * 6 + j];
        ln_relu6(h, g1 + bi * 6, be1 + bi * 6);
#pragma unroll
        for (int j = 0; j < 6; j++) {
            float s = b1[bi * 6 + j];
#pragma unroll
            for (int i = 0; i < 6; i++) s += h[i] * w1[(bi * 6 + i) * 6 + j];
            tmp[j] = s;
        }
#pragma unroll
        for (int j = 0; j < 6; j++) h[j] = tmp[j];
        ln_relu6(h, g2 + bi * 6, be2 + bi * 6);
#pragma unroll
        for (int j = 0; j < 6; j++) {
            float s = b2[bi * 6 + j];
#pragma unroll
            for (int i = 0; i < 6; i++) s += h[i] * w2[(bi * 6 + i) * 6 + j];
            tmp[j] = s;
        }
#pragma unroll
        for (int j = 0; j < 6; j++) h[j] = tmp[j];
        ln_relu6(h, g3 + bi * 6, be3 + bi * 6);
#pragma unroll
        for (int j = 0; j < HB; j++) {
            float s = b3[bi * HB + j];
#pragma unroll
            for (int i = 0; i < 6; i++) s += h[i] * w3[(bi * 6 + i) * HB + j];
            p[t][j] = s;
        }
    }
    __syncthreads();

    for (int i = t; i < HB * NWIN * NWIN; i += blockDim.x) {
        int hb = i >> 8;
        int nm = i & 255;
        biasb[bi * (HB * NWIN * NWIN) + i] = p[relidx[bi * 256 + nm]][hb];
    }
}

// ==================== windowed attention ====================
__global__ __launch_bounds__(64)
void attn_kernel(const float* __restrict__ qkv, const float* __restrict__ biasb,
                 float* __restrict__ y) {
    const int bi = blockIdx.z;
    const int b  = blockIdx.y;
    const int Dsp = c_Dsp[bi], Hsp = c_Hsp[bi], Wsp = c_Wsp[bi];
    const int nH = RESV / Hsp, nW = RESV / Wsp;
    int widx = blockIdx.x;
    int wblk = widx % nW; int tmp = widx / nW;
    int hblk = tmp % nH;  int dblk = tmp / nH;

    const int t  = threadIdx.x;
    const int hb = t >> 4;
    const int n  = t & 15;
    const int HW = Hsp * Wsp;
    int dd = n / HW; int r = n - dd * HW;
    int hh = r / Wsp; int ww = r - hh * Wsp;
    int l = ((dblk * Dsp + dd) * RESV + hblk * Hsp + hh) * RESV + wblk * Wsp + ww;

    size_t rowbase = ((size_t)b * L_TOT + l) * QKV_N + bi * 96 + hb * HDIM;

    __shared__ float sk[64][25];
    __shared__ float sv[64][25];
    float q[HDIM];
    const float scale = 0.2041241452319315f;

    const float4* qp = (const float4*)(qkv + rowbase);
    const float4* kp = (const float4*)(qkv + rowbase + CDIM);
    const float4* vp = (const float4*)(qkv + rowbase + 2 * CDIM);
#pragma unroll
    for (int j = 0; j < 6; j++) {
        float4 a = qp[j];
        q[4*j+0] = a.x * scale; q[4*j+1] = a.y * scale;
        q[4*j+2] = a.z * scale; q[4*j+3] = a.w * scale;
        float4 kk = kp[j];
        sk[t][4*j+0] = kk.x; sk[t][4*j+1] = kk.y; sk[t][4*j+2] = kk.z; sk[t][4*j+3] = kk.w;
        float4 vv = vp[j];
        sv[t][4*j+0] = vv.x; sv[t][4*j+1] = vv.y; sv[t][4*j+2] = vv.z; sv[t][4*j+3] = vv.w;
    }
    __syncthreads();

    const float* brow = biasb + (((size_t)bi * HB + hb) * NWIN + n) * NWIN;
    float lg[NWIN];
    float mx = -1e30f;
#pragma unroll
    for (int m = 0; m < NWIN; m++) {
        float s = brow[m];
        const float* kr = sk[hb * 16 + m];
#pragma unroll
        for (int e = 0; e < HDIM; e++) s = fmaf(q[e], kr[e], s);
        lg[m] = s;
        mx = fmaxf(mx, s);
    }
    float sum = 0.f;
#pragma unroll
    for (int m = 0; m < NWIN; m++) { lg[m] = expf(lg[m] - mx); sum += lg[m]; }
    float inv = 1.0f / sum;

    float o[HDIM];
#pragma unroll
    for (int e = 0; e < HDIM; e++) o[e] = 0.f;
#pragma unroll
    for (int m = 0; m < NWIN; m++) {
        float w = lg[m] * inv;
        const float* vr = sv[hb * 16 + m];
#pragma unroll
        for (int e = 0; e < HDIM; e++) o[e] = fmaf(w, vr[e], o[e]);
    }

    float* yp = y + ((size_t)b * L_TOT + l) * CDIM + bi * 96 + hb * HDIM;
#pragma unroll
    for (int e = 0; e < HDIM; e++) yp[e] = o[e];
}

// ==================== depthwise 3x3x3 conv (channel-major) ====================
__global__ __launch_bounds__(256)
void conv3d_kernel(const float* __restrict__ vc, const float* __restrict__ cw,
                   const float* __restrict__ cb, float* __restrict__ lcm) {
    const int bc = blockIdx.x;          // b*288 + c
    const int c = bc % CDIM;
    const float* src = vc + (size_t)bc * L_TOT;
    float* dst = lcm + (size_t)bc * L_TOT;

    float wt[27];
#pragma unroll
    for (int j = 0; j < 27; j++) wt[j] = cw[c * 27 + j];
    const float bias = cb[c];

    __shared__ float sp[3][34][36];
    const int tid = threadIdx.x;
    const int w = tid & 31;
    const int h0 = (tid >> 5) * 4;

    for (int i = tid; i < 3 * 34 * 36; i += 256) ((float*)sp)[i] = 0.f;
    __syncthreads();
#pragma unroll
    for (int jh = 0; jh < 4; jh++) {
        int h = h0 + jh;
        sp[0][1 + h][1 + w] = src[h * 32 + w];
        sp[1][1 + h][1 + w] = src[1024 + h * 32 + w];
    }
    __syncthreads();

#pragma unroll 1
    for (int d = 0; d < 32; d++) {
        const int bm = (d + 2) % 3;
        const int b0 = d % 3;
        const int bp = (d + 1) % 3;
        float acc[4] = {bias, bias, bias, bias};

#define TAPS(BUF, KD) { \
        const float (*P)[36] = sp[BUF]; \
        _Pragma("unroll") \
        for (int rr = 0; rr < 6; rr++) { \
            float va = P[h0 + rr][w], vb = P[h0 + rr][w + 1], vcx = P[h0 + rr][w + 2]; \
            _Pragma("unroll") \
            for (int jh = 0; jh < 4; jh++) { \
                int kh = rr - jh; \
                if (kh >= 0 && kh < 3) { \
                    acc[jh] = fmaf(wt[(KD)*9 + kh*3 + 0], va, \
                              fmaf(wt[(KD)*9 + kh*3 + 1], vb, \
                              fmaf(wt[(KD)*9 + kh*3 + 2], vcx, acc[jh]))); \
                } \
            } \
        } }

        if (d > 0)  TAPS(bm, 0);
        TAPS(b0, 1);
        if (d < 31) TAPS(bp, 2);
#undef TAPS

#pragma unroll
        for (int jh = 0; jh < 4; jh++)
            dst[d * 1024 + (h0 + jh) * 32 + w] = acc[jh];

        __syncthreads();
        if (d + 2 < 32) {
            const float* s2 = src + (d + 2) * 1024;
#pragma unroll
            for (int jh = 0; jh < 4; jh++) {
                int h = h0 + jh;
                sp[(d + 2) % 3][1 + h][1 + w] = s2[h * 32 + w];
            }
        }
        __syncthreads();
    }
}

// ==================== launch ====================
extern "C" void kernel_launch(void* const* d_in, const int* in_sizes, int n_in,
                              void* d_out, int out_size) {
    const float* x      = (const float*)d_in[0];
    const float* w_qkv  = (const float*)d_in[4];
    const float* w_proj = (const float*)d_in[5];
    const float* b_proj = (const float*)d_in[6];
    const float* conv_w = (const float*)d_in[7];
    const float* conv_b = (const float*)d_in[8];
    const float* pos_w  = (const float*)d_in[9];
    const float* pos_b  = (const float*)d_in[10];
    const float* ln1g   = (const float*)d_in[11];
    const float* ln1b   = (const float*)d_in[12];
    const float* lin1w  = (const float*)d_in[13];
    const float* lin1b  = (const float*)d_in[14];
    const float* ln2g   = (const float*)d_in[15];
    const float* ln2b   = (const float*)d_in[16];
    const float* lin2w  = (const float*)d_in[17];
    const float* lin2b  = (const float*)d_in[18];
    const float* ln3g   = (const float*)d_in[19];
    const float* ln3b   = (const float*)d_in[20];
    const float* lin3w  = (const float*)d_in[21];
    const float* lin3b  = (const float*)d_in[22];
    const float* rpe    = (const float*)d_in[23];
    const int*   relidx = (const int*)d_in[24];
    float* out = (float*)d_out;

    float *qkvp, *yp, *bp, *vcp, *lcmp, *wqkvT, *wprojT;
    cudaGetSymbolAddress((void**)&qkvp,   g_qkv);
    cudaGetSymbolAddress((void**)&yp,     g_y);
    cudaGetSymbolAddress((void**)&bp,     g_bias);
    cudaGetSymbolAddress((void**)&vcp,    g_vc);
    cudaGetSymbolAddress((void**)&lcmp,   g_lcm);
    cudaGetSymbolAddress((void**)&wqkvT,  g_wqkvT);
    cudaGetSymbolAddress((void**)&wprojT, g_wprojT);

    cudaFuncSetAttribute(gemm_mma<false, true, false>,
                         cudaFuncAttributeMaxDynamicSharedMemorySize, SMEM_G2);
    cudaFuncSetAttribute(gemm_mma<true, false, true>,
                         cudaFuncAttributeMaxDynamicSharedMemorySize, SMEM_G2);

    // 0) weight transposes
    transpose_kernel<<<dim3(QKV_N / 32, CDIM / 32), dim3(32, 8)>>>(w_qkv, wqkvT, CDIM, QKV_N);
    transpose_kernel<<<dim3(CDIM / 32, CDIM / 32), dim3(32, 8)>>>(w_proj, wprojT, CDIM, CDIM);

    // 1) qkv = x @ w_qkv  (also writes v channel-major into vc)
    gemm_mma<false, true, false><<<dim3(QKV_N / 96, NROWS / 128), 256, SMEM_G1>>>(
        x, wqkvT, qkvp, QKV_N, nullptr, nullptr, vcp);

    // 2) RPE bias tables
    biasmlp_kernel<<<3, 64>>>(rpe, pos_w, pos_b,
                              ln1g, ln1b, lin1w, lin1b,
                              ln2g, ln2b, lin2w, lin2b,
                              ln3g, ln3b, lin3w, lin3b,
                              relidx, bp);

    // 3) windowed attention -> y
    attn_kernel<<<dim3(2048, BATCH, 3), 64>>>(qkvp, bp, yp);

    // 4) depthwise conv(vc) -> lcm (channel-major)
    conv3d_kernel<<<BATCH * CDIM, 256>>>(vcp, conv_w, conv_b, lcmp);

    // 5) out = (y + lcm^T) @ w_proj + b_proj   (lcm fused into A-load)
    gemm_mma<true, false, true><<<dim3(CDIM / 96, NROWS / 128), 256, SMEM_G2>>>(
        yp, wprojT, out, CDIM, b_proj, lcmp, nullptr);
}

// round 5
// speedup vs baseline: 3.1349x; 1.1652x over previous
#include <cuda_runtime.h>
#include <cuda_fp16.h>
#include <math.h>
#include <stdint.h>

// ---------------- problem constants ----------------
#define RESV   32
#define L_TOT  (RESV*RESV*RESV)      // 32768
#define BATCH  2
#define CDIM   288
#define QKV_N  (3*CDIM)              // 864
#define NROWS  (BATCH*L_TOT)         // 65536
#define HB     4
#define HDIM   24
#define NWIN   16
#define TBIAS  63

// scratch (no cudaMalloc allowed)
__device__ float g_qkv [(size_t)NROWS * QKV_N];         // (B*L, 864)
__device__ float g_y   [(size_t)NROWS * CDIM];          // attention output
__device__ float g_vc  [(size_t)BATCH * CDIM * L_TOT];  // v, channel-major [b][c][l]
__device__ float g_lcm [(size_t)BATCH * CDIM * L_TOT];  // conv output, channel-major
__device__ float g_wqkvT[(size_t)QKV_N * CDIM];         // w_qkv^T  (864, 288)
__device__ float g_wprojT[(size_t)CDIM * CDIM];         // w_proj^T (288, 288)
__device__ float g_bias[3 * HB * NWIN * NWIN];

__constant__ int c_Dsp[3] = {2, 2, 2};
__constant__ int c_Hsp[3] = {2, 2, 4};
__constant__ int c_Wsp[3] = {4, 4, 2};

// ==================== fp16 mma helper ====================
__device__ __forceinline__ void mma16(float* d,
                                      uint32_t a0, uint32_t a1, uint32_t a2, uint32_t a3,
                                      uint32_t b0, uint32_t b1) {
    asm volatile("mma.sync.aligned.m16n8k16.row.col.f32.f16.f16.f32 "
                 "{%0,%1,%2,%3}, {%4,%5,%6,%7}, {%8,%9}, {%0,%1,%2,%3};"
                 : "+f"(d[0]), "+f"(d[1]), "+f"(d[2]), "+f"(d[3])
                 : "r"(a0), "r"(a1), "r"(a2), "r"(a3), "r"(b0), "r"(b1));
}

__device__ __forceinline__ uint32_t pack_h2(float x, float y) {
    __half2 h = __floats2half2_rn(x, y);
    return *(uint32_t*)&h;
}

// ==================== fp16 mma.sync GEMM ====================
// C[M, N] = A[M, 288] * Bt[N, 288]^T ; BM=128, BN=96, BK=32, 9 K-chunks.
// HAS_LCM: A' = A + lcm^T (lcm channel-major). HAS_VC: write v cols transposed
// into vc (channel-major). HAS_BIAS: add bias on C.
//
// smem half2 layout, row stride 20 half2 (=> lane bank = identity, conflict-free)
#define OFF_A0  0
#define OFF_A1  2560          // 128*20
#define OFF_B0  5120
#define OFF_B1  7040          // + 96*20
#define H2_TOT  8960          // total half2 for A+B bufs
#define OFF_LSF 8960          // float offset of lcm stage (32 x 132 floats)
#define SMEM_G1 51200         // bytes: max(35840 tiles, 51200 epilogue stage)
#define SMEM_G2 52736         // bytes: 35840 + 16896 lcm stage (epi 51200 fits)

template<bool HAS_LCM, bool HAS_VC, bool HAS_BIAS>
__global__ __launch_bounds__(256)
void gemm_mma(const float* __restrict__ A, const float* __restrict__ Bt,
              float* __restrict__ C, int ldc, const float* __restrict__ bias,
              const float* __restrict__ lcm, float* __restrict__ vc) {
    extern __shared__ float smf[];
    uint32_t* smh2 = (uint32_t*)smf;               // half2-pair view
    const int tid  = threadIdx.x;
    const int lane = tid & 31, warp = tid >> 5;
    const int wm = warp & 3, wn = warp >> 2;       // warp tile: rows wm*32, cols wn*48
    const int m0 = blockIdx.y * 128, n0 = blockIdx.x * 96;
    const int bb = m0 >> 15;                        // batch
    const int l0 = m0 & (L_TOT - 1);                // l offset within batch

    float acc[2][6][4];
#pragma unroll
    for (int mt = 0; mt < 2; mt++)
#pragma unroll
        for (int nt = 0; nt < 6; nt++)
#pragma unroll
            for (int r = 0; r < 4; r++) acc[mt][nt][r] = 0.0f;

    float4 ra[4], rb[3], rl[4];

    // ---- global loads for chunk `k0` into registers ----
#define G_LOADS(K0) do { \
        if (HAS_LCM) { \
            _Pragma("unroll") \
            for (int i = 0; i < 4; i++) { \
                int idx = tid + i * 256; int cc = idx >> 5, l4 = (idx & 31) * 4; \
                rl[i] = *(const float4*)(lcm + ((size_t)bb * CDIM + (K0) + cc) * L_TOT + l0 + l4); \
            } \
        } \
        _Pragma("unroll") \
        for (int i = 0; i < 4; i++) { \
            int idx = tid + i * 256; int m = idx >> 3, k4 = idx & 7; \
            ra[i] = *(const float4*)(A + (size_t)(m0 + m) * CDIM + (K0) + k4 * 4); \
        } \
        _Pragma("unroll") \
        for (int i = 0; i < 3; i++) { \
            int idx = tid + i * 256; int n = idx >> 3, k4 = idx & 7; \
            rb[i] = *(const float4*)(Bt + (size_t)(n0 + n) * CDIM + (K0) + k4 * 4); \
        } \
    } while (0)

    // ---- convert + store staged registers into smem buffer `BUF` ----
#define S_STORES(BUF) do { \
        uint32_t* As_ = smh2 + ((BUF) ? OFF_A1 : OFF_A0); \
        uint32_t* Bs_ = smh2 + ((BUF) ? OFF_B1 : OFF_B0); \
        float* LS_ = smf + OFF_LSF; \
        if (HAS_LCM) { \
            _Pragma("unroll") \
            for (int i = 0; i < 4; i++) { \
                int idx = tid + i * 256; int cc = idx >> 5, l4 = (idx & 31) * 4; \
                *(float4*)(LS_ + cc * 132 + l4) = rl[i]; \
            } \
            __syncthreads(); \
        } \
        _Pragma("unroll") \
        for (int i = 0; i < 4; i++) { \
            int idx = tid + i * 256; int m = idx >> 3, k4 = idx & 7; \
            float4 v = ra[i]; \
            if (HAS_LCM) { \
                v.x += LS_[(k4 * 4 + 0) * 132 + m]; \
                v.y += LS_[(k4 * 4 + 1) * 132 + m]; \
                v.z += LS_[(k4 * 4 + 2) * 132 + m]; \
                v.w += LS_[(k4 * 4 + 3) * 132 + m]; \
            } \
            uint2 u = make_uint2(pack_h2(v.x, v.y), pack_h2(v.z, v.w)); \
            *(uint2*)(As_ + m * 20 + k4 * 2) = u; \
        } \
        _Pragma("unroll") \
        for (int i = 0; i < 3; i++) { \
            int idx = tid + i * 256; int n = idx >> 3, k4 = idx & 7; \
            float4 v = rb[i]; \
            uint2 u = make_uint2(pack_h2(v.x, v.y), pack_h2(v.z, v.w)); \
            *(uint2*)(Bs_ + n * 20 + k4 * 2) = u; \
        } \
    } while (0)

    // prologue: chunk 0 -> buf 0
    G_LOADS(0);
    S_STORES(0);
    __syncthreads();

    const int qr = lane >> 2, qc = lane & 3;

#pragma unroll 1
    for (int ch = 0; ch < 9; ch++) {
        const int cur = ch & 1;
        if (ch < 8) G_LOADS((ch + 1) * 32);

        // compute from buf cur: 2 k16-steps x 12 MMAs
        const uint32_t* As = smh2 + (cur ? OFF_A1 : OFF_A0);
        const uint32_t* Bs = smh2 + (cur ? OFF_B1 : OFF_B0);
#pragma unroll
        for (int s = 0; s < 2; s++) {
            const int k8 = s * 8;                  // half2 offset within row
            uint32_t af[2][4];
#pragma unroll
            for (int mt = 0; mt < 2; mt++) {
                int r0 = (wm * 32 + mt * 16 + qr) * 20 + k8 + qc;
                af[mt][0] = As[r0];
                af[mt][1] = As[r0 + 8 * 20];
                af[mt][2] = As[r0 + 4];
                af[mt][3] = As[r0 + 8 * 20 + 4];
            }
            uint32_t bf[6][2];
#pragma unroll
            for (int nt = 0; nt < 6; nt++) {
                int c0 = (wn * 48 + nt * 8 + qr) * 20 + k8 + qc;
                bf[nt][0] = Bs[c0];
                bf[nt][1] = Bs[c0 + 4];
            }
#pragma unroll
            for (int mt = 0; mt < 2; mt++)
#pragma unroll
                for (int nt = 0; nt < 6; nt++)
                    mma16(acc[mt][nt], af[mt][0], af[mt][1], af[mt][2], af[mt][3],
                          bf[nt][0], bf[nt][1]);
        }

        if (ch < 8) {
            S_STORES(cur ^ 1);
            __syncthreads();
        }
    }
#undef G_LOADS
#undef S_STORES

    // ==================== epilogue ====================
    __syncthreads();                 // all compute done; stage overlaps tile buffers
    float* stg = smf;                // [128][100]
#pragma unroll
    for (int mt = 0; mt < 2; mt++) {
        int r0 = wm * 32 + mt * 16 + qr;
#pragma unroll
        for (int nt = 0; nt < 6; nt++) {
            int c0 = wn * 48 + nt * 8 + 2 * qc;
            stg[r0 * 100 + c0]           = acc[mt][nt][0];
            stg[r0 * 100 + c0 + 1]       = acc[mt][nt][1];
            stg[(r0 + 8) * 100 + c0]     = acc[mt][nt][2];
            stg[(r0 + 8) * 100 + c0 + 1] = acc[mt][nt][3];
        }
    }
    __syncthreads();

    // coalesced C writes: 128 rows x 24 float4
#pragma unroll
    for (int i = 0; i < 12; i++) {
        int idx = tid + i * 256;
        int r = idx / 24, q = idx - r * 24;
        float4 o = *(const float4*)(stg + r * 100 + q * 4);
        if (HAS_BIAS) {
            const float* bp = bias + n0 + q * 4;
            o.x += bp[0]; o.y += bp[1]; o.z += bp[2]; o.w += bp[3];
        }
        *(float4*)(C + (size_t)(m0 + r) * ldc + n0 + q * 4) = o;
    }

    if (HAS_VC && n0 >= 2 * CDIM) {
        const int s = tid & 3;
#pragma unroll
        for (int j0 = 0; j0 < 96; j0 += 64) {
            int j = j0 + (tid >> 2);
            if (j < 96) {
                int cg = n0 + j - 2 * CDIM;
                float* vp = vc + ((size_t)bb * CDIM + cg) * L_TOT + l0 + s * 32;
#pragma unroll
                for (int i8 = 0; i8 < 8; i8++) {
                    int r = s * 32 + i8 * 4;
                    float4 o;
                    o.x = stg[(r + 0) * 100 + j];
                    o.y = stg[(r + 1) * 100 + j];
                    o.z = stg[(r + 2) * 100 + j];
                    o.w = stg[(r + 3) * 100 + j];
                    *(float4*)(vp + i8 * 4) = o;
                }
            }
        }
    }
}

// ==================== weight transpose ====================
__global__ void transpose_kernel(const float* __restrict__ in, float* __restrict__ out,
                                 int R, int Cc) {   // in (R, Cc) -> out (Cc, R)
    __shared__ float t[32][33];
    int bx = blockIdx.x * 32, by = blockIdx.y * 32;
    int x = threadIdx.x, y = threadIdx.y;
#pragma unroll
    for (int j = 0; j < 4; j++) t[y + 8 * j][x] = in[(size_t)(by + y + 8 * j) * Cc + bx + x];
    __syncthreads();
#pragma unroll
    for (int j = 0; j < 4; j++) out[(size_t)(bx + y + 8 * j) * R + by + x] = t[x][y + 8 * j];
}

// ==================== RPE-bias MLP ====================
__device__ __forceinline__ void ln_relu6(float* h, const float* g, const float* b) {
    float m = 0.f;
#pragma unroll
    for (int j = 0; j < 6; j++) m += h[j];
    m *= (1.0f / 6.0f);
    float v = 0.f;
#pragma unroll
    for (int j = 0; j < 6; j++) { float d = h[j] - m; v += d * d; }
    v *= (1.0f / 6.0f);
    float inv = rsqrtf(v + 1e-5f);
#pragma unroll
    for (int j = 0; j < 6; j++) {
        float t = (h[j] - m) * inv * g[j] + b[j];
        h[j] = t > 0.f ? t : 0.f;
    }
}

__global__ void biasmlp_kernel(const float* __restrict__ rpe,
                               const float* __restrict__ pw, const float* __restrict__ pb,
                               const float* __restrict__ g1, const float* __restrict__ be1,
                               const float* __restrict__ w1, const float* __restrict__ b1,
                               const float* __restrict__ g2, const float* __restrict__ be2,
                               const float* __restrict__ w2, const float* __restrict__ b2,
                               const float* __restrict__ g3, const float* __restrict__ be3,
                               const float* __restrict__ w3, const float* __restrict__ b3,
                               const int* __restrict__ relidx,
                               float* __restrict__ biasb) {
    int bi = blockIdx.x;
    int t = threadIdx.x;
    __shared__ float p[TBIAS][HB];

    if (t < TBIAS) {
        float h[6], tmp[6];
        const float* r = rpe + (bi * TBIAS + t) * 3;
        float r0 = r[0], r1 = r[1], r2 = r[2];
#pragma unroll
        for (int j = 0; j < 6; j++)
            h[j] = pb[bi * 6 + j]
                 + r0 * pw[(bi * 3 + 0) * 6 + j]
                 + r1 * pw[(bi * 3 + 1) * 6 + j]
                 + r2 * pw[(bi * 3 + 2) * 6 + j];
        ln_relu6(h, g1 + bi * 6, be1 + bi * 6);
#pragma unroll
        for (int j = 0; j < 6; j++) {
            float s = b1[bi * 6 + j];
#pragma unroll
            for (int i = 0; i < 6; i++) s += h[i] * w1[(bi * 6 + i) * 6 + j];
            tmp[j] = s;
        }
#pragma unroll
        for (int j = 0; j < 6; j++) h[j] = tmp[j];
        ln_relu6(h, g2 + bi * 6, be2 + bi * 6);
#pragma unroll
        for (int j = 0; j < 6; j++) {
            float s = b2[bi * 6 + j];
#pragma unroll
            for (int i = 0; i < 6; i++) s += h[i] * w2[(bi * 6 + i) * 6 + j];
            tmp[j] = s;
        }
#pragma unroll
        for (int j = 0; j < 6; j++) h[j] = tmp[j];
        ln_relu6(h, g3 + bi * 6, be3 + bi * 6);
#pragma unroll
        for (int j = 0; j < HB; j++) {
            float s = b3[bi * HB + j];
#pragma unroll
            for (int i = 0; i < 6; i++) s += h[i] * w3[(bi * 6 + i) * HB + j];
            p[t][j] = s;
        }
    }
    __syncthreads();

    for (int i = t; i < HB * NWIN * NWIN; i += blockDim.x) {
        int hb = i >> 8;
        int nm = i & 255;
        biasb[bi * (HB * NWIN * NWIN) + i] = p[relidx[bi * 256 + nm]][hb];
    }
}

// ==================== windowed attention ====================
__global__ __launch_bounds__(64)
void attn_kernel(const float* __restrict__ qkv, const float* __restrict__ biasb,
                 float* __restrict__ y) {
    const int bi = blockIdx.z;
    const int b  = blockIdx.y;
    const int Dsp = c_Dsp[bi], Hsp = c_Hsp[bi], Wsp = c_Wsp[bi];
    const int nH = RESV / Hsp, nW = RESV / Wsp;
    int widx = blockIdx.x;
    int wblk = widx % nW; int tmp = widx / nW;
    int hblk = tmp % nH;  int dblk = tmp / nH;

    const int t  = threadIdx.x;
    const int hb = t >> 4;
    const int n  = t & 15;
    const int HW = Hsp * Wsp;
    int dd = n / HW; int r = n - dd * HW;
    int hh = r / Wsp; int ww = r - hh * Wsp;
    int l = ((dblk * Dsp + dd) * RESV + hblk * Hsp + hh) * RESV + wblk * Wsp + ww;

    size_t rowbase = ((size_t)b * L_TOT + l) * QKV_N + bi * 96 + hb * HDIM;

    __shared__ float sk[64][25];
    __shared__ float sv[64][25];
    float q[HDIM];
    const float scale = 0.2041241452319315f;

    const float4* qp = (const float4*)(qkv + rowbase);
    const float4* kp = (const float4*)(qkv + rowbase + CDIM);
    const float4* vp = (const float4*)(qkv + rowbase + 2 * CDIM);
#pragma unroll
    for (int j = 0; j < 6; j++) {
        float4 a = qp[j];
        q[4*j+0] = a.x * scale; q[4*j+1] = a.y * scale;
        q[4*j+2] = a.z * scale; q[4*j+3] = a.w * scale;
        float4 kk = kp[j];
        sk[t][4*j+0] = kk.x; sk[t][4*j+1] = kk.y; sk[t][4*j+2] = kk.z; sk[t][4*j+3] = kk.w;
        float4 vv = vp[j];
        sv[t][4*j+0] = vv.x; sv[t][4*j+1] = vv.y; sv[t][4*j+2] = vv.z; sv[t][4*j+3] = vv.w;
    }
    __syncthreads();

    const float* brow = biasb + (((size_t)bi * HB + hb) * NWIN + n) * NWIN;
    float lg[NWIN];
    float mx = -1e30f;
#pragma unroll
    for (int m = 0; m < NWIN; m++) {
        float s = brow[m];
        const float* kr = sk[hb * 16 + m];
#pragma unroll
        for (int e = 0; e < HDIM; e++) s = fmaf(q[e], kr[e], s);
        lg[m] = s;
        mx = fmaxf(mx, s);
    }
    float sum = 0.f;
#pragma unroll
    for (int m = 0; m < NWIN; m++) { lg[m] = expf(lg[m] - mx); sum += lg[m]; }
    float inv = 1.0f / sum;

    float o[HDIM];
#pragma unroll
    for (int e = 0; e < HDIM; e++) o[e] = 0.f;
#pragma unroll
    for (int m = 0; m < NWIN; m++) {
        float w = lg[m] * inv;
        const float* vr = sv[hb * 16 + m];
#pragma unroll
        for (int e = 0; e < HDIM; e++) o[e] = fmaf(w, vr[e], o[e]);
    }

    float* yp = y + ((size_t)b * L_TOT + l) * CDIM + bi * 96 + hb * HDIM;
#pragma unroll
    for (int e = 0; e < HDIM; e++) yp[e] = o[e];
}

// ==================== depthwise 3x3x3 conv (channel-major) ====================
__global__ __launch_bounds__(256)
void conv3d_kernel(const float* __restrict__ vc, const float* __restrict__ cw,
                   const float* __restrict__ cb, float* __restrict__ lcm) {
    const int bc = blockIdx.x;          // b*288 + c
    const int c = bc % CDIM;
    const float* src = vc + (size_t)bc * L_TOT;
    float* dst = lcm + (size_t)bc * L_TOT;

    float wt[27];
#pragma unroll
    for (int j = 0; j < 27; j++) wt[j] = cw[c * 27 + j];
    const float bias = cb[c];

    __shared__ float sp[3][34][36];
    const int tid = threadIdx.x;
    const int w = tid & 31;
    const int h0 = (tid >> 5) * 4;

    for (int i = tid; i < 3 * 34 * 36; i += 256) ((float*)sp)[i] = 0.f;
    __syncthreads();
#pragma unroll
    for (int jh = 0; jh < 4; jh++) {
        int h = h0 + jh;
        sp[0][1 + h][1 + w] = src[h * 32 + w];
        sp[1][1 + h][1 + w] = src[1024 + h * 32 + w];
    }
    __syncthreads();

#pragma unroll 1
    for (int d = 0; d < 32; d++) {
        const int bm = (d + 2) % 3;
        const int b0 = d % 3;
        const int bp = (d + 1) % 3;
        float acc[4] = {bias, bias, bias, bias};

#define TAPS(BUF, KD) { \
        const float (*P)[36] = sp[BUF]; \
        _Pragma("unroll") \
        for (int rr = 0; rr < 6; rr++) { \
            float va = P[h0 + rr][w], vb = P[h0 + rr][w + 1], vcx = P[h0 + rr][w + 2]; \
            _Pragma("unroll") \
            for (int jh = 0; jh < 4; jh++) { \
                int kh = rr - jh; \
                if (kh >= 0 && kh < 3) { \
                    acc[jh] = fmaf(wt[(KD)*9 + kh*3 + 0], va, \
                              fmaf(wt[(KD)*9 + kh*3 + 1], vb, \
                              fmaf(wt[(KD)*9 + kh*3 + 2], vcx, acc[jh]))); \
                } \
            } \
        } }

        if (d > 0)  TAPS(bm, 0);
        TAPS(b0, 1);
        if (d < 31) TAPS(bp, 2);
#undef TAPS

#pragma unroll
        for (int jh = 0; jh < 4; jh++)
            dst[d * 1024 + (h0 + jh) * 32 + w] = acc[jh];

        __syncthreads();
        if (d + 2 < 32) {
            const float* s2 = src + (d + 2) * 1024;
#pragma unroll
            for (int jh = 0; jh < 4; jh++) {
                int h = h0 + jh;
                sp[(d + 2) % 3][1 + h][1 + w] = s2[h * 32 + w];
            }
        }
        __syncthreads();
    }
}

// ==================== launch ====================
extern "C" void kernel_launch(void* const* d_in, const int* in_sizes, int n_in,
                              void* d_out, int out_size) {
    const float* x      = (const float*)d_in[0];
    const float* w_qkv  = (const float*)d_in[4];
    const float* w_proj = (const float*)d_in[5];
    const float* b_proj = (const float*)d_in[6];
    const float* conv_w = (const float*)d_in[7];
    const float* conv_b = (const float*)d_in[8];
    const float* pos_w  = (const float*)d_in[9];
    const float* pos_b  = (const float*)d_in[10];
    const float* ln1g   = (const float*)d_in[11];
    const float* ln1b   = (const float*)d_in[12];
    const float* lin1w  = (const float*)d_in[13];
    const float* lin1b  = (const float*)d_in[14];
    const float* ln2g   = (const float*)d_in[15];
    const float* ln2b   = (const float*)d_in[16];
    const float* lin2w  = (const float*)d_in[17];
    const float* lin2b  = (const float*)d_in[18];
    const float* ln3g   = (const float*)d_in[19];
    const float* ln3b   = (const float*)d_in[20];
    const float* lin3w  = (const float*)d_in[21];
    const float* lin3b  = (const float*)d_in[22];
    const float* rpe    = (const float*)d_in[23];
    const int*   relidx = (const int*)d_in[24];
    float* out = (float*)d_out;

    float *qkvp, *yp, *bp, *vcp, *lcmp, *wqkvT, *wprojT;
    cudaGetSymbolAddress((void**)&qkvp,   g_qkv);
    cudaGetSymbolAddress((void**)&yp,     g_y);
    cudaGetSymbolAddress((void**)&bp,     g_bias);
    cudaGetSymbolAddress((void**)&vcp,    g_vc);
    cudaGetSymbolAddress((void**)&lcmp,   g_lcm);
    cudaGetSymbolAddress((void**)&wqkvT,  g_wqkvT);
    cudaGetSymbolAddress((void**)&wprojT, g_wprojT);

    cudaFuncSetAttribute(gemm_mma<false, true, false>,
                         cudaFuncAttributeMaxDynamicSharedMemorySize, SMEM_G2);
    cudaFuncSetAttribute(gemm_mma<true, false, true>,
                         cudaFuncAttributeMaxDynamicSharedMemorySize, SMEM_G2);

    // 0) weight transposes
    transpose_kernel<<<dim3(QKV_N / 32, CDIM / 32), dim3(32, 8)>>>(w_qkv, wqkvT, CDIM, QKV_N);
    transpose_kernel<<<dim3(CDIM / 32, CDIM / 32), dim3(32, 8)>>>(w_proj, wprojT, CDIM, CDIM);

    // 1) qkv = x @ w_qkv  (also writes v channel-major into vc)
    gemm_mma<false, true, false><<<dim3(QKV_N / 96, NROWS / 128), 256, SMEM_G1>>>(
        x, wqkvT, qkvp, QKV_N, nullptr, nullptr, vcp);

    // 2) RPE bias tables
    biasmlp_kernel<<<3, 64>>>(rpe, pos_w, pos_b,
                              ln1g, ln1b, lin1w, lin1b,
                              ln2g, ln2b, lin2w, lin2b,
                              ln3g, ln3b, lin3w, lin3b,
                              relidx, bp);

    // 3) windowed attention -> y
    attn_kernel<<<dim3(2048, BATCH, 3), 64>>>(qkvp, bp, yp);

    // 4) depthwise conv(vc) -> lcm (channel-major)
    conv3d_kernel<<<BATCH * CDIM, 256>>>(vcp, conv_w, conv_b, lcmp);

    // 5) out = (y + lcm^T) @ w_proj + b_proj   (lcm fused into A-load)
    gemm_mma<true, false, true><<<dim3(CDIM / 96, NROWS / 128), 256, SMEM_G2>>>(
        yp, wprojT, out, CDIM, b_proj, lcmp, nullptr);
}

// round 6
// speedup vs baseline: 3.8198x; 1.2185x over previous
#include <cuda_runtime.h>
#include <cuda_fp16.h>
#include <math.h>
#include <stdint.h>

// ---------------- problem constants ----------------
#define RESV   32
#define L_TOT  (RESV*RESV*RESV)      // 32768
#define BATCH  2
#define CDIM   288
#define QKV_N  (3*CDIM)              // 864
#define NROWS  (BATCH*L_TOT)         // 65536
#define HB     4
#define HDIM   24
#define NWIN   16
#define TBIAS  63

// scratch (no cudaMalloc allowed) — fp16 intermediates
__device__ __half g_qkv [(size_t)NROWS * QKV_N];         // (B*L, 864)
__device__ __half g_y   [(size_t)NROWS * CDIM];          // attention output
__device__ __half g_vc  [(size_t)BATCH * CDIM * L_TOT];  // v, channel-major [b][c][l]
__device__ __half g_lcm [(size_t)BATCH * CDIM * L_TOT];  // conv output, channel-major
__device__ __half g_wqkvT[(size_t)QKV_N * CDIM];         // w_qkv^T  (864, 288)
__device__ __half g_wprojT[(size_t)CDIM * CDIM];         // w_proj^T (288, 288)
__device__ float  g_bias[3 * HB * NWIN * NWIN];

__constant__ int c_Dsp[3] = {2, 2, 2};
__constant__ int c_Hsp[3] = {2, 2, 4};
__constant__ int c_Wsp[3] = {4, 4, 2};

// ==================== fp16 mma helpers ====================
__device__ __forceinline__ void mma16(float* d,
                                      uint32_t a0, uint32_t a1, uint32_t a2, uint32_t a3,
                                      uint32_t b0, uint32_t b1) {
    asm volatile("mma.sync.aligned.m16n8k16.row.col.f32.f16.f16.f32 "
                 "{%0,%1,%2,%3}, {%4,%5,%6,%7}, {%8,%9}, {%0,%1,%2,%3};"
                 : "+f"(d[0]), "+f"(d[1]), "+f"(d[2]), "+f"(d[3])
                 : "r"(a0), "r"(a1), "r"(a2), "r"(a3), "r"(b0), "r"(b1));
}

__device__ __forceinline__ uint32_t pack_h2(float x, float y) {
    __half2 h = __floats2half2_rn(x, y);
    return *(uint32_t*)&h;
}

// ==================== fp16 mma.sync GEMM (weights-as-M) ====================
// C[token, chan] = Bdata[token, 288] @ Aw[chan, 288]^T
// BM=96 (chans), BN=128 (tokens), BK=32, 9 K-chunks. x streams once; weights in L2.
// IS_G1: B = x (fp32), C = qkv (half), vc writeout for v chans.
// !IS_G1: B = y (half) + lcm^T (half, channel-major), C = out (fp32) + bias.
//
// smem (half2 units): As 96x20 x2 @ {0,1920}; Bs 128x20 x2 @ {3840,6400}; tot 8960
// LS (G2 lcm stage): floats [128][33] @ float offset 8960 (bytes 35840..52736)
// epilogue stage: floats [96][133] @ 0 (51072 B)
#define SMEM_GM 52736

template<bool IS_G1>
__global__ __launch_bounds__(256)
void gemm_mma(const __half* __restrict__ Aw, const float* __restrict__ Bx,
              const __half* __restrict__ By, const __half* __restrict__ lcm,
              __half* __restrict__ Ch, float* __restrict__ Cf,
              const float* __restrict__ bias, __half* __restrict__ vc) {
    extern __shared__ float smf[];
    uint32_t* smh2 = (uint32_t*)smf;
    float* LS = smf + 8960;                    // [128][33]
    const int tid = threadIdx.x, lane = tid & 31, warp = tid >> 5;
    const int qr = lane >> 2, qc = lane & 3;
    const int wm = warp & 1, wn = warp >> 1;   // 2 x 4 warps: 48 chans x 32 tokens
    const int n0 = blockIdx.x * 128;           // token tile
    const int m0 = blockIdx.y * 96;            // chan tile
    const int bb = n0 >> 15;
    const int l0 = n0 & (L_TOT - 1);

    float acc[3][4][4];
#pragma unroll
    for (int mt = 0; mt < 3; mt++)
#pragma unroll
        for (int nt = 0; nt < 4; nt++)
#pragma unroll
            for (int r = 0; r < 4; r++) acc[mt][nt][r] = 0.0f;

    uint2  rA[3];
    float4 rBf[4];
    uint4  rBy[2], rLc[2];

#define G_LOADS(K0) do { \
    _Pragma("unroll") for (int i = 0; i < 3; i++) { \
        int idx = tid + i * 256; int m = idx >> 3, q = idx & 7; \
        rA[i] = *(const uint2*)(Aw + (size_t)(m0 + m) * CDIM + (K0) + q * 4); } \
    if (IS_G1) { \
        _Pragma("unroll") for (int i = 0; i < 4; i++) { \
            int idx = tid + i * 256; int t = idx >> 3, k4 = idx & 7; \
            rBf[i] = *(const float4*)(Bx + (size_t)(n0 + t) * CDIM + (K0) + k4 * 4); } \
    } else { \
        _Pragma("unroll") for (int i = 0; i < 2; i++) { \
            int idx = tid + i * 256; int t = idx >> 2, k8 = (idx & 3) * 8; \
            rBy[i] = *(const uint4*)(By + (size_t)(n0 + t) * CDIM + (K0) + k8); } \
        _Pragma("unroll") for (int i = 0; i < 2; i++) { \
            int idx = tid + i * 256; int cc = idx >> 4, l8 = (idx & 15) * 8; \
            rLc[i] = *(const uint4*)(lcm + ((size_t)bb * CDIM + (K0) + cc) * L_TOT + l0 + l8); } \
    } } while (0)

#define S_STORES(BUF) do { \
    uint32_t* As_ = smh2 + ((BUF) ? 1920 : 0); \
    uint32_t* Bs_ = smh2 + ((BUF) ? 6400 : 3840); \
    if (!IS_G1) { \
        _Pragma("unroll") for (int i = 0; i < 2; i++) { \
            int idx = tid + i * 256; int cc = idx >> 4, l8 = (idx & 15) * 8; \
            __half2* hh = (__half2*)&rLc[i]; \
            _Pragma("unroll") for (int e = 0; e < 4; e++) { \
                float2 f = __half22float2(hh[e]); \
                LS[(l8 + 2 * e) * 33 + cc]     = f.x; \
                LS[(l8 + 2 * e + 1) * 33 + cc] = f.y; } } \
        __syncthreads(); \
    } \
    _Pragma("unroll") for (int i = 0; i < 3; i++) { \
        int idx = tid + i * 256; int m = idx >> 3, q = idx & 7; \
        *(uint2*)(As_ + m * 20 + q * 2) = rA[i]; } \
    if (IS_G1) { \
        _Pragma("unroll") for (int i = 0; i < 4; i++) { \
            int idx = tid + i * 256; int t = idx >> 3, k4 = idx & 7; \
            float4 v = rBf[i]; \
            uint2 u = make_uint2(pack_h2(v.x, v.y), pack_h2(v.z, v.w)); \
            *(uint2*)(Bs_ + t * 20 + k4 * 2) = u; } \
    } else { \
        _Pragma("unroll") for (int i = 0; i < 2; i++) { \
            int idx = tid + i * 256; int t = idx >> 2, k8 = (idx & 3) * 8; \
            __half2* hh = (__half2*)&rBy[i]; \
            uint32_t u0, u1, u2, u3; \
            { float2 f = __half22float2(hh[0]); \
              u0 = pack_h2(f.x + LS[t * 33 + k8 + 0], f.y + LS[t * 33 + k8 + 1]); } \
            { float2 f = __half22float2(hh[1]); \
              u1 = pack_h2(f.x + LS[t * 33 + k8 + 2], f.y + LS[t * 33 + k8 + 3]); } \
            { float2 f = __half22float2(hh[2]); \
              u2 = pack_h2(f.x + LS[t * 33 + k8 + 4], f.y + LS[t * 33 + k8 + 5]); } \
            { float2 f = __half22float2(hh[3]); \
              u3 = pack_h2(f.x + LS[t * 33 + k8 + 6], f.y + LS[t * 33 + k8 + 7]); } \
            *(uint4*)(Bs_ + t * 20 + (k8 >> 1)) = make_uint4(u0, u1, u2, u3); } \
    } } while (0)

    // prologue
    G_LOADS(0);
    S_STORES(0);
    __syncthreads();

#pragma unroll 1
    for (int ch = 0; ch < 9; ch++) {
        const int cur = ch & 1;
        if (ch < 8) G_LOADS((ch + 1) * 32);

        const uint32_t* As = smh2 + (cur ? 1920 : 0);
        const uint32_t* Bs = smh2 + (cur ? 6400 : 3840);
#pragma unroll
        for (int s = 0; s < 2; s++) {
            const int k8 = s * 8;
            uint32_t af[3][4];
#pragma unroll
            for (int mt = 0; mt < 3; mt++) {
                int r0 = (wm * 48 + mt * 16 + qr) * 20 + k8 + qc;
                af[mt][0] = As[r0];
                af[mt][1] = As[r0 + 8 * 20];
                af[mt][2] = As[r0 + 4];
                af[mt][3] = As[r0 + 8 * 20 + 4];
            }
            uint32_t bf[4][2];
#pragma unroll
            for (int nt = 0; nt < 4; nt++) {
                int c0 = (wn * 32 + nt * 8 + qr) * 20 + k8 + qc;
                bf[nt][0] = Bs[c0];
                bf[nt][1] = Bs[c0 + 4];
            }
#pragma unroll
            for (int mt = 0; mt < 3; mt++)
#pragma unroll
                for (int nt = 0; nt < 4; nt++)
                    mma16(acc[mt][nt], af[mt][0], af[mt][1], af[mt][2], af[mt][3],
                          bf[nt][0], bf[nt][1]);
        }

        if (ch < 8) {
            S_STORES(cur ^ 1);
            __syncthreads();
        }
    }
#undef G_LOADS
#undef S_STORES

    // ==================== epilogue ====================
    __syncthreads();
    float* stg = smf;                  // [96][133]: [chan][token]
#pragma unroll
    for (int mt = 0; mt < 3; mt++) {
        int r0 = wm * 48 + mt * 16 + qr;
#pragma unroll
        for (int nt = 0; nt < 4; nt++) {
            int c0 = wn * 32 + nt * 8 + 2 * qc;
            stg[r0 * 133 + c0]           = acc[mt][nt][0];
            stg[r0 * 133 + c0 + 1]       = acc[mt][nt][1];
            stg[(r0 + 8) * 133 + c0]     = acc[mt][nt][2];
            stg[(r0 + 8) * 133 + c0 + 1] = acc[mt][nt][3];
        }
    }
    __syncthreads();

    if (IS_G1) {
        // qkv half writes: 128 tokens x 12 uint4 (8 chans each)
#pragma unroll
        for (int i = 0; i < 6; i++) {
            int idx = tid + i * 256;
            int t = idx / 12, q = idx - t * 12;
            uint32_t u0 = pack_h2(stg[(q * 8 + 0) * 133 + t], stg[(q * 8 + 1) * 133 + t]);
            uint32_t u1 = pack_h2(stg[(q * 8 + 2) * 133 + t], stg[(q * 8 + 3) * 133 + t]);
            uint32_t u2 = pack_h2(stg[(q * 8 + 4) * 133 + t], stg[(q * 8 + 5) * 133 + t]);
            uint32_t u3 = pack_h2(stg[(q * 8 + 6) * 133 + t], stg[(q * 8 + 7) * 133 + t]);
            *(uint4*)(Ch + (size_t)(n0 + t) * QKV_N + m0 + q * 8) = make_uint4(u0, u1, u2, u3);
        }
        if (m0 >= 2 * CDIM) {
            // vc channel-major: row-contiguous stage reads
#pragma unroll
            for (int i = 0; i < 6; i++) {
                int idx = tid + i * 256;
                int m = idx >> 4, c8 = (idx & 15) * 8;
                uint32_t u0 = pack_h2(stg[m * 133 + c8 + 0], stg[m * 133 + c8 + 1]);
                uint32_t u1 = pack_h2(stg[m * 133 + c8 + 2], stg[m * 133 + c8 + 3]);
                uint32_t u2 = pack_h2(stg[m * 133 + c8 + 4], stg[m * 133 + c8 + 5]);
                uint32_t u3 = pack_h2(stg[m * 133 + c8 + 6], stg[m * 133 + c8 + 7]);
                *(uint4*)(vc + ((size_t)bb * CDIM + (m0 - 2 * CDIM) + m) * L_TOT + l0 + c8)
                    = make_uint4(u0, u1, u2, u3);
            }
        }
    } else {
        // out fp32 + bias: 128 tokens x 24 float4
#pragma unroll
        for (int i = 0; i < 12; i++) {
            int idx = tid + i * 256;
            int t = idx / 24, q = idx - t * 24;
            float4 o;
            o.x = stg[(q * 4 + 0) * 133 + t] + bias[m0 + q * 4 + 0];
            o.y = stg[(q * 4 + 1) * 133 + t] + bias[m0 + q * 4 + 1];
            o.z = stg[(q * 4 + 2) * 133 + t] + bias[m0 + q * 4 + 2];
            o.w = stg[(q * 4 + 3) * 133 + t] + bias[m0 + q * 4 + 3];
            *(float4*)(Cf + (size_t)(n0 + t) * CDIM + m0 + q * 4) = o;
        }
    }
}

// ==================== weight transpose (fp32 -> fp16) ====================
__global__ void transpose_kernel(const float* __restrict__ in, __half* __restrict__ out,
                                 int R, int Cc) {   // in (R, Cc) -> out (Cc, R)
    __shared__ float t[32][33];
    int bx = blockIdx.x * 32, by = blockIdx.y * 32;
    int x = threadIdx.x, y = threadIdx.y;
#pragma unroll
    for (int j = 0; j < 4; j++) t[y + 8 * j][x] = in[(size_t)(by + y + 8 * j) * Cc + bx + x];
    __syncthreads();
#pragma unroll
    for (int j = 0; j < 4; j++)
        out[(size_t)(bx + y + 8 * j) * R + by + x] = __float2half(t[x][y + 8 * j]);
}

// ==================== RPE-bias MLP ====================
__device__ __forceinline__ void ln_relu6(float* h, const float* g, const float* b) {
    float m = 0.f;
#pragma unroll
    for (int j = 0; j < 6; j++) m += h[j];
    m *= (1.0f / 6.0f);
    float v = 0.f;
#pragma unroll
    for (int j = 0; j < 6; j++) { float d = h[j] - m; v += d * d; }
    v *= (1.0f / 6.0f);
    float inv = rsqrtf(v + 1e-5f);
#pragma unroll
    for (int j = 0; j < 6; j++) {
        float t = (h[j] - m) * inv * g[j] + b[j];
        h[j] = t > 0.f ? t : 0.f;
    }
}

__global__ void biasmlp_kernel(const float* __restrict__ rpe,
                               const float* __restrict__ pw, const float* __restrict__ pb,
                               const float* __restrict__ g1, const float* __restrict__ be1,
                               const float* __restrict__ w1, const float* __restrict__ b1,
                               const float* __restrict__ g2, const float* __restrict__ be2,
                               const float* __restrict__ w2, const float* __restrict__ b2,
                               const float* __restrict__ g3, const float* __restrict__ be3,
                               const float* __restrict__ w3, const float* __restrict__ b3,
                               const int* __restrict__ relidx,
                               float* __restrict__ biasb) {
    int bi = blockIdx.x;
    int t = threadIdx.x;
    __shared__ float p[TBIAS][HB];

    if (t < TBIAS) {
        float h[6], tmp[6];
        const float* r = rpe + (bi * TBIAS + t) * 3;
        float r0 = r[0], r1 = r[1], r2 = r[2];
#pragma unroll
        for (int j = 0; j < 6; j++)
            h[j] = pb[bi * 6 + j]
                 + r0 * pw[(bi * 3 + 0) * 6 + j]
                 + r1 * pw[(bi * 3 + 1) * 6 + j]
                 + r2 * pw[(bi * 3 + 2) * 6 + j];
        ln_relu6(h, g1 + bi * 6, be1 + bi * 6);
#pragma unroll
        for (int j = 0; j < 6; j++) {
            float s = b1[bi * 6 + j];
#pragma unroll
            for (int i = 0; i < 6; i++) s += h[i] * w1[(bi * 6 + i) * 6 + j];
            tmp[j] = s;
        }
#pragma unroll
        for (int j = 0; j < 6; j++) h[j] = tmp[j];
        ln_relu6(h, g2 + bi * 6, be2 + bi * 6);
#pragma unroll
        for (int j = 0; j < 6; j++) {
            float s = b2[bi * 6 + j];
#pragma unroll
            for (int i = 0; i < 6; i++) s += h[i] * w2[(bi * 6 + i) * 6 + j];
            tmp[j] = s;
        }
#pragma unroll
        for (int j = 0; j < 6; j++) h[j] = tmp[j];
        ln_relu6(h, g3 + bi * 6, be3 + bi * 6);
#pragma unroll
        for (int j = 0; j < HB; j++) {
            float s = b3[bi * HB + j];
#pragma unroll
            for (int i = 0; i < 6; i++) s += h[i] * w3[(bi * 6 + i) * HB + j];
            p[t][j] = s;
        }
    }
    __syncthreads();

    for (int i = t; i < HB * NWIN * NWIN; i += blockDim.x) {
        int hb = i >> 8;
        int nm = i & 255;
        biasb[bi * (HB * NWIN * NWIN) + i] = p[relidx[bi * 256 + nm]][hb];
    }
}

// ==================== windowed attention (half IO, 2 windows/block) ====================
__global__ __launch_bounds__(128)
void attn_kernel(const __half* __restrict__ qkv, const float* __restrict__ biasb,
                 __half* __restrict__ y) {
    const int bi = blockIdx.z;
    const int b  = blockIdx.y;
    const int Dsp = c_Dsp[bi], Hsp = c_Hsp[bi], Wsp = c_Wsp[bi];
    const int nH = RESV / Hsp, nW = RESV / Wsp;
    const int t  = threadIdx.x;
    const int g  = t >> 6;             // window slot within block
    const int tl = t & 63;
    int widx = blockIdx.x * 2 + g;
    int wblk = widx % nW; int tmp = widx / nW;
    int hblk = tmp % nH;  int dblk = tmp / nH;

    const int hb = tl >> 4;
    const int n  = tl & 15;
    const int HW = Hsp * Wsp;
    int dd = n / HW; int r = n - dd * HW;
    int hh = r / Wsp; int ww = r - hh * Wsp;
    int l = ((dblk * Dsp + dd) * RESV + hblk * Hsp + hh) * RESV + wblk * Wsp + ww;

    size_t rowbase = ((size_t)b * L_TOT + l) * QKV_N + bi * 96 + hb * HDIM;

    __shared__ float sk[2][64][25];
    __shared__ float sv[2][64][25];
    float q[HDIM];
    const float scale = 0.2041241452319315f;  // 24^-0.5

    const uint4* qp = (const uint4*)(qkv + rowbase);
    const uint4* kp = (const uint4*)(qkv + rowbase + CDIM);
    const uint4* vp = (const uint4*)(qkv + rowbase + 2 * CDIM);
#pragma unroll
    for (int j = 0; j < 3; j++) {
        uint4 uq = qp[j], uk = kp[j], uv = vp[j];
        __half2* hq = (__half2*)&uq;
        __half2* hk = (__half2*)&uk;
        __half2* hv = (__half2*)&uv;
#pragma unroll
        for (int e = 0; e < 4; e++) {
            float2 fq = __half22float2(hq[e]);
            q[8 * j + 2 * e]     = fq.x * scale;
            q[8 * j + 2 * e + 1] = fq.y * scale;
            float2 fk = __half22float2(hk[e]);
            sk[g][tl][8 * j + 2 * e]     = fk.x;
            sk[g][tl][8 * j + 2 * e + 1] = fk.y;
            float2 fv = __half22float2(hv[e]);
            sv[g][tl][8 * j + 2 * e]     = fv.x;
            sv[g][tl][8 * j + 2 * e + 1] = fv.y;
        }
    }
    __syncthreads();

    const float* brow = biasb + (((size_t)bi * HB + hb) * NWIN + n) * NWIN;
    float lg[NWIN];
    float mx = -1e30f;
#pragma unroll
    for (int m = 0; m < NWIN; m++) {
        float s = brow[m];
        const float* kr = sk[g][hb * 16 + m];
#pragma unroll
        for (int e = 0; e < HDIM; e++) s = fmaf(q[e], kr[e], s);
        lg[m] = s;
        mx = fmaxf(mx, s);
    }
    float sum = 0.f;
#pragma unroll
    for (int m = 0; m < NWIN; m++) { lg[m] = __expf(lg[m] - mx); sum += lg[m]; }
    float inv = 1.0f / sum;

    float o[HDIM];
#pragma unroll
    for (int e = 0; e < HDIM; e++) o[e] = 0.f;
#pragma unroll
    for (int m = 0; m < NWIN; m++) {
        float w = lg[m] * inv;
        const float* vr = sv[g][hb * 16 + m];
#pragma unroll
        for (int e = 0; e < HDIM; e++) o[e] = fmaf(w, vr[e], o[e]);
    }

    __half* yp = y + ((size_t)b * L_TOT + l) * CDIM + bi * 96 + hb * HDIM;
#pragma unroll
    for (int j = 0; j < 3; j++) {
        uint32_t u0 = pack_h2(o[8 * j + 0], o[8 * j + 1]);
        uint32_t u1 = pack_h2(o[8 * j + 2], o[8 * j + 3]);
        uint32_t u2 = pack_h2(o[8 * j + 4], o[8 * j + 5]);
        uint32_t u3 = pack_h2(o[8 * j + 6], o[8 * j + 7]);
        *(uint4*)(yp + 8 * j) = make_uint4(u0, u1, u2, u3);
    }
}

// ==================== depthwise 3x3x3 conv (channel-major, half IO) ====================
__global__ __launch_bounds__(256)
void conv3d_kernel(const __half* __restrict__ vc, const float* __restrict__ cw,
                   const float* __restrict__ cb, __half* __restrict__ lcm) {
    const int bc = blockIdx.x;          // b*288 + c
    const int c = bc % CDIM;
    const __half* src = vc + (size_t)bc * L_TOT;
    __half* dst = lcm + (size_t)bc * L_TOT;

    float wt[27];
#pragma unroll
    for (int j = 0; j < 27; j++) wt[j] = cw[c * 27 + j];
    const float bias = cb[c];

    __shared__ float sp[3][34][36];
    const int tid = threadIdx.x;
    const int w = tid & 31;
    const int h0 = (tid >> 5) * 4;

    for (int i = tid; i < 3 * 34 * 36; i += 256) ((float*)sp)[i] = 0.f;
    __syncthreads();
#pragma unroll
    for (int jh = 0; jh < 4; jh++) {
        int h = h0 + jh;
        sp[0][1 + h][1 + w] = __half2float(src[h * 32 + w]);
        sp[1][1 + h][1 + w] = __half2float(src[1024 + h * 32 + w]);
    }
    __syncthreads();

#pragma unroll 1
    for (int d = 0; d < 32; d++) {
        const int bm = (d + 2) % 3;
        const int b0 = d % 3;
        const int bp = (d + 1) % 3;
        float acc[4] = {bias, bias, bias, bias};

#define TAPS(BUF, KD) { \
        const float (*P)[36] = sp[BUF]; \
        _Pragma("unroll") \
        for (int rr = 0; rr < 6; rr++) { \
            float va = P[h0 + rr][w], vb = P[h0 + rr][w + 1], vcx = P[h0 + rr][w + 2]; \
            _Pragma("unroll") \
            for (int jh = 0; jh < 4; jh++) { \
                int kh = rr - jh; \
                if (kh >= 0 && kh < 3) { \
                    acc[jh] = fmaf(wt[(KD)*9 + kh*3 + 0], va, \
                              fmaf(wt[(KD)*9 + kh*3 + 1], vb, \
                              fmaf(wt[(KD)*9 + kh*3 + 2], vcx, acc[jh]))); \
                } \
            } \
        } }

        if (d > 0)  TAPS(bm, 0);
        TAPS(b0, 1);
        if (d < 31) TAPS(bp, 2);
#undef TAPS

#pragma unroll
        for (int jh = 0; jh < 4; jh++)
            dst[d * 1024 + (h0 + jh) * 32 + w] = __float2half(acc[jh]);

        __syncthreads();
        if (d + 2 < 32) {
            const __half* s2 = src + (d + 2) * 1024;
#pragma unroll
            for (int jh = 0; jh < 4; jh++) {
                int h = h0 + jh;
                sp[(d + 2) % 3][1 + h][1 + w] = __half2float(s2[h * 32 + w]);
            }
        }
        __syncthreads();
    }
}

// ==================== launch ====================
extern "C" void kernel_launch(void* const* d_in, const int* in_sizes, int n_in,
                              void* d_out, int out_size) {
    const float* x      = (const float*)d_in[0];
    const float* w_qkv  = (const float*)d_in[4];
    const float* w_proj = (const float*)d_in[5];
    const float* b_proj = (const float*)d_in[6];
    const float* conv_w = (const float*)d_in[7];
    const float* conv_b = (const float*)d_in[8];
    const float* pos_w  = (const float*)d_in[9];
    const float* pos_b  = (const float*)d_in[10];
    const float* ln1g   = (const float*)d_in[11];
    const float* ln1b   = (const float*)d_in[12];
    const float* lin1w  = (const float*)d_in[13];
    const float* lin1b  = (const float*)d_in[14];
    const float* ln2g   = (const float*)d_in[15];
    const float* ln2b   = (const float*)d_in[16];
    const float* lin2w  = (const float*)d_in[17];
    const float* lin2b  = (const float*)d_in[18];
    const float* ln3g   = (const float*)d_in[19];
    const float* ln3b   = (const float*)d_in[20];
    const float* lin3w  = (const float*)d_in[21];
    const float* lin3b  = (const float*)d_in[22];
    const float* rpe    = (const float*)d_in[23];
    const int*   relidx = (const int*)d_in[24];
    float* out = (float*)d_out;

    __half *qkvp, *yp, *vcp, *lcmp, *wqkvT, *wprojT;
    float *bp;
    cudaGetSymbolAddress((void**)&qkvp,   g_qkv);
    cudaGetSymbolAddress((void**)&yp,     g_y);
    cudaGetSymbolAddress((void**)&bp,     g_bias);
    cudaGetSymbolAddress((void**)&vcp,    g_vc);
    cudaGetSymbolAddress((void**)&lcmp,   g_lcm);
    cudaGetSymbolAddress((void**)&wqkvT,  g_wqkvT);
    cudaGetSymbolAddress((void**)&wprojT, g_wprojT);

    cudaFuncSetAttribute(gemm_mma<true>,
                         cudaFuncAttributeMaxDynamicSharedMemorySize, SMEM_GM);
    cudaFuncSetAttribute(gemm_mma<false>,
                         cudaFuncAttributeMaxDynamicSharedMemorySize, SMEM_GM);

    // 0) weight transposes (fp32 -> fp16)
    transpose_kernel<<<dim3(QKV_N / 32, CDIM / 32), dim3(32, 8)>>>(w_qkv, wqkvT, CDIM, QKV_N);
    transpose_kernel<<<dim3(CDIM / 32, CDIM / 32), dim3(32, 8)>>>(w_proj, wprojT, CDIM, CDIM);

    // 1) qkv = x @ w_qkv  (half out; v also written channel-major into vc)
    gemm_mma<true><<<dim3(NROWS / 128, QKV_N / 96), 256, SMEM_GM>>>(
        wqkvT, x, nullptr, nullptr, qkvp, nullptr, nullptr, vcp);

    // 2) RPE bias tables
    biasmlp_kernel<<<3, 64>>>(rpe, pos_w, pos_b,
                              ln1g, ln1b, lin1w, lin1b,
                              ln2g, ln2b, lin2w, lin2b,
                              ln3g, ln3b, lin3w, lin3b,
                              relidx, bp);

    // 3) windowed attention -> y (half)
    attn_kernel<<<dim3(1024, BATCH, 3), 128>>>(qkvp, bp, yp);

    // 4) depthwise conv(vc) -> lcm (channel-major, half)
    conv3d_kernel<<<BATCH * CDIM, 256>>>(vcp, conv_w, conv_b, lcmp);

    // 5) out = (y + lcm^T) @ w_proj + b_proj  (fp32 out)
    gemm_mma<false><<<dim3(NROWS / 128, CDIM / 96), 256, SMEM_GM>>>(
        wprojT, nullptr, yp, lcmp, nullptr, out, b_proj, nullptr);
}

// round 7
// speedup vs baseline: 3.9774x; 1.0413x over previous
#include <cuda_runtime.h>
#include <cuda_fp16.h>
#include <math.h>
#include <stdint.h>

// ---------------- problem constants ----------------
#define RESV   32
#define L_TOT  (RESV*RESV*RESV)      // 32768
#define BATCH  2
#define CDIM   288
#define QKV_N  (3*CDIM)              // 864
#define NROWS  (BATCH*L_TOT)         // 65536
#define HB     4
#define HDIM   24
#define NWIN   16
#define TBIAS  63

// scratch (no cudaMalloc allowed) — fp16 intermediates
__device__ __half g_xh  [(size_t)NROWS * CDIM];          // x in fp16
__device__ __half g_qkv [(size_t)NROWS * QKV_N];         // (B*L, 864)
__device__ __half g_y   [(size_t)NROWS * CDIM];          // attention output
__device__ __half g_vc  [(size_t)BATCH * CDIM * L_TOT];  // v, channel-major [b][c][l]
__device__ __half g_lcm [(size_t)BATCH * CDIM * L_TOT];  // conv output, channel-major
__device__ __half g_wqkvT[(size_t)QKV_N * CDIM];         // w_qkv^T  (864, 288)
__device__ __half g_wprojT[(size_t)CDIM * CDIM];         // w_proj^T (288, 288)
__device__ float  g_bias[3 * HB * NWIN * NWIN];

__constant__ int c_Dsp[3] = {2, 2, 2};
__constant__ int c_Hsp[3] = {2, 2, 4};
__constant__ int c_Wsp[3] = {4, 4, 2};

// ==================== helpers ====================
__device__ __forceinline__ uint32_t smem_u32_of(const void* p) {
    uint32_t a;
    asm("{ .reg .u64 t; cvta.to.shared.u64 t, %1; cvt.u32.u64 %0, t; }" : "=r"(a) : "l"(p));
    return a;
}

__device__ __forceinline__ void mma16(float* d,
                                      uint32_t a0, uint32_t a1, uint32_t a2, uint32_t a3,
                                      uint32_t b0, uint32_t b1) {
    asm volatile("mma.sync.aligned.m16n8k16.row.col.f32.f16.f16.f32 "
                 "{%0,%1,%2,%3}, {%4,%5,%6,%7}, {%8,%9}, {%0,%1,%2,%3};"
                 : "+f"(d[0]), "+f"(d[1]), "+f"(d[2]), "+f"(d[3])
                 : "r"(a0), "r"(a1), "r"(a2), "r"(a3), "r"(b0), "r"(b1));
}

__device__ __forceinline__ uint32_t pack_h2(float x, float y) {
    __half2 h = __floats2half2_rn(x, y);
    return *(uint32_t*)&h;
}

#define CP16(dst, src) \
    asm volatile("cp.async.cg.shared.global [%0], [%1], 16;" :: "r"(dst), "l"(src))
#define CP_COMMIT() asm volatile("cp.async.commit_group;")
#define CP_WAIT1()  asm volatile("cp.async.wait_group 1;")
#define CP_WAIT0()  asm volatile("cp.async.wait_group 0;")

// ==================== x -> half ====================
__global__ __launch_bounds__(256)
void x2h_kernel(const float* __restrict__ x, __half* __restrict__ xh) {
    size_t i = ((size_t)blockIdx.x * 256 + threadIdx.x) * 8;
    float4 a = *(const float4*)(x + i);
    float4 b = *(const float4*)(x + i + 4);
    uint4 u = make_uint4(pack_h2(a.x, a.y), pack_h2(a.z, a.w),
                         pack_h2(b.x, b.y), pack_h2(b.z, b.w));
    *(uint4*)(xh + i) = u;
}

// ==================== GEMM1: cp.async 3-stage, all-half ====================
// qkv[token][chan] = xh[token][288] @ wqkvT[chan][288]^T
// BM=96 chans, BN=128 tokens, BK=32, 9 chunks. Also writes v channel-major -> vc.
// Stage layout (bytes): A 96x80 (7680), B 128x80 (10240); 3 stages = 53760.
#define G1_SMEM 53760

__global__ __launch_bounds__(256)
void gemm1_kernel(const __half* __restrict__ Aw, const __half* __restrict__ Bx,
                  __half* __restrict__ Ch, __half* __restrict__ vc) {
    extern __shared__ float smf[];
    uint32_t* smh2 = (uint32_t*)smf;
    const uint32_t smb = smem_u32_of(smf);
    const int tid = threadIdx.x, lane = tid & 31, warp = tid >> 5;
    const int qr = lane >> 2, qc = lane & 3;
    const int wm = warp & 1, wn = warp >> 1;   // 48 chans x 32 tokens per warp
    const int n0 = blockIdx.x * 128;           // token tile
    const int m0 = blockIdx.y * 96;            // chan tile
    const int bb = n0 >> 15;
    const int l0 = n0 & (L_TOT - 1);

    float acc[3][4][4];
#pragma unroll
    for (int mt = 0; mt < 3; mt++)
#pragma unroll
        for (int nt = 0; nt < 4; nt++)
#pragma unroll
            for (int r = 0; r < 4; r++) acc[mt][nt][r] = 0.0f;

#define ISSUE(S, K0) do { \
    uint32_t base = smb + (S) * 17920; \
    { int idx = tid; \
      int r = idx >> 2, c = idx & 3; \
      CP16(base + r * 80 + c * 16, Aw + (size_t)(m0 + r) * CDIM + (K0) + c * 8); } \
    if (tid < 128) { int idx = tid + 256; \
      int r = idx >> 2, c = idx & 3; \
      CP16(base + r * 80 + c * 16, Aw + (size_t)(m0 + r) * CDIM + (K0) + c * 8); } \
    _Pragma("unroll") for (int i = 0; i < 2; i++) { \
      int idx = tid + i * 256; \
      int r = idx >> 2, c = idx & 3; \
      CP16(base + 7680 + r * 80 + c * 16, Bx + (size_t)(n0 + r) * CDIM + (K0) + c * 8); } \
    CP_COMMIT(); \
} while (0)

    ISSUE(0, 0);
    ISSUE(1, 32);

#pragma unroll 1
    for (int ch = 0; ch < 9; ch++) {
        if (ch < 8) { CP_WAIT1(); } else { CP_WAIT0(); }
        __syncthreads();
        if (ch < 7) ISSUE((ch + 2) % 3, (ch + 2) * 32);

        const uint32_t* As = smh2 + (ch % 3) * 4480;
        const uint32_t* Bs = As + 1920;
#pragma unroll
        for (int s = 0; s < 2; s++) {
            const int k8 = s * 8;
            uint32_t af[3][4];
#pragma unroll
            for (int mt = 0; mt < 3; mt++) {
                int r0 = (wm * 48 + mt * 16 + qr) * 20 + k8 + qc;
                af[mt][0] = As[r0];
                af[mt][1] = As[r0 + 8 * 20];
                af[mt][2] = As[r0 + 4];
                af[mt][3] = As[r0 + 8 * 20 + 4];
            }
            uint32_t bf[4][2];
#pragma unroll
            for (int nt = 0; nt < 4; nt++) {
                int c0 = (wn * 32 + nt * 8 + qr) * 20 + k8 + qc;
                bf[nt][0] = Bs[c0];
                bf[nt][1] = Bs[c0 + 4];
            }
#pragma unroll
            for (int mt = 0; mt < 3; mt++)
#pragma unroll
                for (int nt = 0; nt < 4; nt++)
                    mma16(acc[mt][nt], af[mt][0], af[mt][1], af[mt][2], af[mt][3],
                          bf[nt][0], bf[nt][1]);
        }
        __syncthreads();
    }
#undef ISSUE

    // ==================== epilogue ====================
    float* stg = smf;                  // [96][133]: [chan][token]
#pragma unroll
    for (int mt = 0; mt < 3; mt++) {
        int r0 = wm * 48 + mt * 16 + qr;
#pragma unroll
        for (int nt = 0; nt < 4; nt++) {
            int c0 = wn * 32 + nt * 8 + 2 * qc;
            stg[r0 * 133 + c0]           = acc[mt][nt][0];
            stg[r0 * 133 + c0 + 1]       = acc[mt][nt][1];
            stg[(r0 + 8) * 133 + c0]     = acc[mt][nt][2];
            stg[(r0 + 8) * 133 + c0 + 1] = acc[mt][nt][3];
        }
    }
    __syncthreads();

    // qkv half writes: 128 tokens x 12 uint4 (8 chans each)
#pragma unroll
    for (int i = 0; i < 6; i++) {
        int idx = tid + i * 256;
        int t = idx / 12, q = idx - t * 12;
        uint32_t u0 = pack_h2(stg[(q * 8 + 0) * 133 + t], stg[(q * 8 + 1) * 133 + t]);
        uint32_t u1 = pack_h2(stg[(q * 8 + 2) * 133 + t], stg[(q * 8 + 3) * 133 + t]);
        uint32_t u2 = pack_h2(stg[(q * 8 + 4) * 133 + t], stg[(q * 8 + 5) * 133 + t]);
        uint32_t u3 = pack_h2(stg[(q * 8 + 6) * 133 + t], stg[(q * 8 + 7) * 133 + t]);
        *(uint4*)(Ch + (size_t)(n0 + t) * QKV_N + m0 + q * 8) = make_uint4(u0, u1, u2, u3);
    }
    if (m0 >= 2 * CDIM) {
        // vc channel-major: row-contiguous stage reads
#pragma unroll
        for (int i = 0; i < 6; i++) {
            int idx = tid + i * 256;
            int m = idx >> 4, c8 = (idx & 15) * 8;
            uint32_t u0 = pack_h2(stg[m * 133 + c8 + 0], stg[m * 133 + c8 + 1]);
            uint32_t u1 = pack_h2(stg[m * 133 + c8 + 2], stg[m * 133 + c8 + 3]);
            uint32_t u2 = pack_h2(stg[m * 133 + c8 + 4], stg[m * 133 + c8 + 5]);
            uint32_t u3 = pack_h2(stg[m * 133 + c8 + 6], stg[m * 133 + c8 + 7]);
            *(uint4*)(vc + ((size_t)bb * CDIM + (m0 - 2 * CDIM) + m) * L_TOT + l0 + c8)
                = make_uint4(u0, u1, u2, u3);
        }
    }
}

// ==================== GEMM2: out = (y + lcm^T) @ w_proj + bias ====================
// smem (half2 units): As 96x20 x2 @ {0,1920}; Bs 128x20 x2 @ {3840,6400}
// LS lcm stage floats [128][33] @ float offset 8960; epilogue stage [96][133] @ 0
#define G2_SMEM 52736

__global__ __launch_bounds__(256)
void gemm2_kernel(const __half* __restrict__ Aw, const __half* __restrict__ By,
                  const __half* __restrict__ lcm, float* __restrict__ Cf,
                  const float* __restrict__ bias) {
    extern __shared__ float smf[];
    uint32_t* smh2 = (uint32_t*)smf;
    float* LS = smf + 8960;                    // [128][33]
    const int tid = threadIdx.x, lane = tid & 31, warp = tid >> 5;
    const int qr = lane >> 2, qc = lane & 3;
    const int wm = warp & 1, wn = warp >> 1;
    const int n0 = blockIdx.x * 128;
    const int m0 = blockIdx.y * 96;
    const int bb = n0 >> 15;
    const int l0 = n0 & (L_TOT - 1);

    float acc[3][4][4];
#pragma unroll
    for (int mt = 0; mt < 3; mt++)
#pragma unroll
        for (int nt = 0; nt < 4; nt++)
#pragma unroll
            for (int r = 0; r < 4; r++) acc[mt][nt][r] = 0.0f;

    uint2 rA[3];
    uint4 rBy[2], rLc[2];

#define G_LOADS(K0) do { \
    _Pragma("unroll") for (int i = 0; i < 3; i++) { \
        int idx = tid + i * 256; int m = idx >> 3, q = idx & 7; \
        rA[i] = *(const uint2*)(Aw + (size_t)(m0 + m) * CDIM + (K0) + q * 4); } \
    _Pragma("unroll") for (int i = 0; i < 2; i++) { \
        int idx = tid + i * 256; int t = idx >> 2, k8 = (idx & 3) * 8; \
        rBy[i] = *(const uint4*)(By + (size_t)(n0 + t) * CDIM + (K0) + k8); } \
    _Pragma("unroll") for (int i = 0; i < 2; i++) { \
        int idx = tid + i * 256; int cc = idx >> 4, l8 = (idx & 15) * 8; \
        rLc[i] = *(const uint4*)(lcm + ((size_t)bb * CDIM + (K0) + cc) * L_TOT + l0 + l8); } \
} while (0)

#define S_STORES(BUF) do { \
    uint32_t* As_ = smh2 + ((BUF) ? 1920 : 0); \
    uint32_t* Bs_ = smh2 + ((BUF) ? 6400 : 3840); \
    _Pragma("unroll") for (int i = 0; i < 2; i++) { \
        int idx = tid + i * 256; int cc = idx >> 4, l8 = (idx & 15) * 8; \
        __half2* hh = (__half2*)&rLc[i]; \
        _Pragma("unroll") for (int e = 0; e < 4; e++) { \
            float2 f = __half22float2(hh[e]); \
            LS[(l8 + 2 * e) * 33 + cc]     = f.x; \
            LS[(l8 + 2 * e + 1) * 33 + cc] = f.y; } } \
    __syncthreads(); \
    _Pragma("unroll") for (int i = 0; i < 3; i++) { \
        int idx = tid + i * 256; int m = idx >> 3, q = idx & 7; \
        *(uint2*)(As_ + m * 20 + q * 2) = rA[i]; } \
    _Pragma("unroll") for (int i = 0; i < 2; i++) { \
        int idx = tid + i * 256; int t = idx >> 2, k8 = (idx & 3) * 8; \
        __half2* hh = (__half2*)&rBy[i]; \
        uint32_t u0, u1, u2, u3; \
        { float2 f = __half22float2(hh[0]); \
          u0 = pack_h2(f.x + LS[t * 33 + k8 + 0], f.y + LS[t * 33 + k8 + 1]); } \
        { float2 f = __half22float2(hh[1]); \
          u1 = pack_h2(f.x + LS[t * 33 + k8 + 2], f.y + LS[t * 33 + k8 + 3]); } \
        { float2 f = __half22float2(hh[2]); \
          u2 = pack_h2(f.x + LS[t * 33 + k8 + 4], f.y + LS[t * 33 + k8 + 5]); } \
        { float2 f = __half22float2(hh[3]); \
          u3 = pack_h2(f.x + LS[t * 33 + k8 + 6], f.y + LS[t * 33 + k8 + 7]); } \
        *(uint4*)(Bs_ + t * 20 + (k8 >> 1)) = make_uint4(u0, u1, u2, u3); } \
} while (0)

    G_LOADS(0);
    S_STORES(0);
    __syncthreads();

#pragma unroll 1
    for (int ch = 0; ch < 9; ch++) {
        const int cur = ch & 1;
        if (ch < 8) G_LOADS((ch + 1) * 32);

        const uint32_t* As = smh2 + (cur ? 1920 : 0);
        const uint32_t* Bs = smh2 + (cur ? 6400 : 3840);
#pragma unroll
        for (int s = 0; s < 2; s++) {
            const int k8 = s * 8;
            uint32_t af[3][4];
#pragma unroll
            for (int mt = 0; mt < 3; mt++) {
                int r0 = (wm * 48 + mt * 16 + qr) * 20 + k8 + qc;
                af[mt][0] = As[r0];
                af[mt][1] = As[r0 + 8 * 20];
                af[mt][2] = As[r0 + 4];
                af[mt][3] = As[r0 + 8 * 20 + 4];
            }
            uint32_t bf[4][2];
#pragma unroll
            for (int nt = 0; nt < 4; nt++) {
                int c0 = (wn * 32 + nt * 8 + qr) * 20 + k8 + qc;
                bf[nt][0] = Bs[c0];
                bf[nt][1] = Bs[c0 + 4];
            }
#pragma unroll
            for (int mt = 0; mt < 3; mt++)
#pragma unroll
                for (int nt = 0; nt < 4; nt++)
                    mma16(acc[mt][nt], af[mt][0], af[mt][1], af[mt][2], af[mt][3],
                          bf[nt][0], bf[nt][1]);
        }

        if (ch < 8) {
            S_STORES(cur ^ 1);
            __syncthreads();
        }
    }
#undef G_LOADS
#undef S_STORES

    __syncthreads();
    float* stg = smf;                  // [96][133]
#pragma unroll
    for (int mt = 0; mt < 3; mt++) {
        int r0 = wm * 48 + mt * 16 + qr;
#pragma unroll
        for (int nt = 0; nt < 4; nt++) {
            int c0 = wn * 32 + nt * 8 + 2 * qc;
            stg[r0 * 133 + c0]           = acc[mt][nt][0];
            stg[r0 * 133 + c0 + 1]       = acc[mt][nt][1];
            stg[(r0 + 8) * 133 + c0]     = acc[mt][nt][2];
            stg[(r0 + 8) * 133 + c0 + 1] = acc[mt][nt][3];
        }
    }
    __syncthreads();

#pragma unroll
    for (int i = 0; i < 12; i++) {
        int idx = tid + i * 256;
        int t = idx / 24, q = idx - t * 24;
        float4 o;
        o.x = stg[(q * 4 + 0) * 133 + t] + bias[m0 + q * 4 + 0];
        o.y = stg[(q * 4 + 1) * 133 + t] + bias[m0 + q * 4 + 1];
        o.z = stg[(q * 4 + 2) * 133 + t] + bias[m0 + q * 4 + 2];
        o.w = stg[(q * 4 + 3) * 133 + t] + bias[m0 + q * 4 + 3];
        *(float4*)(Cf + (size_t)(n0 + t) * CDIM + m0 + q * 4) = o;
    }
}

// ==================== weight transpose (fp32 -> fp16) ====================
__global__ void transpose_kernel(const float* __restrict__ in, __half* __restrict__ out,
                                 int R, int Cc) {   // in (R, Cc) -> out (Cc, R)
    __shared__ float t[32][33];
    int bx = blockIdx.x * 32, by = blockIdx.y * 32;
    int x = threadIdx.x, y = threadIdx.y;
#pragma unroll
    for (int j = 0; j < 4; j++) t[y + 8 * j][x] = in[(size_t)(by + y + 8 * j) * Cc + bx + x];
    __syncthreads();
#pragma unroll
    for (int j = 0; j < 4; j++)
        out[(size_t)(bx + y + 8 * j) * R + by + x] = __float2half(t[x][y + 8 * j]);
}

// ==================== RPE-bias MLP ====================
__device__ __forceinline__ void ln_relu6(float* h, const float* g, const float* b) {
    float m = 0.f;
#pragma unroll
    for (int j = 0; j < 6; j++) m += h[j];
    m *= (1.0f / 6.0f);
    float v = 0.f;
#pragma unroll
    for (int j = 0; j < 6; j++) { float d = h[j] - m; v += d * d; }
    v *= (1.0f / 6.0f);
    float inv = rsqrtf(v + 1e-5f);
#pragma unroll
    for (int j = 0; j < 6; j++) {
        float t = (h[j] - m) * inv * g[j] + b[j];
        h[j] = t > 0.f ? t : 0.f;
    }
}

__global__ void biasmlp_kernel(const float* __restrict__ rpe,
                               const float* __restrict__ pw, const float* __restrict__ pb,
                               const float* __restrict__ g1, const float* __restrict__ be1,
                               const float* __restrict__ w1, const float* __restrict__ b1,
                               const float* __restrict__ g2, const float* __restrict__ be2,
                               const float* __restrict__ w2, const float* __restrict__ b2,
                               const float* __restrict__ g3, const float* __restrict__ be3,
                               const float* __restrict__ w3, const float* __restrict__ b3,
                               const int* __restrict__ relidx,
                               float* __restrict__ biasb) {
    int bi = blockIdx.x;
    int t = threadIdx.x;
    __shared__ float p[TBIAS][HB];

    if (t < TBIAS) {
        float h[6], tmp[6];
        const float* r = rpe + (bi * TBIAS + t) * 3;
        float r0 = r[0], r1 = r[1], r2 = r[2];
#pragma unroll
        for (int j = 0; j < 6; j++)
            h[j] = pb[bi * 6 + j]
                 + r0 * pw[(bi * 3 + 0) * 6 + j]
                 + r1 * pw[(bi * 3 + 1) * 6 + j]
                 + r2 * pw[(bi * 3 + 2) * 6 + j];
        ln_relu6(h, g1 + bi * 6, be1 + bi * 6);
#pragma unroll
        for (int j = 0; j < 6; j++) {
            float s = b1[bi * 6 + j];
#pragma unroll
            for (int i = 0; i < 6; i++) s += h[i] * w1[(bi * 6 + i) * 6 + j];
            tmp[j] = s;
        }
#pragma unroll
        for (int j = 0; j < 6; j++) h[j] = tmp[j];
        ln_relu6(h, g2 + bi * 6, be2 + bi * 6);
#pragma unroll
        for (int j = 0; j < 6; j++) {
            float s = b2[bi * 6 + j];
#pragma unroll
            for (int i = 0; i < 6; i++) s += h[i] * w2[(bi * 6 + i) * 6 + j];
            tmp[j] = s;
        }
#pragma unroll
        for (int j = 0; j < 6; j++) h[j] = tmp[j];
        ln_relu6(h, g3 + bi * 6, be3 + bi * 6);
#pragma unroll
        for (int j = 0; j < HB; j++) {
            float s = b3[bi * HB + j];
#pragma unroll
            for (int i = 0; i < 6; i++) s += h[i] * w3[(bi * 6 + i) * HB + j];
            p[t][j] = s;
        }
    }
    __syncthreads();

    for (int i = t; i < HB * NWIN * NWIN; i += blockDim.x) {
        int hb = i >> 8;
        int nm = i & 255;
        biasb[bi * (HB * NWIN * NWIN) + i] = p[relidx[bi * 256 + nm]][hb];
    }
}

// ==================== windowed attention (half IO, 2 windows/block) ====================
__global__ __launch_bounds__(128)
void attn_kernel(const __half* __restrict__ qkv, const float* __restrict__ biasb,
                 __half* __restrict__ y) {
    const int bi = blockIdx.z;
    const int b  = blockIdx.y;
    const int Dsp = c_Dsp[bi], Hsp = c_Hsp[bi], Wsp = c_Wsp[bi];
    const int nH = RESV / Hsp, nW = RESV / Wsp;
    const int t  = threadIdx.x;
    const int g  = t >> 6;
    const int tl = t & 63;
    int widx = blockIdx.x * 2 + g;
    int wblk = widx % nW; int tmp = widx / nW;
    int hblk = tmp % nH;  int dblk = tmp / nH;

    const int hb = tl >> 4;
    const int n  = tl & 15;
    const int HW = Hsp * Wsp;
    int dd = n / HW; int r = n - dd * HW;
    int hh = r / Wsp; int ww = r - hh * Wsp;
    int l = ((dblk * Dsp + dd) * RESV + hblk * Hsp + hh) * RESV + wblk * Wsp + ww;

    size_t rowbase = ((size_t)b * L_TOT + l) * QKV_N + bi * 96 + hb * HDIM;

    __shared__ float sk[2][64][25];
    __shared__ float sv[2][64][25];
    float q[HDIM];
    const float scale = 0.2041241452319315f;

    const uint4* qp = (const uint4*)(qkv + rowbase);
    const uint4* kp = (const uint4*)(qkv + rowbase + CDIM);
    const uint4* vp = (const uint4*)(qkv + rowbase + 2 * CDIM);
#pragma unroll
    for (int j = 0; j < 3; j++) {
        uint4 uq = qp[j], uk = kp[j], uv = vp[j];
        __half2* hq = (__half2*)&uq;
        __half2* hk = (__half2*)&uk;
        __half2* hv = (__half2*)&uv;
#pragma unroll
        for (int e = 0; e < 4; e++) {
            float2 fq = __half22float2(hq[e]);
            q[8 * j + 2 * e]     = fq.x * scale;
            q[8 * j + 2 * e + 1] = fq.y * scale;
            float2 fk = __half22float2(hk[e]);
            sk[g][tl][8 * j + 2 * e]     = fk.x;
            sk[g][tl][8 * j + 2 * e + 1] = fk.y;
            float2 fv = __half22float2(hv[e]);
            sv[g][tl][8 * j + 2 * e]     = fv.x;
            sv[g][tl][8 * j + 2 * e + 1] = fv.y;
        }
    }
    __syncthreads();

    const float* brow = biasb + (((size_t)bi * HB + hb) * NWIN + n) * NWIN;
    float lg[NWIN];
    float mx = -1e30f;
#pragma unroll
    for (int m = 0; m < NWIN; m++) {
        float s = brow[m];
        const float* kr = sk[g][hb * 16 + m];
#pragma unroll
        for (int e = 0; e < HDIM; e++) s = fmaf(q[e], kr[e], s);
        lg[m] = s;
        mx = fmaxf(mx, s);
    }
    float sum = 0.f;
#pragma unroll
    for (int m = 0; m < NWIN; m++) { lg[m] = __expf(lg[m] - mx); sum += lg[m]; }
    float inv = 1.0f / sum;

    float o[HDIM];
#pragma unroll
    for (int e = 0; e < HDIM; e++) o[e] = 0.f;
#pragma unroll
    for (int m = 0; m < NWIN; m++) {
        float w = lg[m] * inv;
        const float* vr = sv[g][hb * 16 + m];
#pragma unroll
        for (int e = 0; e < HDIM; e++) o[e] = fmaf(w, vr[e], o[e]);
    }

    __half* yp = y + ((size_t)b * L_TOT + l) * CDIM + bi * 96 + hb * HDIM;
#pragma unroll
    for (int j = 0; j < 3; j++) {
        uint32_t u0 = pack_h2(o[8 * j + 0], o[8 * j + 1]);
        uint32_t u1 = pack_h2(o[8 * j + 2], o[8 * j + 3]);
        uint32_t u2 = pack_h2(o[8 * j + 4], o[8 * j + 5]);
        uint32_t u3 = pack_h2(o[8 * j + 6], o[8 * j + 7]);
        *(uint4*)(yp + 8 * j) = make_uint4(u0, u1, u2, u3);
    }
}

// ==================== depthwise 3x3x3 conv (channel-major, half IO) ====================
__global__ __launch_bounds__(256)
void conv3d_kernel(const __half* __restrict__ vc, const float* __restrict__ cw,
                   const float* __restrict__ cb, __half* __restrict__ lcm) {
    const int bc = blockIdx.x;          // b*288 + c
    const int c = bc % CDIM;
    const __half* src = vc + (size_t)bc * L_TOT;
    __half* dst = lcm + (size_t)bc * L_TOT;

    float wt[27];
#pragma unroll
    for (int j = 0; j < 27; j++) wt[j] = cw[c * 27 + j];
    const float bias = cb[c];

    __shared__ float sp[3][34][36];
    const int tid = threadIdx.x;
    const int w = tid & 31;
    const int h0 = (tid >> 5) * 4;

    for (int i = tid; i < 3 * 34 * 36; i += 256) ((float*)sp)[i] = 0.f;
    __syncthreads();
#pragma unroll
    for (int jh = 0; jh < 4; jh++) {
        int h = h0 + jh;
        sp[0][1 + h][1 + w] = __half2float(src[h * 32 + w]);
        sp[1][1 + h][1 + w] = __half2float(src[1024 + h * 32 + w]);
    }
    __syncthreads();

#pragma unroll 1
    for (int d = 0; d < 32; d++) {
        const int bm = (d + 2) % 3;
        const int b0 = d % 3;
        const int bp = (d + 1) % 3;
        float acc[4] = {bias, bias, bias, bias};

#define TAPS(BUF, KD) { \
        const float (*P)[36] = sp[BUF]; \
        _Pragma("unroll") \
        for (int rr = 0; rr < 6; rr++) { \
            float va = P[h0 + rr][w], vb = P[h0 + rr][w + 1], vcx = P[h0 + rr][w + 2]; \
            _Pragma("unroll") \
            for (int jh = 0; jh < 4; jh++) { \
                int kh = rr - jh; \
                if (kh >= 0 && kh < 3) { \
                    acc[jh] = fmaf(wt[(KD)*9 + kh*3 + 0], va, \
                              fmaf(wt[(KD)*9 + kh*3 + 1], vb, \
                              fmaf(wt[(KD)*9 + kh*3 + 2], vcx, acc[jh]))); \
                } \
            } \
        } }

        if (d > 0)  TAPS(bm, 0);
        TAPS(b0, 1);
        if (d < 31) TAPS(bp, 2);
#undef TAPS

#pragma unroll
        for (int jh = 0; jh < 4; jh++)
            dst[d * 1024 + (h0 + jh) * 32 + w] = __float2half(acc[jh]);

        __syncthreads();
        if (d + 2 < 32) {
            const __half* s2 = src + (d + 2) * 1024;
#pragma unroll
            for (int jh = 0; jh < 4; jh++) {
                int h = h0 + jh;
                sp[(d + 2) % 3][1 + h][1 + w] = __half2float(s2[h * 32 + w]);
            }
        }
        __syncthreads();
    }
}

// ==================== launch ====================
extern "C" void kernel_launch(void* const* d_in, const int* in_sizes, int n_in,
                              void* d_out, int out_size) {
    const float* x      = (const float*)d_in[0];
    const float* w_qkv  = (const float*)d_in[4];
    const float* w_proj = (const float*)d_in[5];
    const float* b_proj = (const float*)d_in[6];
    const float* conv_w = (const float*)d_in[7];
    const float* conv_b = (const float*)d_in[8];
    const float* pos_w  = (const float*)d_in[9];
    const float* pos_b  = (const float*)d_in[10];
    const float* ln1g   = (const float*)d_in[11];
    const float* ln1b   = (const float*)d_in[12];
    const float* lin1w  = (const float*)d_in[13];
    const float* lin1b  = (const float*)d_in[14];
    const float* ln2g   = (const float*)d_in[15];
    const float* ln2b   = (const float*)d_in[16];
    const float* lin2w  = (const float*)d_in[17];
    const float* lin2b  = (const float*)d_in[18];
    const float* ln3g   = (const float*)d_in[19];
    const float* ln3b   = (const float*)d_in[20];
    const float* lin3w  = (const float*)d_in[21];
    const float* lin3b  = (const float*)d_in[22];
    const float* rpe    = (const float*)d_in[23];
    const int*   relidx = (const int*)d_in[24];
    float* out = (float*)d_out;

    __half *xhp, *qkvp, *yp, *vcp, *lcmp, *wqkvT, *wprojT;
    float *bp;
    cudaGetSymbolAddress((void**)&xhp,    g_xh);
    cudaGetSymbolAddress((void**)&qkvp,   g_qkv);
    cudaGetSymbolAddress((void**)&yp,     g_y);
    cudaGetSymbolAddress((void**)&bp,     g_bias);
    cudaGetSymbolAddress((void**)&vcp,    g_vc);
    cudaGetSymbolAddress((void**)&lcmp,   g_lcm);
    cudaGetSymbolAddress((void**)&wqkvT,  g_wqkvT);
    cudaGetSymbolAddress((void**)&wprojT, g_wprojT);

    cudaFuncSetAttribute(gemm1_kernel, cudaFuncAttributeMaxDynamicSharedMemorySize, G1_SMEM);
    cudaFuncSetAttribute(gemm2_kernel, cudaFuncAttributeMaxDynamicSharedMemorySize, G2_SMEM);

    // 0) weight transposes (fp32 -> fp16), x -> half
    transpose_kernel<<<dim3(QKV_N / 32, CDIM / 32), dim3(32, 8)>>>(w_qkv, wqkvT, CDIM, QKV_N);
    transpose_kernel<<<dim3(CDIM / 32, CDIM / 32), dim3(32, 8)>>>(w_proj, wprojT, CDIM, CDIM);
    x2h_kernel<<<(NROWS * CDIM) / 2048, 256>>>(x, xhp);

    // 1) qkv = xh @ w_qkv  (launch index 3 -> gets the ncu capture slot)
    gemm1_kernel<<<dim3(NROWS / 128, QKV_N / 96), 256, G1_SMEM>>>(wqkvT, xhp, qkvp, vcp);

    // 2) RPE bias tables
    biasmlp_kernel<<<3, 64>>>(rpe, pos_w, pos_b,
                              ln1g, ln1b, lin1w, lin1b,
                              ln2g, ln2b, lin2w, lin2b,
                              ln3g, ln3b, lin3w, lin3b,
                              relidx, bp);

    // 3) windowed attention -> y (half)
    attn_kernel<<<dim3(1024, BATCH, 3), 128>>>(qkvp, bp, yp);

    // 4) depthwise conv(vc) -> lcm (channel-major, half)
    conv3d_kernel<<<BATCH * CDIM, 256>>>(vcp, conv_w, conv_b, lcmp);

    // 5) out = (y + lcm^T) @ w_proj + b_proj  (fp32 out)
    gemm2_kernel<<<dim3(NROWS / 128, CDIM / 96), 256, G2_SMEM>>>(wprojT, yp, lcmp, out, b_proj);
}

// round 8
// speedup vs baseline: 4.0969x; 1.0301x over previous
#include <cuda_runtime.h>
#include <cuda_fp16.h>
#include <math.h>
#include <stdint.h>

// ---------------- problem constants ----------------
#define RESV   32
#define L_TOT  (RESV*RESV*RESV)      // 32768
#define BATCH  2
#define CDIM   288
#define QKV_N  (3*CDIM)              // 864
#define NROWS  (BATCH*L_TOT)         // 65536
#define HB     4
#define HDIM   24
#define NWIN   16
#define TBIAS  63

// scratch (no cudaMalloc allowed) — fp16 intermediates
__device__ __half g_xh  [(size_t)NROWS * CDIM];          // x in fp16
__device__ __half g_qkv [(size_t)NROWS * QKV_N];         // (B*L, 864)
__device__ __half g_y   [(size_t)NROWS * CDIM];          // attention output
__device__ __half g_vc  [(size_t)BATCH * CDIM * L_TOT];  // v, channel-major [b][c][l]
__device__ __half g_lcm [(size_t)BATCH * CDIM * L_TOT];  // conv output, channel-major
__device__ __half g_wqkvT[(size_t)QKV_N * CDIM];         // w_qkv^T  (864, 288)
__device__ __half g_wprojT[(size_t)CDIM * CDIM];         // w_proj^T (288, 288)
__device__ float  g_bias[3 * HB * NWIN * NWIN];

__constant__ int c_Dsp[3] = {2, 2, 2};
__constant__ int c_Hsp[3] = {2, 2, 4};
__constant__ int c_Wsp[3] = {4, 4, 2};

// ==================== helpers ====================
__device__ __forceinline__ uint32_t smem_u32_of(const void* p) {
    uint32_t a;
    asm("{ .reg .u64 t; cvta.to.shared.u64 t, %1; cvt.u32.u64 %0, t; }" : "=r"(a) : "l"(p));
    return a;
}

__device__ __forceinline__ void mma16(float* d,
                                      uint32_t a0, uint32_t a1, uint32_t a2, uint32_t a3,
                                      uint32_t b0, uint32_t b1) {
    asm volatile("mma.sync.aligned.m16n8k16.row.col.f32.f16.f16.f32 "
                 "{%0,%1,%2,%3}, {%4,%5,%6,%7}, {%8,%9}, {%0,%1,%2,%3};"
                 : "+f"(d[0]), "+f"(d[1]), "+f"(d[2]), "+f"(d[3])
                 : "r"(a0), "r"(a1), "r"(a2), "r"(a3), "r"(b0), "r"(b1));
}

__device__ __forceinline__ void ldsm4(uint32_t& r0, uint32_t& r1, uint32_t& r2, uint32_t& r3,
                                      uint32_t addr) {
    asm volatile("ldmatrix.sync.aligned.m8n8.x4.shared.b16 {%0,%1,%2,%3}, [%4];"
                 : "=r"(r0), "=r"(r1), "=r"(r2), "=r"(r3) : "r"(addr));
}

__device__ __forceinline__ uint32_t pack_h2(float x, float y) {
    __half2 h = __floats2half2_rn(x, y);
    return *(uint32_t*)&h;
}

#define CP16(dst, src) \
    asm volatile("cp.async.cg.shared.global [%0], [%1], 16;" :: "r"(dst), "l"(src))
#define CP_COMMIT() asm volatile("cp.async.commit_group;")
#define CP_WAIT1()  asm volatile("cp.async.wait_group 1;")
#define CP_WAIT0()  asm volatile("cp.async.wait_group 0;")

// ==================== x -> half ====================
__global__ __launch_bounds__(256)
void x2h_kernel(const float* __restrict__ x, __half* __restrict__ xh) {
    size_t i = ((size_t)blockIdx.x * 256 + threadIdx.x) * 8;
    float4 a = *(const float4*)(x + i);
    float4 b = *(const float4*)(x + i + 4);
    uint4 u = make_uint4(pack_h2(a.x, a.y), pack_h2(a.z, a.w),
                         pack_h2(b.x, b.y), pack_h2(b.z, b.w));
    *(uint4*)(xh + i) = u;
}

// ==================== GEMM1: cp.async 3-stage + ldmatrix ====================
// qkv[token][chan] = xh[token][288] @ wqkvT[chan][288]^T
// BM=96 chans, BN=128 tokens, BK=32, 9 chunks. Also writes v channel-major -> vc.
// Stage (bytes): A 96x80 (7680), B 128x80 (10240); 3 stages = 53760.
#define G1_SMEM 53760

__global__ __launch_bounds__(256)
void gemm1_kernel(const __half* __restrict__ Aw, const __half* __restrict__ Bx,
                  __half* __restrict__ Ch, __half* __restrict__ vc) {
    extern __shared__ float smf[];
    const uint32_t smb = smem_u32_of(smf);
    const int tid = threadIdx.x, lane = tid & 31, warp = tid >> 5;
    const int qr = lane >> 2, qc = lane & 3;
    const int wm = warp & 1, wn = warp >> 1;   // 48 chans x 32 tokens per warp
    const int n0 = blockIdx.x * 128;           // token tile
    const int m0 = blockIdx.y * 96;            // chan tile
    const int bb = n0 >> 15;
    const int l0 = n0 & (L_TOT - 1);

    // ldmatrix per-lane address offsets (bytes, row stride 80)
    const int g8 = lane >> 3, lr = lane & 7;
    const int rowA = lr + (g8 & 1) * 8, colA = (g8 >> 1) * 16;
    const int rowB = lr + (g8 >> 1) * 8, colB = (g8 & 1) * 16;
    uint32_t aoff[3], boff[2];
#pragma unroll
    for (int mt = 0; mt < 3; mt++)
        aoff[mt] = (wm * 48 + mt * 16 + rowA) * 80 + colA;
#pragma unroll
    for (int p = 0; p < 2; p++)
        boff[p] = 7680 + (wn * 32 + p * 16 + rowB) * 80 + colB;

    float acc[3][4][4];
#pragma unroll
    for (int mt = 0; mt < 3; mt++)
#pragma unroll
        for (int nt = 0; nt < 4; nt++)
#pragma unroll
            for (int r = 0; r < 4; r++) acc[mt][nt][r] = 0.0f;

#define ISSUE(S, K0) do { \
    uint32_t base = smb + (S) * 17920; \
    { int idx = tid; \
      int r = idx >> 2, c = idx & 3; \
      CP16(base + r * 80 + c * 16, Aw + (size_t)(m0 + r) * CDIM + (K0) + c * 8); } \
    if (tid < 128) { int idx = tid + 256; \
      int r = idx >> 2, c = idx & 3; \
      CP16(base + r * 80 + c * 16, Aw + (size_t)(m0 + r) * CDIM + (K0) + c * 8); } \
    _Pragma("unroll") for (int i = 0; i < 2; i++) { \
      int idx = tid + i * 256; \
      int r = idx >> 2, c = idx & 3; \
      CP16(base + 7680 + r * 80 + c * 16, Bx + (size_t)(n0 + r) * CDIM + (K0) + c * 8); } \
    CP_COMMIT(); \
} while (0)

    ISSUE(0, 0);
    ISSUE(1, 32);

#pragma unroll 1
    for (int ch = 0; ch < 9; ch++) {
        if (ch < 8) { CP_WAIT1(); } else { CP_WAIT0(); }
        __syncthreads();
        if (ch < 7) ISSUE((ch + 2) % 3, (ch + 2) * 32);

        const uint32_t sb = smb + (ch % 3) * 17920;
#pragma unroll
        for (int s = 0; s < 2; s++) {
            const int so = s * 32;
            uint32_t af[3][4], bf[2][4];
#pragma unroll
            for (int mt = 0; mt < 3; mt++)
                ldsm4(af[mt][0], af[mt][1], af[mt][2], af[mt][3], sb + aoff[mt] + so);
#pragma unroll
            for (int p = 0; p < 2; p++)
                ldsm4(bf[p][0], bf[p][1], bf[p][2], bf[p][3], sb + boff[p] + so);
#pragma unroll
            for (int mt = 0; mt < 3; mt++)
#pragma unroll
                for (int nt = 0; nt < 4; nt++)
                    mma16(acc[mt][nt], af[mt][0], af[mt][1], af[mt][2], af[mt][3],
                          bf[nt >> 1][(nt & 1) * 2], bf[nt >> 1][(nt & 1) * 2 + 1]);
        }
        __syncthreads();
    }
#undef ISSUE

    // ==================== epilogue ====================
    float* stg = smf;                  // [96][133]: [chan][token]
#pragma unroll
    for (int mt = 0; mt < 3; mt++) {
        int r0 = wm * 48 + mt * 16 + qr;
#pragma unroll
        for (int nt = 0; nt < 4; nt++) {
            int c0 = wn * 32 + nt * 8 + 2 * qc;
            stg[r0 * 133 + c0]           = acc[mt][nt][0];
            stg[r0 * 133 + c0 + 1]       = acc[mt][nt][1];
            stg[(r0 + 8) * 133 + c0]     = acc[mt][nt][2];
            stg[(r0 + 8) * 133 + c0 + 1] = acc[mt][nt][3];
        }
    }
    __syncthreads();

    // qkv half writes: 128 tokens x 12 uint4 (8 chans each)
#pragma unroll
    for (int i = 0; i < 6; i++) {
        int idx = tid + i * 256;
        int t = idx / 12, q = idx - t * 12;
        uint32_t u0 = pack_h2(stg[(q * 8 + 0) * 133 + t], stg[(q * 8 + 1) * 133 + t]);
        uint32_t u1 = pack_h2(stg[(q * 8 + 2) * 133 + t], stg[(q * 8 + 3) * 133 + t]);
        uint32_t u2 = pack_h2(stg[(q * 8 + 4) * 133 + t], stg[(q * 8 + 5) * 133 + t]);
        uint32_t u3 = pack_h2(stg[(q * 8 + 6) * 133 + t], stg[(q * 8 + 7) * 133 + t]);
        *(uint4*)(Ch + (size_t)(n0 + t) * QKV_N + m0 + q * 8) = make_uint4(u0, u1, u2, u3);
    }
    if (m0 >= 2 * CDIM) {
#pragma unroll
        for (int i = 0; i < 6; i++) {
            int idx = tid + i * 256;
            int m = idx >> 4, c8 = (idx & 15) * 8;
            uint32_t u0 = pack_h2(stg[m * 133 + c8 + 0], stg[m * 133 + c8 + 1]);
            uint32_t u1 = pack_h2(stg[m * 133 + c8 + 2], stg[m * 133 + c8 + 3]);
            uint32_t u2 = pack_h2(stg[m * 133 + c8 + 4], stg[m * 133 + c8 + 5]);
            uint32_t u3 = pack_h2(stg[m * 133 + c8 + 6], stg[m * 133 + c8 + 7]);
            *(uint4*)(vc + ((size_t)bb * CDIM + (m0 - 2 * CDIM) + m) * L_TOT + l0 + c8)
                = make_uint4(u0, u1, u2, u3);
        }
    }
}

// ==================== GEMM2: out = (y + lcm^T) @ w_proj + bias ====================
// smem bytes: As 96x80 x2 @ {0,7680}; Bs 128x80 x2 @ {15360,25600}
// LS lcm stage floats [128][33] @ float offset 8960; epilogue stage [96][133] @ 0
#define G2_SMEM 52736

__global__ __launch_bounds__(256)
void gemm2_kernel(const __half* __restrict__ Aw, const __half* __restrict__ By,
                  const __half* __restrict__ lcm, float* __restrict__ Cf,
                  const float* __restrict__ bias) {
    extern __shared__ float smf[];
    uint32_t* smh2 = (uint32_t*)smf;
    float* LS = smf + 8960;                    // [128][33]
    const uint32_t smb = smem_u32_of(smf);
    const int tid = threadIdx.x, lane = tid & 31, warp = tid >> 5;
    const int qr = lane >> 2, qc = lane & 3;
    const int wm = warp & 1, wn = warp >> 1;
    const int n0 = blockIdx.x * 128;
    const int m0 = blockIdx.y * 96;
    const int bb = n0 >> 15;
    const int l0 = n0 & (L_TOT - 1);

    const int g8 = lane >> 3, lr = lane & 7;
    const int rowA = lr + (g8 & 1) * 8, colA = (g8 >> 1) * 16;
    const int rowB = lr + (g8 >> 1) * 8, colB = (g8 & 1) * 16;
    uint32_t aoff[3], boff[2];
#pragma unroll
    for (int mt = 0; mt < 3; mt++)
        aoff[mt] = (wm * 48 + mt * 16 + rowA) * 80 + colA;
#pragma unroll
    for (int p = 0; p < 2; p++)
        boff[p] = 15360 + (wn * 32 + p * 16 + rowB) * 80 + colB;

    float acc[3][4][4];
#pragma unroll
    for (int mt = 0; mt < 3; mt++)
#pragma unroll
        for (int nt = 0; nt < 4; nt++)
#pragma unroll
            for (int r = 0; r < 4; r++) acc[mt][nt][r] = 0.0f;

    uint2 rA[3];
    uint4 rBy[2], rLc[2];

#define G_LOADS(K0) do { \
    _Pragma("unroll") for (int i = 0; i < 3; i++) { \
        int idx = tid + i * 256; int m = idx >> 3, q = idx & 7; \
        rA[i] = *(const uint2*)(Aw + (size_t)(m0 + m) * CDIM + (K0) + q * 4); } \
    _Pragma("unroll") for (int i = 0; i < 2; i++) { \
        int idx = tid + i * 256; int t = idx >> 2, k8 = (idx & 3) * 8; \
        rBy[i] = *(const uint4*)(By + (size_t)(n0 + t) * CDIM + (K0) + k8); } \
    _Pragma("unroll") for (int i = 0; i < 2; i++) { \
        int idx = tid + i * 256; int cc = idx >> 4, l8 = (idx & 15) * 8; \
        rLc[i] = *(const uint4*)(lcm + ((size_t)bb * CDIM + (K0) + cc) * L_TOT + l0 + l8); } \
} while (0)

#define S_STORES(BUF) do { \
    uint32_t* As_ = smh2 + ((BUF) ? 1920 : 0); \
    uint32_t* Bs_ = smh2 + ((BUF) ? 6400 : 3840); \
    _Pragma("unroll") for (int i = 0; i < 2; i++) { \
        int idx = tid + i * 256; int cc = idx >> 4, l8 = (idx & 15) * 8; \
        __half2* hh = (__half2*)&rLc[i]; \
        _Pragma("unroll") for (int e = 0; e < 4; e++) { \
            float2 f = __half22float2(hh[e]); \
            LS[(l8 + 2 * e) * 33 + cc]     = f.x; \
            LS[(l8 + 2 * e + 1) * 33 + cc] = f.y; } } \
    __syncthreads(); \
    _Pragma("unroll") for (int i = 0; i < 3; i++) { \
        int idx = tid + i * 256; int m = idx >> 3, q = idx & 7; \
        *(uint2*)(As_ + m * 20 + q * 2) = rA[i]; } \
    _Pragma("unroll") for (int i = 0; i < 2; i++) { \
        int idx = tid + i * 256; int t = idx >> 2, k8 = (idx & 3) * 8; \
        __half2* hh = (__half2*)&rBy[i]; \
        uint32_t u0, u1, u2, u3; \
        { float2 f = __half22float2(hh[0]); \
          u0 = pack_h2(f.x + LS[t * 33 + k8 + 0], f.y + LS[t * 33 + k8 + 1]); } \
        { float2 f = __half22float2(hh[1]); \
          u1 = pack_h2(f.x + LS[t * 33 + k8 + 2], f.y + LS[t * 33 + k8 + 3]); } \
        { float2 f = __half22float2(hh[2]); \
          u2 = pack_h2(f.x + LS[t * 33 + k8 + 4], f.y + LS[t * 33 + k8 + 5]); } \
        { float2 f = __half22float2(hh[3]); \
          u3 = pack_h2(f.x + LS[t * 33 + k8 + 6], f.y + LS[t * 33 + k8 + 7]); } \
        *(uint4*)(Bs_ + t * 20 + (k8 >> 1)) = make_uint4(u0, u1, u2, u3); } \
} while (0)

    G_LOADS(0);
    S_STORES(0);
    __syncthreads();

#pragma unroll 1
    for (int ch = 0; ch < 9; ch++) {
        const int cur = ch & 1;
        if (ch < 8) G_LOADS((ch + 1) * 32);

        const uint32_t abase = smb + (cur ? 7680 : 0);
        const uint32_t bbase = smb + (cur ? 10240 : 0);
#pragma unroll
        for (int s = 0; s < 2; s++) {
            const int so = s * 32;
            uint32_t af[3][4], bf[2][4];
#pragma unroll
            for (int mt = 0; mt < 3; mt++)
                ldsm4(af[mt][0], af[mt][1], af[mt][2], af[mt][3], abase + aoff[mt] + so);
#pragma unroll
            for (int p = 0; p < 2; p++)
                ldsm4(bf[p][0], bf[p][1], bf[p][2], bf[p][3], bbase + boff[p] + so);
#pragma unroll
            for (int mt = 0; mt < 3; mt++)
#pragma unroll
                for (int nt = 0; nt < 4; nt++)
                    mma16(acc[mt][nt], af[mt][0], af[mt][1], af[mt][2], af[mt][3],
                          bf[nt >> 1][(nt & 1) * 2], bf[nt >> 1][(nt & 1) * 2 + 1]);
        }

        if (ch < 8) {
            S_STORES(cur ^ 1);
            __syncthreads();
        }
    }
#undef G_LOADS
#undef S_STORES

    __syncthreads();
    float* stg = smf;                  // [96][133]
#pragma unroll
    for (int mt = 0; mt < 3; mt++) {
        int r0 = wm * 48 + mt * 16 + qr;
#pragma unroll
        for (int nt = 0; nt < 4; nt++) {
            int c0 = wn * 32 + nt * 8 + 2 * qc;
            stg[r0 * 133 + c0]           = acc[mt][nt][0];
            stg[r0 * 133 + c0 + 1]       = acc[mt][nt][1];
            stg[(r0 + 8) * 133 + c0]     = acc[mt][nt][2];
            stg[(r0 + 8) * 133 + c0 + 1] = acc[mt][nt][3];
        }
    }
    __syncthreads();

#pragma unroll
    for (int i = 0; i < 12; i++) {
        int idx = tid + i * 256;
        int t = idx / 24, q = idx - t * 24;
        float4 o;
        o.x = stg[(q * 4 + 0) * 133 + t] + bias[m0 + q * 4 + 0];
        o.y = stg[(q * 4 + 1) * 133 + t] + bias[m0 + q * 4 + 1];
        o.z = stg[(q * 4 + 2) * 133 + t] + bias[m0 + q * 4 + 2];
        o.w = stg[(q * 4 + 3) * 133 + t] + bias[m0 + q * 4 + 3];
        *(float4*)(Cf + (size_t)(n0 + t) * CDIM + m0 + q * 4) = o;
    }
}

// ==================== weight transpose (fp32 -> fp16) ====================
__global__ void transpose_kernel(const float* __restrict__ in, __half* __restrict__ out,
                                 int R, int Cc) {   // in (R, Cc) -> out (Cc, R)
    __shared__ float t[32][33];
    int bx = blockIdx.x * 32, by = blockIdx.y * 32;
    int x = threadIdx.x, y = threadIdx.y;
#pragma unroll
    for (int j = 0; j < 4; j++) t[y + 8 * j][x] = in[(size_t)(by + y + 8 * j) * Cc + bx + x];
    __syncthreads();
#pragma unroll
    for (int j = 0; j < 4; j++)
        out[(size_t)(bx + y + 8 * j) * R + by + x] = __float2half(t[x][y + 8 * j]);
}

// ==================== RPE-bias MLP ====================
__device__ __forceinline__ void ln_relu6(float* h, const float* g, const float* b) {
    float m = 0.f;
#pragma unroll
    for (int j = 0; j < 6; j++) m += h[j];
    m *= (1.0f / 6.0f);
    float v = 0.f;
#pragma unroll
    for (int j = 0; j < 6; j++) { float d = h[j] - m; v += d * d; }
    v *= (1.0f / 6.0f);
    float inv = rsqrtf(v + 1e-5f);
#pragma unroll
    for (int j = 0; j < 6; j++) {
        float t = (h[j] - m) * inv * g[j] + b[j];
        h[j] = t > 0.f ? t : 0.f;
    }
}

__global__ void biasmlp_kernel(const float* __restrict__ rpe,
                               const float* __restrict__ pw, const float* __restrict__ pb,
                               const float* __restrict__ g1, const float* __restrict__ be1,
                               const float* __restrict__ w1, const float* __restrict__ b1,
                               const float* __restrict__ g2, const float* __restrict__ be2,
                               const float* __restrict__ w2, const float* __restrict__ b2,
                               const float* __restrict__ g3, const float* __restrict__ be3,
                               const float* __restrict__ w3, const float* __restrict__ b3,
                               const int* __restrict__ relidx,
                               float* __restrict__ biasb) {
    int bi = blockIdx.x;
    int t = threadIdx.x;
    __shared__ float p[TBIAS][HB];

    if (t < TBIAS) {
        float h[6], tmp[6];
        const float* r = rpe + (bi * TBIAS + t) * 3;
        float r0 = r[0], r1 = r[1], r2 = r[2];
#pragma unroll
        for (int j = 0; j < 6; j++)
            h[j] = pb[bi * 6 + j]
                 + r0 * pw[(bi * 3 + 0) * 6 + j]
                 + r1 * pw[(bi * 3 + 1) * 6 + j]
                 + r2 * pw[(bi * 3 + 2) * 6 + j];
        ln_relu6(h, g1 + bi * 6, be1 + bi * 6);
#pragma unroll
        for (int j = 0; j < 6; j++) {
            float s = b1[bi * 6 + j];
#pragma unroll
            for (int i = 0; i < 6; i++) s += h[i] * w1[(bi * 6 + i) * 6 + j];
            tmp[j] = s;
        }
#pragma unroll
        for (int j = 0; j < 6; j++) h[j] = tmp[j];
        ln_relu6(h, g2 + bi * 6, be2 + bi * 6);
#pragma unroll
        for (int j = 0; j < 6; j++) {
            float s = b2[bi * 6 + j];
#pragma unroll
            for (int i = 0; i < 6; i++) s += h[i] * w2[(bi * 6 + i) * 6 + j];
            tmp[j] = s;
        }
#pragma unroll
        for (int j = 0; j < 6; j++) h[j] = tmp[j];
        ln_relu6(h, g3 + bi * 6, be3 + bi * 6);
#pragma unroll
        for (int j = 0; j < HB; j++) {
            float s = b3[bi * HB + j];
#pragma unroll
            for (int i = 0; i < 6; i++) s += h[i] * w3[(bi * 6 + i) * HB + j];
            p[t][j] = s;
        }
    }
    __syncthreads();

    for (int i = t; i < HB * NWIN * NWIN; i += blockDim.x) {
        int hb = i >> 8;
        int nm = i & 255;
        biasb[bi * (HB * NWIN * NWIN) + i] = p[relidx[bi * 256 + nm]][hb];
    }
}

// ==================== windowed attention (half IO, 2 windows/block) ====================
__global__ __launch_bounds__(128)
void attn_kernel(const __half* __restrict__ qkv, const float* __restrict__ biasb,
                 __half* __restrict__ y) {
    const int bi = blockIdx.z;
    const int b  = blockIdx.y;
    const int Dsp = c_Dsp[bi], Hsp = c_Hsp[bi], Wsp = c_Wsp[bi];
    const int nH = RESV / Hsp, nW = RESV / Wsp;
    const int t  = threadIdx.x;
    const int g  = t >> 6;
    const int tl = t & 63;
    int widx = blockIdx.x * 2 + g;
    int wblk = widx % nW; int tmp = widx / nW;
    int hblk = tmp % nH;  int dblk = tmp / nH;

    const int hb = tl >> 4;
    const int n  = tl & 15;
    const int HW = Hsp * Wsp;
    int dd = n / HW; int r = n - dd * HW;
    int hh = r / Wsp; int ww = r - hh * Wsp;
    int l = ((dblk * Dsp + dd) * RESV + hblk * Hsp + hh) * RESV + wblk * Wsp + ww;

    size_t rowbase = ((size_t)b * L_TOT + l) * QKV_N + bi * 96 + hb * HDIM;

    __shared__ float sk[2][64][25];
    __shared__ float sv[2][64][25];
    float q[HDIM];
    const float scale = 0.2041241452319315f;

    const uint4* qp = (const uint4*)(qkv + rowbase);
    const uint4* kp = (const uint4*)(qkv + rowbase + CDIM);
    const uint4* vp = (const uint4*)(qkv + rowbase + 2 * CDIM);
#pragma unroll
    for (int j = 0; j < 3; j++) {
        uint4 uq = qp[j], uk = kp[j], uv = vp[j];
        __half2* hq = (__half2*)&uq;
        __half2* hk = (__half2*)&uk;
        __half2* hv = (__half2*)&uv;
#pragma unroll
        for (int e = 0; e < 4; e++) {
            float2 fq = __half22float2(hq[e]);
            q[8 * j + 2 * e]     = fq.x * scale;
            q[8 * j + 2 * e + 1] = fq.y * scale;
            float2 fk = __half22float2(hk[e]);
            sk[g][tl][8 * j + 2 * e]     = fk.x;
            sk[g][tl][8 * j + 2 * e + 1] = fk.y;
            float2 fv = __half22float2(hv[e]);
            sv[g][tl][8 * j + 2 * e]     = fv.x;
            sv[g][tl][8 * j + 2 * e + 1] = fv.y;
        }
    }
    __syncthreads();

    const float* brow = biasb + (((size_t)bi * HB + hb) * NWIN + n) * NWIN;
    float lg[NWIN];
    float mx = -1e30f;
#pragma unroll
    for (int m = 0; m < NWIN; m++) {
        float s = brow[m];
        const float* kr = sk[g][hb * 16 + m];
#pragma unroll
        for (int e = 0; e < HDIM; e++) s = fmaf(q[e], kr[e], s);
        lg[m] = s;
        mx = fmaxf(mx, s);
    }
    float sum = 0.f;
#pragma unroll
    for (int m = 0; m < NWIN; m++) { lg[m] = __expf(lg[m] - mx); sum += lg[m]; }
    float inv = 1.0f / sum;

    float o[HDIM];
#pragma unroll
    for (int e = 0; e < HDIM; e++) o[e] = 0.f;
#pragma unroll
    for (int m = 0; m < NWIN; m++) {
        float w = lg[m] * inv;
        const float* vr = sv[g][hb * 16 + m];
#pragma unroll
        for (int e = 0; e < HDIM; e++) o[e] = fmaf(w, vr[e], o[e]);
    }

    __half* yp = y + ((size_t)b * L_TOT + l) * CDIM + bi * 96 + hb * HDIM;
#pragma unroll
    for (int j = 0; j < 3; j++) {
        uint32_t u0 = pack_h2(o[8 * j + 0], o[8 * j + 1]);
        uint32_t u1 = pack_h2(o[8 * j + 2], o[8 * j + 3]);
        uint32_t u2 = pack_h2(o[8 * j + 4], o[8 * j + 5]);
        uint32_t u3 = pack_h2(o[8 * j + 6], o[8 * j + 7]);
        *(uint4*)(yp + 8 * j) = make_uint4(u0, u1, u2, u3);
    }
}

// ==================== depthwise 3x3x3 conv (channel-major, half IO) ====================
__global__ __launch_bounds__(256)
void conv3d_kernel(const __half* __restrict__ vc, const float* __restrict__ cw,
                   const float* __restrict__ cb, __half* __restrict__ lcm) {
    const int bc = blockIdx.x;          // b*288 + c
    const int c = bc % CDIM;
    const __half* src = vc + (size_t)bc * L_TOT;
    __half* dst = lcm + (size_t)bc * L_TOT;

    float wt[27];
#pragma unroll
    for (int j = 0; j < 27; j++) wt[j] = cw[c * 27 + j];
    const float bias = cb[c];

    __shared__ float sp[3][34][36];
    const int tid = threadIdx.x;
    const int w = tid & 31;
    const int h0 = (tid >> 5) * 4;

    for (int i = tid; i < 3 * 34 * 36; i += 256) ((float*)sp)[i] = 0.f;
    __syncthreads();
#pragma unroll
    for (int jh = 0; jh < 4; jh++) {
        int h = h0 + jh;
        sp[0][1 + h][1 + w] = __half2float(src[h * 32 + w]);
        sp[1][1 + h][1 + w] = __half2float(src[1024 + h * 32 + w]);
    }
    __syncthreads();

#pragma unroll 1
    for (int d = 0; d < 32; d++) {
        const int bm = (d + 2) % 3;
        const int b0 = d % 3;
        const int bp = (d + 1) % 3;
        float acc[4] = {bias, bias, bias, bias};

#define TAPS(BUF, KD) { \
        const float (*P)[36] = sp[BUF]; \
        _Pragma("unroll") \
        for (int rr = 0; rr < 6; rr++) { \
            float va = P[h0 + rr][w], vb = P[h0 + rr][w + 1], vcx = P[h0 + rr][w + 2]; \
            _Pragma("unroll") \
            for (int jh = 0; jh < 4; jh++) { \
                int kh = rr - jh; \
                if (kh >= 0 && kh < 3) { \
                    acc[jh] = fmaf(wt[(KD)*9 + kh*3 + 0], va, \
                              fmaf(wt[(KD)*9 + kh*3 + 1], vb, \
                              fmaf(wt[(KD)*9 + kh*3 + 2], vcx, acc[jh]))); \
                } \
            } \
        } }

        if (d > 0)  TAPS(bm, 0);
        TAPS(b0, 1);
        if (d < 31) TAPS(bp, 2);
#undef TAPS

#pragma unroll
        for (int jh = 0; jh < 4; jh++)
            dst[d * 1024 + (h0 + jh) * 32 + w] = __float2half(acc[jh]);

        __syncthreads();
        if (d + 2 < 32) {
            const __half* s2 = src + (d + 2) * 1024;
#pragma unroll
            for (int jh = 0; jh < 4; jh++) {
                int h = h0 + jh;
                sp[(d + 2) % 3][1 + h][1 + w] = __half2float(s2[h * 32 + w]);
            }
        }
        __syncthreads();
    }
}

// ==================== launch ====================
extern "C" void kernel_launch(void* const* d_in, const int* in_sizes, int n_in,
                              void* d_out, int out_size) {
    const float* x      = (const float*)d_in[0];
    const float* w_qkv  = (const float*)d_in[4];
    const float* w_proj = (const float*)d_in[5];
    const float* b_proj = (const float*)d_in[6];
    const float* conv_w = (const float*)d_in[7];
    const float* conv_b = (const float*)d_in[8];
    const float* pos_w  = (const float*)d_in[9];
    const float* pos_b  = (const float*)d_in[10];
    const float* ln1g   = (const float*)d_in[11];
    const float* ln1b   = (const float*)d_in[12];
    const float* lin1w  = (const float*)d_in[13];
    const float* lin1b  = (const float*)d_in[14];
    const float* ln2g   = (const float*)d_in[15];
    const float* ln2b   = (const float*)d_in[16];
    const float* lin2w  = (const float*)d_in[17];
    const float* lin2b  = (const float*)d_in[18];
    const float* ln3g   = (const float*)d_in[19];
    const float* ln3b   = (const float*)d_in[20];
    const float* lin3w  = (const float*)d_in[21];
    const float* lin3b  = (const float*)d_in[22];
    const float* rpe    = (const float*)d_in[23];
    const int*   relidx = (const int*)d_in[24];
    float* out = (float*)d_out;

    __half *xhp, *qkvp, *yp, *vcp, *lcmp, *wqkvT, *wprojT;
    float *bp;
    cudaGetSymbolAddress((void**)&xhp,    g_xh);
    cudaGetSymbolAddress((void**)&qkvp,   g_qkv);
    cudaGetSymbolAddress((void**)&yp,     g_y);
    cudaGetSymbolAddress((void**)&bp,     g_bias);
    cudaGetSymbolAddress((void**)&vcp,    g_vc);
    cudaGetSymbolAddress((void**)&lcmp,   g_lcm);
    cudaGetSymbolAddress((void**)&wqkvT,  g_wqkvT);
    cudaGetSymbolAddress((void**)&wprojT, g_wprojT);

    cudaFuncSetAttribute(gemm1_kernel, cudaFuncAttributeMaxDynamicSharedMemorySize, G1_SMEM);
    cudaFuncSetAttribute(gemm2_kernel, cudaFuncAttributeMaxDynamicSharedMemorySize, G2_SMEM);

    // 0) weight transposes (fp32 -> fp16), x -> half
    transpose_kernel<<<dim3(QKV_N / 32, CDIM / 32), dim3(32, 8)>>>(w_qkv, wqkvT, CDIM, QKV_N);
    transpose_kernel<<<dim3(CDIM / 32, CDIM / 32), dim3(32, 8)>>>(w_proj, wprojT, CDIM, CDIM);
    x2h_kernel<<<(NROWS * CDIM) / 2048, 256>>>(x, xhp);

    // 1) qkv = xh @ w_qkv  (launch index 3 -> ncu capture slot)
    gemm1_kernel<<<dim3(NROWS / 128, QKV_N / 96), 256, G1_SMEM>>>(wqkvT, xhp, qkvp, vcp);

    // 2) RPE bias tables
    biasmlp_kernel<<<3, 64>>>(rpe, pos_w, pos_b,
                              ln1g, ln1b, lin1w, lin1b,
                              ln2g, ln2b, lin2w, lin2b,
                              ln3g, ln3b, lin3w, lin3b,
                              relidx, bp);

    // 3) windowed attention -> y (half)
    attn_kernel<<<dim3(1024, BATCH, 3), 128>>>(qkvp, bp, yp);

    // 4) depthwise conv(vc) -> lcm (channel-major, half)
    conv3d_kernel<<<BATCH * CDIM, 256>>>(vcp, conv_w, conv_b, lcmp);

    // 5) out = (y + lcm^T) @ w_proj + b_proj  (fp32 out)
    gemm2_kernel<<<dim3(NROWS / 128, CDIM / 96), 256, G2_SMEM>>>(wprojT, yp, lcmp, out, b_proj);
}

// round 9
// speedup vs baseline: 4.1535x; 1.0138x over previous
#include <cuda_runtime.h>
#include <cuda_fp16.h>
#include <math.h>
#include <stdint.h>

// ---------------- problem constants ----------------
#define RESV   32
#define L_TOT  (RESV*RESV*RESV)      // 32768
#define BATCH  2
#define CDIM   288
#define QKV_N  (3*CDIM)              // 864
#define NROWS  (BATCH*L_TOT)         // 65536
#define HB     4
#define HDIM   24
#define NWIN   16
#define TBIAS  63

// scratch (no cudaMalloc allowed) — fp16 intermediates
__device__ __half g_xh  [(size_t)NROWS * CDIM];
__device__ __half g_qkv [(size_t)NROWS * QKV_N];
__device__ __half g_y   [(size_t)NROWS * CDIM];
__device__ __half g_vc  [(size_t)BATCH * CDIM * L_TOT];  // v, channel-major
__device__ __half g_lcm [(size_t)BATCH * CDIM * L_TOT];  // conv out, channel-major
__device__ __half g_wqkvT[(size_t)QKV_N * CDIM];
__device__ __half g_wprojT[(size_t)CDIM * CDIM];
__device__ float  g_bias[3 * HB * NWIN * NWIN];

__constant__ int c_Dsp[3] = {2, 2, 2};
__constant__ int c_Hsp[3] = {2, 2, 4};
__constant__ int c_Wsp[3] = {4, 4, 2};

// ==================== helpers ====================
__device__ __forceinline__ uint32_t smem_u32_of(const void* p) {
    uint32_t a;
    asm("{ .reg .u64 t; cvta.to.shared.u64 t, %1; cvt.u32.u64 %0, t; }" : "=r"(a) : "l"(p));
    return a;
}

__device__ __forceinline__ void mma16(float* d,
                                      uint32_t a0, uint32_t a1, uint32_t a2, uint32_t a3,
                                      uint32_t b0, uint32_t b1) {
    asm volatile("mma.sync.aligned.m16n8k16.row.col.f32.f16.f16.f32 "
                 "{%0,%1,%2,%3}, {%4,%5,%6,%7}, {%8,%9}, {%0,%1,%2,%3};"
                 : "+f"(d[0]), "+f"(d[1]), "+f"(d[2]), "+f"(d[3])
                 : "r"(a0), "r"(a1), "r"(a2), "r"(a3), "r"(b0), "r"(b1));
}

__device__ __forceinline__ void ldsm4(uint32_t& r0, uint32_t& r1, uint32_t& r2, uint32_t& r3,
                                      uint32_t addr) {
    asm volatile("ldmatrix.sync.aligned.m8n8.x4.shared.b16 {%0,%1,%2,%3}, [%4];"
                 : "=r"(r0), "=r"(r1), "=r"(r2), "=r"(r3) : "r"(addr));
}

__device__ __forceinline__ uint32_t pack_h2(float x, float y) {
    __half2 h = __floats2half2_rn(x, y);
    return *(uint32_t*)&h;
}

#define CP16(dst, src) \
    asm volatile("cp.async.cg.shared.global [%0], [%1], 16;" :: "r"(dst), "l"(src))
#define CP_COMMIT() asm volatile("cp.async.commit_group;")
#define CP_WAIT2()  asm volatile("cp.async.wait_group 2;")
#define CP_WAIT1()  asm volatile("cp.async.wait_group 1;")
#define CP_WAIT0()  asm volatile("cp.async.wait_group 0;")

// ==================== fused prep: x->half + both weight transposes ====================
#define X2H_BLOCKS 9216                 // NROWS*CDIM/2048
#define TQ_BLOCKS  (27 * 9)             // 864/32 x 288/32
#define TP_BLOCKS  (9 * 9)
#define PREP_BLOCKS (X2H_BLOCKS + TQ_BLOCKS + TP_BLOCKS)

__global__ __launch_bounds__(256)
void prep_kernel(const float* __restrict__ x, __half* __restrict__ xh,
                 const float* __restrict__ wq, __half* __restrict__ wqT,
                 const float* __restrict__ wp, __half* __restrict__ wpT) {
    __shared__ float tt[32][33];
    const int bid = blockIdx.x, tid = threadIdx.x;
    if (bid < X2H_BLOCKS) {
        size_t i = ((size_t)bid * 256 + tid) * 8;
        float4 a = *(const float4*)(x + i);
        float4 b = *(const float4*)(x + i + 4);
        *(uint4*)(xh + i) = make_uint4(pack_h2(a.x, a.y), pack_h2(a.z, a.w),
                                       pack_h2(b.x, b.y), pack_h2(b.z, b.w));
        return;
    }
    const float* in;  __half* out;  int R, Cc, bx, by;
    if (bid < X2H_BLOCKS + TQ_BLOCKS) {
        int t = bid - X2H_BLOCKS;
        in = wq; out = wqT; R = CDIM; Cc = QKV_N;
        bx = (t % 27) * 32; by = (t / 27) * 32;
    } else {
        int t = bid - X2H_BLOCKS - TQ_BLOCKS;
        in = wp; out = wpT; R = CDIM; Cc = CDIM;
        bx = (t % 9) * 32; by = (t / 9) * 32;
    }
    int xx = tid & 31, yy = tid >> 5;
#pragma unroll
    for (int j = 0; j < 4; j++)
        tt[yy + 8 * j][xx] = in[(size_t)(by + yy + 8 * j) * Cc + bx + xx];
    __syncthreads();
#pragma unroll
    for (int j = 0; j < 4; j++)
        out[(size_t)(bx + yy + 8 * j) * R + by + xx] = __float2half(tt[xx][yy + 8 * j]);
}

// ==================== GEMM1: cp.async 4-stage (1 barrier/chunk) + ldmatrix ====================
// qkv[token][chan] = xh[token][288] @ wqkvT[chan][288]^T
// BM=96 chans, BN=128 tokens, BK=32, 9 chunks. Stage 17920 B x 4 = 71680.
#define G1_SMEM 71680

__global__ __launch_bounds__(256)
void gemm1_kernel(const __half* __restrict__ Aw, const __half* __restrict__ Bx,
                  __half* __restrict__ Ch, __half* __restrict__ vc) {
    extern __shared__ float smf[];
    const uint32_t smb = smem_u32_of(smf);
    const int tid = threadIdx.x, lane = tid & 31, warp = tid >> 5;
    const int qr = lane >> 2, qc = lane & 3;
    const int wm = warp & 1, wn = warp >> 1;
    const int n0 = blockIdx.x * 128;
    const int m0 = blockIdx.y * 96;
    const int bb = n0 >> 15;
    const int l0 = n0 & (L_TOT - 1);

    const int g8 = lane >> 3, lr = lane & 7;
    const int rowA = lr + (g8 & 1) * 8, colA = (g8 >> 1) * 16;
    const int rowB = lr + (g8 >> 1) * 8, colB = (g8 & 1) * 16;
    uint32_t aoff[3], boff[2];
#pragma unroll
    for (int mt = 0; mt < 3; mt++)
        aoff[mt] = (wm * 48 + mt * 16 + rowA) * 80 + colA;
#pragma unroll
    for (int p = 0; p < 2; p++)
        boff[p] = 7680 + (wn * 32 + p * 16 + rowB) * 80 + colB;

    float acc[3][4][4];
#pragma unroll
    for (int mt = 0; mt < 3; mt++)
#pragma unroll
        for (int nt = 0; nt < 4; nt++)
#pragma unroll
            for (int r = 0; r < 4; r++) acc[mt][nt][r] = 0.0f;

#define ISSUE(S, K0) do { \
    uint32_t base = smb + (S) * 17920; \
    { int r = tid >> 2, c = tid & 3; \
      CP16(base + r * 80 + c * 16, Aw + (size_t)(m0 + r) * CDIM + (K0) + c * 8); } \
    if (tid < 128) { int idx = tid + 256; \
      int r = idx >> 2, c = idx & 3; \
      CP16(base + r * 80 + c * 16, Aw + (size_t)(m0 + r) * CDIM + (K0) + c * 8); } \
    _Pragma("unroll") for (int i = 0; i < 2; i++) { \
      int idx = tid + i * 256; \
      int r = idx >> 2, c = idx & 3; \
      CP16(base + 7680 + r * 80 + c * 16, Bx + (size_t)(n0 + r) * CDIM + (K0) + c * 8); } \
    CP_COMMIT(); \
} while (0)

    ISSUE(0, 0);
    ISSUE(1, 32);
    ISSUE(2, 64);

#pragma unroll 1
    for (int ch = 0; ch < 9; ch++) {
        if (ch <= 6) { CP_WAIT2(); } else if (ch == 7) { CP_WAIT1(); } else { CP_WAIT0(); }
        __syncthreads();                          // single barrier per chunk
        if (ch < 6) ISSUE((ch + 3) & 3, (ch + 3) * 32);

        const uint32_t sb = smb + (ch & 3) * 17920;
#pragma unroll
        for (int s = 0; s < 2; s++) {
            const int so = s * 32;
            uint32_t af[3][4], bf[2][4];
#pragma unroll
            for (int mt = 0; mt < 3; mt++)
                ldsm4(af[mt][0], af[mt][1], af[mt][2], af[mt][3], sb + aoff[mt] + so);
#pragma unroll
            for (int p = 0; p < 2; p++)
                ldsm4(bf[p][0], bf[p][1], bf[p][2], bf[p][3], sb + boff[p] + so);
#pragma unroll
            for (int mt = 0; mt < 3; mt++)
#pragma unroll
                for (int nt = 0; nt < 4; nt++)
                    mma16(acc[mt][nt], af[mt][0], af[mt][1], af[mt][2], af[mt][3],
                          bf[nt >> 1][(nt & 1) * 2], bf[nt >> 1][(nt & 1) * 2 + 1]);
        }
    }
#undef ISSUE
    __syncthreads();

    // ==================== epilogue ====================
    float* stg = smf;                  // [96][133]: [chan][token]
#pragma unroll
    for (int mt = 0; mt < 3; mt++) {
        int r0 = wm * 48 + mt * 16 + qr;
#pragma unroll
        for (int nt = 0; nt < 4; nt++) {
            int c0 = wn * 32 + nt * 8 + 2 * qc;
            stg[r0 * 133 + c0]           = acc[mt][nt][0];
            stg[r0 * 133 + c0 + 1]       = acc[mt][nt][1];
            stg[(r0 + 8) * 133 + c0]     = acc[mt][nt][2];
            stg[(r0 + 8) * 133 + c0 + 1] = acc[mt][nt][3];
        }
    }
    __syncthreads();

#pragma unroll
    for (int i = 0; i < 6; i++) {
        int idx = tid + i * 256;
        int t = idx / 12, q = idx - t * 12;
        uint32_t u0 = pack_h2(stg[(q * 8 + 0) * 133 + t], stg[(q * 8 + 1) * 133 + t]);
        uint32_t u1 = pack_h2(stg[(q * 8 + 2) * 133 + t], stg[(q * 8 + 3) * 133 + t]);
        uint32_t u2 = pack_h2(stg[(q * 8 + 4) * 133 + t], stg[(q * 8 + 5) * 133 + t]);
        uint32_t u3 = pack_h2(stg[(q * 8 + 6) * 133 + t], stg[(q * 8 + 7) * 133 + t]);
        *(uint4*)(Ch + (size_t)(n0 + t) * QKV_N + m0 + q * 8) = make_uint4(u0, u1, u2, u3);
    }
    if (m0 >= 2 * CDIM) {
#pragma unroll
        for (int i = 0; i < 6; i++) {
            int idx = tid + i * 256;
            int m = idx >> 4, c8 = (idx & 15) * 8;
            uint32_t u0 = pack_h2(stg[m * 133 + c8 + 0], stg[m * 133 + c8 + 1]);
            uint32_t u1 = pack_h2(stg[m * 133 + c8 + 2], stg[m * 133 + c8 + 3]);
            uint32_t u2 = pack_h2(stg[m * 133 + c8 + 4], stg[m * 133 + c8 + 5]);
            uint32_t u3 = pack_h2(stg[m * 133 + c8 + 6], stg[m * 133 + c8 + 7]);
            *(uint4*)(vc + ((size_t)bb * CDIM + (m0 - 2 * CDIM) + m) * L_TOT + l0 + c8)
                = make_uint4(u0, u1, u2, u3);
        }
    }
}

// ==================== GEMM2: out = (y + lcm^T) @ w_proj + bias ====================
#define G2_SMEM 52736

__global__ __launch_bounds__(256)
void gemm2_kernel(const __half* __restrict__ Aw, const __half* __restrict__ By,
                  const __half* __restrict__ lcm, float* __restrict__ Cf,
                  const float* __restrict__ bias) {
    extern __shared__ float smf[];
    uint32_t* smh2 = (uint32_t*)smf;
    float* LS = smf + 8960;                    // [128][33]
    const uint32_t smb = smem_u32_of(smf);
    const int tid = threadIdx.x, lane = tid & 31, warp = tid >> 5;
    const int qr = lane >> 2, qc = lane & 3;
    const int wm = warp & 1, wn = warp >> 1;
    const int n0 = blockIdx.x * 128;
    const int m0 = blockIdx.y * 96;
    const int bb = n0 >> 15;
    const int l0 = n0 & (L_TOT - 1);

    const int g8 = lane >> 3, lr = lane & 7;
    const int rowA = lr + (g8 & 1) * 8, colA = (g8 >> 1) * 16;
    const int rowB = lr + (g8 >> 1) * 8, colB = (g8 & 1) * 16;
    uint32_t aoff[3], boff[2];
#pragma unroll
    for (int mt = 0; mt < 3; mt++)
        aoff[mt] = (wm * 48 + mt * 16 + rowA) * 80 + colA;
#pragma unroll
    for (int p = 0; p < 2; p++)
        boff[p] = 15360 + (wn * 32 + p * 16 + rowB) * 80 + colB;

    float acc[3][4][4];
#pragma unroll
    for (int mt = 0; mt < 3; mt++)
#pragma unroll
        for (int nt = 0; nt < 4; nt++)
#pragma unroll
            for (int r = 0; r < 4; r++) acc[mt][nt][r] = 0.0f;

    uint2 rA[3];
    uint4 rBy[2], rLc[2];

#define G_LOADS(K0) do { \
    _Pragma("unroll") for (int i = 0; i < 3; i++) { \
        int idx = tid + i * 256; int m = idx >> 3, q = idx & 7; \
        rA[i] = *(const uint2*)(Aw + (size_t)(m0 + m) * CDIM + (K0) + q * 4); } \
    _Pragma("unroll") for (int i = 0; i < 2; i++) { \
        int idx = tid + i * 256; int t = idx >> 2, k8 = (idx & 3) * 8; \
        rBy[i] = *(const uint4*)(By + (size_t)(n0 + t) * CDIM + (K0) + k8); } \
    _Pragma("unroll") for (int i = 0; i < 2; i++) { \
        int idx = tid + i * 256; int cc = idx >> 4, l8 = (idx & 15) * 8; \
        rLc[i] = *(const uint4*)(lcm + ((size_t)bb * CDIM + (K0) + cc) * L_TOT + l0 + l8); } \
} while (0)

#define S_STORES(BUF) do { \
    uint32_t* As_ = smh2 + ((BUF) ? 1920 : 0); \
    uint32_t* Bs_ = smh2 + ((BUF) ? 6400 : 3840); \
    _Pragma("unroll") for (int i = 0; i < 2; i++) { \
        int idx = tid + i * 256; int cc = idx >> 4, l8 = (idx & 15) * 8; \
        __half2* hh = (__half2*)&rLc[i]; \
        _Pragma("unroll") for (int e = 0; e < 4; e++) { \
            float2 f = __half22float2(hh[e]); \
            LS[(l8 + 2 * e) * 33 + cc]     = f.x; \
            LS[(l8 + 2 * e + 1) * 33 + cc] = f.y; } } \
    __syncthreads(); \
    _Pragma("unroll") for (int i = 0; i < 3; i++) { \
        int idx = tid + i * 256; int m = idx >> 3, q = idx & 7; \
        *(uint2*)(As_ + m * 20 + q * 2) = rA[i]; } \
    _Pragma("unroll") for (int i = 0; i < 2; i++) { \
        int idx = tid + i * 256; int t = idx >> 2, k8 = (idx & 3) * 8; \
        __half2* hh = (__half2*)&rBy[i]; \
        uint32_t u0, u1, u2, u3; \
        { float2 f = __half22float2(hh[0]); \
          u0 = pack_h2(f.x + LS[t * 33 + k8 + 0], f.y + LS[t * 33 + k8 + 1]); } \
        { float2 f = __half22float2(hh[1]); \
          u1 = pack_h2(f.x + LS[t * 33 + k8 + 2], f.y + LS[t * 33 + k8 + 3]); } \
        { float2 f = __half22float2(hh[2]); \
          u2 = pack_h2(f.x + LS[t * 33 + k8 + 4], f.y + LS[t * 33 + k8 + 5]); } \
        { float2 f = __half22float2(hh[3]); \
          u3 = pack_h2(f.x + LS[t * 33 + k8 + 6], f.y + LS[t * 33 + k8 + 7]); } \
        *(uint4*)(Bs_ + t * 20 + (k8 >> 1)) = make_uint4(u0, u1, u2, u3); } \
} while (0)

    G_LOADS(0);
    S_STORES(0);
    __syncthreads();

#pragma unroll 1
    for (int ch = 0; ch < 9; ch++) {
        const int cur = ch & 1;
        if (ch < 8) G_LOADS((ch + 1) * 32);

        const uint32_t abase = smb + (cur ? 7680 : 0);
        const uint32_t bbase = smb + (cur ? 10240 : 0);
#pragma unroll
        for (int s = 0; s < 2; s++) {
            const int so = s * 32;
            uint32_t af[3][4], bf[2][4];
#pragma unroll
            for (int mt = 0; mt < 3; mt++)
                ldsm4(af[mt][0], af[mt][1], af[mt][2], af[mt][3], abase + aoff[mt] + so);
#pragma unroll
            for (int p = 0; p < 2; p++)
                ldsm4(bf[p][0], bf[p][1], bf[p][2], bf[p][3], bbase + boff[p] + so);
#pragma unroll
            for (int mt = 0; mt < 3; mt++)
#pragma unroll
                for (int nt = 0; nt < 4; nt++)
                    mma16(acc[mt][nt], af[mt][0], af[mt][1], af[mt][2], af[mt][3],
                          bf[nt >> 1][(nt & 1) * 2], bf[nt >> 1][(nt & 1) * 2 + 1]);
        }

        if (ch < 8) {
            S_STORES(cur ^ 1);
            __syncthreads();
        }
    }
#undef G_LOADS
#undef S_STORES

    __syncthreads();
    float* stg = smf;                  // [96][133]
#pragma unroll
    for (int mt = 0; mt < 3; mt++) {
        int r0 = wm * 48 + mt * 16 + qr;
#pragma unroll
        for (int nt = 0; nt < 4; nt++) {
            int c0 = wn * 32 + nt * 8 + 2 * qc;
            stg[r0 * 133 + c0]           = acc[mt][nt][0];
            stg[r0 * 133 + c0 + 1]       = acc[mt][nt][1];
            stg[(r0 + 8) * 133 + c0]     = acc[mt][nt][2];
            stg[(r0 + 8) * 133 + c0 + 1] = acc[mt][nt][3];
        }
    }
    __syncthreads();

#pragma unroll
    for (int i = 0; i < 12; i++) {
        int idx = tid + i * 256;
        int t = idx / 24, q = idx - t * 24;
        float4 o;
        o.x = stg[(q * 4 + 0) * 133 + t] + bias[m0 + q * 4 + 0];
        o.y = stg[(q * 4 + 1) * 133 + t] + bias[m0 + q * 4 + 1];
        o.z = stg[(q * 4 + 2) * 133 + t] + bias[m0 + q * 4 + 2];
        o.w = stg[(q * 4 + 3) * 133 + t] + bias[m0 + q * 4 + 3];
        *(float4*)(Cf + (size_t)(n0 + t) * CDIM + m0 + q * 4) = o;
    }
}

// ==================== RPE-bias MLP ====================
__device__ __forceinline__ void ln_relu6(float* h, const float* g, const float* b) {
    float m = 0.f;
#pragma unroll
    for (int j = 0; j < 6; j++) m += h[j];
    m *= (1.0f / 6.0f);
    float v = 0.f;
#pragma unroll
    for (int j = 0; j < 6; j++) { float d = h[j] - m; v += d * d; }
    v *= (1.0f / 6.0f);
    float inv = rsqrtf(v + 1e-5f);
#pragma unroll
    for (int j = 0; j < 6; j++) {
        float t = (h[j] - m) * inv * g[j] + b[j];
        h[j] = t > 0.f ? t : 0.f;
    }
}

__global__ void biasmlp_kernel(const float* __restrict__ rpe,
                               const float* __restrict__ pw, const float* __restrict__ pb,
                               const float* __restrict__ g1, const float* __restrict__ be1,
                               const float* __restrict__ w1, const float* __restrict__ b1,
                               const float* __restrict__ g2, const float* __restrict__ be2,
                               const float* __restrict__ w2, const float* __restrict__ b2,
                               const float* __restrict__ g3, const float* __restrict__ be3,
                               const float* __restrict__ w3, const float* __restrict__ b3,
                               const int* __restrict__ relidx,
                               float* __restrict__ biasb) {
    int bi = blockIdx.x;
    int t = threadIdx.x;
    __shared__ float p[TBIAS][HB];

    if (t < TBIAS) {
        float h[6], tmp[6];
        const float* r = rpe + (bi * TBIAS + t) * 3;
        float r0 = r[0], r1 = r[1], r2 = r[2];
#pragma unroll
        for (int j = 0; j < 6; j++)
            h[j] = pb[bi * 6 + j]
                 + r0 * pw[(bi * 3 + 0) * 6 + j]
                 + r1 * pw[(bi * 3 + 1) * 6 + j]
                 + r2 * pw[(bi * 3 + 2) * 6 + j];
        ln_relu6(h, g1 + bi * 6, be1 + bi * 6);
#pragma unroll
        for (int j = 0; j < 6; j++) {
            float s = b1[bi * 6 + j];
#pragma unroll
            for (int i = 0; i < 6; i++) s += h[i] * w1[(bi * 6 + i) * 6 + j];
            tmp[j] = s;
        }
#pragma unroll
        for (int j = 0; j < 6; j++) h[j] = tmp[j];
        ln_relu6(h, g2 + bi * 6, be2 + bi * 6);
#pragma unroll
        for (int j = 0; j < 6; j++) {
            float s = b2[bi * 6 + j];
#pragma unroll
            for (int i = 0; i < 6; i++) s += h[i] * w2[(bi * 6 + i) * 6 + j];
            tmp[j] = s;
        }
#pragma unroll
        for (int j = 0; j < 6; j++) h[j] = tmp[j];
        ln_relu6(h, g3 + bi * 6, be3 + bi * 6);
#pragma unroll
        for (int j = 0; j < HB; j++) {
            float s = b3[bi * HB + j];
#pragma unroll
            for (int i = 0; i < 6; i++) s += h[i] * w3[(bi * 6 + i) * HB + j];
            p[t][j] = s;
        }
    }
    __syncthreads();

    for (int i = t; i < HB * NWIN * NWIN; i += blockDim.x) {
        int hb = i >> 8;
        int nm = i & 255;
        biasb[bi * (HB * NWIN * NWIN) + i] = p[relidx[bi * 256 + nm]][hb];
    }
}

// ==================== fused attention + depthwise conv ====================
// blocks [0, 6144): attention, 2 windows per 128-thread block
// blocks [6144, 6720): conv, one (b,c) per 128-thread block, 8 h-rows/thread
#define ATTN_BLOCKS 6144
#define FUSE_BLOCKS (ATTN_BLOCKS + BATCH * CDIM)

__global__ __launch_bounds__(128)
void attn_conv_kernel(const __half* __restrict__ qkv, const float* __restrict__ biasb,
                      __half* __restrict__ y, const __half* __restrict__ vc,
                      const float* __restrict__ cw, const float* __restrict__ cb,
                      __half* __restrict__ lcm) {
    __shared__ float shm[6400];
    const int tid = threadIdx.x;

    if (blockIdx.x < ATTN_BLOCKS) {
        // -------- attention --------
        const int bi = blockIdx.x / 2048;
        const int rem = blockIdx.x - bi * 2048;
        const int b = rem >> 10;
        const int pair = rem & 1023;
        const int Dsp = c_Dsp[bi], Hsp = c_Hsp[bi], Wsp = c_Wsp[bi];
        const int nH = RESV / Hsp, nW = RESV / Wsp;
        const int g  = tid >> 6;
        const int tl = tid & 63;
        int widx = pair * 2 + g;
        int wblk = widx % nW; int tmp = widx / nW;
        int hblk = tmp % nH;  int dblk = tmp / nH;

        const int hb = tl >> 4;
        const int n  = tl & 15;
        const int HW = Hsp * Wsp;
        int dd = n / HW; int r = n - dd * HW;
        int hh = r / Wsp; int ww = r - hh * Wsp;
        int l = ((dblk * Dsp + dd) * RESV + hblk * Hsp + hh) * RESV + wblk * Wsp + ww;

        size_t rowbase = ((size_t)b * L_TOT + l) * QKV_N + bi * 96 + hb * HDIM;

        float* sk = shm;            // [2][64][25]
        float* sv = shm + 3200;
        float* skr = sk + g * 1600;
        float* svr = sv + g * 1600;
        float q[HDIM];
        const float scale = 0.2041241452319315f;

        const uint4* qp = (const uint4*)(qkv + rowbase);
        const uint4* kp = (const uint4*)(qkv + rowbase + CDIM);
        const uint4* vp = (const uint4*)(qkv + rowbase + 2 * CDIM);
#pragma unroll
        for (int j = 0; j < 3; j++) {
            uint4 uq = qp[j], uk = kp[j], uv = vp[j];
            __half2* hq = (__half2*)&uq;
            __half2* hk = (__half2*)&uk;
            __half2* hv = (__half2*)&uv;
#pragma unroll
            for (int e = 0; e < 4; e++) {
                float2 fq = __half22float2(hq[e]);
                q[8 * j + 2 * e]     = fq.x * scale;
                q[8 * j + 2 * e + 1] = fq.y * scale;
                float2 fk = __half22float2(hk[e]);
                skr[tl * 25 + 8 * j + 2 * e]     = fk.x;
                skr[tl * 25 + 8 * j + 2 * e + 1] = fk.y;
                float2 fv = __half22float2(hv[e]);
                svr[tl * 25 + 8 * j + 2 * e]     = fv.x;
                svr[tl * 25 + 8 * j + 2 * e + 1] = fv.y;
            }
        }
        __syncthreads();

        const float* brow = biasb + (((size_t)bi * HB + hb) * NWIN + n) * NWIN;
        float lg[NWIN];
        float mx = -1e30f;
#pragma unroll
        for (int m = 0; m < NWIN; m++) {
            float s = brow[m];
            const float* kr = skr + (hb * 16 + m) * 25;
#pragma unroll
            for (int e = 0; e < HDIM; e++) s = fmaf(q[e], kr[e], s);
            lg[m] = s;
            mx = fmaxf(mx, s);
        }
        float sum = 0.f;
#pragma unroll
        for (int m = 0; m < NWIN; m++) { lg[m] = __expf(lg[m] - mx); sum += lg[m]; }
        float inv = 1.0f / sum;

        float o[HDIM];
#pragma unroll
        for (int e = 0; e < HDIM; e++) o[e] = 0.f;
#pragma unroll
        for (int m = 0; m < NWIN; m++) {
            float w = lg[m] * inv;
            const float* vr = svr + (hb * 16 + m) * 25;
#pragma unroll
            for (int e = 0; e < HDIM; e++) o[e] = fmaf(w, vr[e], o[e]);
        }

        __half* yp = y + ((size_t)b * L_TOT + l) * CDIM + bi * 96 + hb * HDIM;
#pragma unroll
        for (int j = 0; j < 3; j++) {
            uint32_t u0 = pack_h2(o[8 * j + 0], o[8 * j + 1]);
            uint32_t u1 = pack_h2(o[8 * j + 2], o[8 * j + 3]);
            uint32_t u2 = pack_h2(o[8 * j + 4], o[8 * j + 5]);
            uint32_t u3 = pack_h2(o[8 * j + 6], o[8 * j + 7]);
            *(uint4*)(yp + 8 * j) = make_uint4(u0, u1, u2, u3);
        }
        return;
    }

    // -------- depthwise 3x3x3 conv --------
    const int bc = blockIdx.x - ATTN_BLOCKS;     // b*288 + c
    const int c = bc % CDIM;
    const __half* src = vc + (size_t)bc * L_TOT;
    __half* dst = lcm + (size_t)bc * L_TOT;

    float wt[27];
#pragma unroll
    for (int j = 0; j < 27; j++) wt[j] = cw[c * 27 + j];
    const float bias = cb[c];

    float* sp = shm;                             // [3][34][36] = 3672 floats
    const int w = tid & 31;
    const int h0 = (tid >> 5) * 8;               // 0,8,16,24

    for (int i = tid; i < 3 * 34 * 36; i += 128) sp[i] = 0.f;
    __syncthreads();
#pragma unroll
    for (int jh = 0; jh < 8; jh++) {
        int h = h0 + jh;
        sp[(1 + h) * 36 + 1 + w]        = __half2float(src[h * 32 + w]);
        sp[1224 + (1 + h) * 36 + 1 + w] = __half2float(src[1024 + h * 32 + w]);
    }
    __syncthreads();

#pragma unroll 1
    for (int d = 0; d < 32; d++) {
        const int bm = (d + 2) % 3;
        const int b0 = d % 3;
        const int bp = (d + 1) % 3;
        float acc[8];
#pragma unroll
        for (int jh = 0; jh < 8; jh++) acc[jh] = bias;

#define TAPS(BUF, KD) { \
        const float* P = sp + (BUF) * 1224; \
        _Pragma("unroll") \
        for (int rr = 0; rr < 10; rr++) { \
            float va = P[(h0 + rr) * 36 + w], vb = P[(h0 + rr) * 36 + w + 1], \
                  vcx = P[(h0 + rr) * 36 + w + 2]; \
            _Pragma("unroll") \
            for (int jh = 0; jh < 8; jh++) { \
                int kh = rr - jh; \
                if (kh >= 0 && kh < 3) { \
                    acc[jh] = fmaf(wt[(KD)*9 + kh*3 + 0], va, \
                              fmaf(wt[(KD)*9 + kh*3 + 1], vb, \
                              fmaf(wt[(KD)*9 + kh*3 + 2], vcx, acc[jh]))); \
                } \
            } \
        } }

        if (d > 0)  TAPS(bm, 0);
        TAPS(b0, 1);
        if (d < 31) TAPS(bp, 2);
#undef TAPS

#pragma unroll
        for (int jh = 0; jh < 8; jh++)
            dst[d * 1024 + (h0 + jh) * 32 + w] = __float2half(acc[jh]);

        __syncthreads();
        if (d + 2 < 32) {
            const __half* s2 = src + (d + 2) * 1024;
            float* spn = sp + ((d + 2) % 3) * 1224;
#pragma unroll
            for (int jh = 0; jh < 8; jh++) {
                int h = h0 + jh;
                spn[(1 + h) * 36 + 1 + w] = __half2float(s2[h * 32 + w]);
            }
        }
        __syncthreads();
    }
}

// ==================== launch ====================
extern "C" void kernel_launch(void* const* d_in, const int* in_sizes, int n_in,
                              void* d_out, int out_size) {
    const float* x      = (const float*)d_in[0];
    const float* w_qkv  = (const float*)d_in[4];
    const float* w_proj = (const float*)d_in[5];
    const float* b_proj = (const float*)d_in[6];
    const float* conv_w = (const float*)d_in[7];
    const float* conv_b = (const float*)d_in[8];
    const float* pos_w  = (const float*)d_in[9];
    const float* pos_b  = (const float*)d_in[10];
    const float* ln1g   = (const float*)d_in[11];
    const float* ln1b   = (const float*)d_in[12];
    const float* lin1w  = (const float*)d_in[13];
    const float* lin1b  = (const float*)d_in[14];
    const float* ln2g   = (const float*)d_in[15];
    const float* ln2b   = (const float*)d_in[16];
    const float* lin2w  = (const float*)d_in[17];
    const float* lin2b  = (const float*)d_in[18];
    const float* ln3g   = (const float*)d_in[19];
    const float* ln3b   = (const float*)d_in[20];
    const float* lin3w  = (const float*)d_in[21];
    const float* lin3b  = (const float*)d_in[22];
    const float* rpe    = (const float*)d_in[23];
    const int*   relidx = (const int*)d_in[24];
    float* out = (float*)d_out;

    __half *xhp, *qkvp, *yp, *vcp, *lcmp, *wqkvT, *wprojT;
    float *bp;
    cudaGetSymbolAddress((void**)&xhp,    g_xh);
    cudaGetSymbolAddress((void**)&qkvp,   g_qkv);
    cudaGetSymbolAddress((void**)&yp,     g_y);
    cudaGetSymbolAddress((void**)&bp,     g_bias);
    cudaGetSymbolAddress((void**)&vcp,    g_vc);
    cudaGetSymbolAddress((void**)&lcmp,   g_lcm);
    cudaGetSymbolAddress((void**)&wqkvT,  g_wqkvT);
    cudaGetSymbolAddress((void**)&wprojT, g_wprojT);

    cudaFuncSetAttribute(gemm1_kernel, cudaFuncAttributeMaxDynamicSharedMemorySize, G1_SMEM);
    cudaFuncSetAttribute(gemm2_kernel, cudaFuncAttributeMaxDynamicSharedMemorySize, G2_SMEM);

    // 0) fused prep: x->half + both weight transposes
    prep_kernel<<<PREP_BLOCKS, 256>>>(x, xhp, w_qkv, wqkvT, w_proj, wprojT);

    // 1) qkv = xh @ w_qkv  (also writes v channel-major into vc)
    gemm1_kernel<<<dim3(NROWS / 128, QKV_N / 96), 256, G1_SMEM>>>(wqkvT, xhp, qkvp, vcp);

    // 2) RPE bias tables
    biasmlp_kernel<<<3, 64>>>(rpe, pos_w, pos_b,
                              ln1g, ln1b, lin1w, lin1b,
                              ln2g, ln2b, lin2w, lin2b,
                              ln3g, ln3b, lin3w, lin3b,
                              relidx, bp);

    // 3) fused attention + depthwise conv
    attn_conv_kernel<<<FUSE_BLOCKS, 128>>>(qkvp, bp, yp, vcp, conv_w, conv_b, lcmp);

    // 4) out = (y + lcm^T) @ w_proj + b_proj
    gemm2_kernel<<<dim3(NROWS / 128, CDIM / 96), 256, G2_SMEM>>>(wprojT, yp, lcmp, out, b_proj);
}

// round 10
// speedup vs baseline: 4.4935x; 1.0819x over previous
#include <cuda_runtime.h>
#include <cuda_fp16.h>
#include <math.h>
#include <stdint.h>

// ---------------- problem constants ----------------
#define RESV   32
#define L_TOT  (RESV*RESV*RESV)      // 32768
#define BATCH  2
#define CDIM   288
#define QKV_N  (3*CDIM)              // 864
#define NROWS  (BATCH*L_TOT)         // 65536
#define HB     4
#define HDIM   24
#define NWIN   16
#define TBIAS  63

// scratch (no cudaMalloc allowed) — fp16 intermediates
__device__ __half g_xh  [(size_t)NROWS * CDIM];
__device__ __half g_qkv [(size_t)NROWS * QKV_N];
__device__ __half g_y   [(size_t)NROWS * CDIM];
__device__ __half g_vc  [(size_t)BATCH * CDIM * L_TOT];  // v, channel-major
__device__ __half g_lcm [(size_t)BATCH * CDIM * L_TOT];  // conv out, channel-major
__device__ __half g_wqkvT[(size_t)QKV_N * CDIM];
__device__ __half g_wprojT[(size_t)CDIM * CDIM];
__device__ float  g_bias[3 * HB * NWIN * NWIN];

__constant__ int c_Dsp[3] = {2, 2, 2};
__constant__ int c_Hsp[3] = {2, 2, 4};
__constant__ int c_Wsp[3] = {4, 4, 2};

// ==================== helpers ====================
__device__ __forceinline__ uint32_t smem_u32_of(const void* p) {
    uint32_t a;
    asm("{ .reg .u64 t; cvta.to.shared.u64 t, %1; cvt.u32.u64 %0, t; }" : "=r"(a) : "l"(p));
    return a;
}

__device__ __forceinline__ void mma16(float* d,
                                      uint32_t a0, uint32_t a1, uint32_t a2, uint32_t a3,
                                      uint32_t b0, uint32_t b1) {
    asm volatile("mma.sync.aligned.m16n8k16.row.col.f32.f16.f16.f32 "
                 "{%0,%1,%2,%3}, {%4,%5,%6,%7}, {%8,%9}, {%0,%1,%2,%3};"
                 : "+f"(d[0]), "+f"(d[1]), "+f"(d[2]), "+f"(d[3])
                 : "r"(a0), "r"(a1), "r"(a2), "r"(a3), "r"(b0), "r"(b1));
}

__device__ __forceinline__ void ldsm4(uint32_t& r0, uint32_t& r1, uint32_t& r2, uint32_t& r3,
                                      uint32_t addr) {
    asm volatile("ldmatrix.sync.aligned.m8n8.x4.shared.b16 {%0,%1,%2,%3}, [%4];"
                 : "=r"(r0), "=r"(r1), "=r"(r2), "=r"(r3) : "r"(addr));
}

__device__ __forceinline__ uint32_t pack_h2(float x, float y) {
    __half2 h = __floats2half2_rn(x, y);
    return *(uint32_t*)&h;
}

#define CP16(dst, src) \
    asm volatile("cp.async.cg.shared.global [%0], [%1], 16;" :: "r"(dst), "l"(src))
#define CP_COMMIT() asm volatile("cp.async.commit_group;")
#define CP_WAIT2()  asm volatile("cp.async.wait_group 2;")
#define CP_WAIT1()  asm volatile("cp.async.wait_group 1;")
#define CP_WAIT0()  asm volatile("cp.async.wait_group 0;")

// ==================== RPE-bias MLP piece (runs inside prep) ====================
__device__ __forceinline__ void ln_relu6(float* h, const float* g, const float* b) {
    float m = 0.f;
#pragma unroll
    for (int j = 0; j < 6; j++) m += h[j];
    m *= (1.0f / 6.0f);
    float v = 0.f;
#pragma unroll
    for (int j = 0; j < 6; j++) { float d = h[j] - m; v += d * d; }
    v *= (1.0f / 6.0f);
    float inv = rsqrtf(v + 1e-5f);
#pragma unroll
    for (int j = 0; j < 6; j++) {
        float t = (h[j] - m) * inv * g[j] + b[j];
        h[j] = t > 0.f ? t : 0.f;
    }
}

// ==================== fused prep: biasmlp + x->half + weight transposes ====================
#define BM_BLOCKS  3
#define X2H_BLOCKS 9216                 // NROWS*CDIM/2048
#define TQ_BLOCKS  (27 * 9)
#define TP_BLOCKS  (9 * 9)
#define PREP_BLOCKS (BM_BLOCKS + X2H_BLOCKS + TQ_BLOCKS + TP_BLOCKS)

__global__ __launch_bounds__(256)
void prep_kernel(const float* __restrict__ x, __half* __restrict__ xh,
                 const float* __restrict__ wq, __half* __restrict__ wqT,
                 const float* __restrict__ wp, __half* __restrict__ wpT,
                 const float* __restrict__ rpe,
                 const float* __restrict__ pw, const float* __restrict__ pb,
                 const float* __restrict__ g1, const float* __restrict__ be1,
                 const float* __restrict__ w1, const float* __restrict__ b1,
                 const float* __restrict__ g2, const float* __restrict__ be2,
                 const float* __restrict__ w2, const float* __restrict__ b2,
                 const float* __restrict__ g3, const float* __restrict__ be3,
                 const float* __restrict__ w3, const float* __restrict__ b3,
                 const int* __restrict__ relidx, float* __restrict__ biasb) {
    __shared__ float tt[32][33];
    __shared__ float p[TBIAS][HB];
    const int bid = blockIdx.x, tid = threadIdx.x;

    if (bid < BM_BLOCKS) {
        // -------- RPE-bias MLP --------
        const int bi = bid;
        if (tid < TBIAS) {
            float h[6], tmp[6];
            const float* r = rpe + (bi * TBIAS + tid) * 3;
            float r0 = r[0], r1 = r[1], r2 = r[2];
#pragma unroll
            for (int j = 0; j < 6; j++)
                h[j] = pb[bi * 6 + j]
                     + r0 * pw[(bi * 3 + 0) * 6 + j]
                     + r1 * pw[(bi * 3 + 1) * 6 + j]
                     + r2 * pw[(bi * 3 + 2) * 6 + j];
            ln_relu6(h, g1 + bi * 6, be1 + bi * 6);
#pragma unroll
            for (int j = 0; j < 6; j++) {
                float s = b1[bi * 6 + j];
#pragma unroll
                for (int i = 0; i < 6; i++) s += h[i] * w1[(bi * 6 + i) * 6 + j];
                tmp[j] = s;
            }
#pragma unroll
            for (int j = 0; j < 6; j++) h[j] = tmp[j];
            ln_relu6(h, g2 + bi * 6, be2 + bi * 6);
#pragma unroll
            for (int j = 0; j < 6; j++) {
                float s = b2[bi * 6 + j];
#pragma unroll
                for (int i = 0; i < 6; i++) s += h[i] * w2[(bi * 6 + i) * 6 + j];
                tmp[j] = s;
            }
#pragma unroll
            for (int j = 0; j < 6; j++) h[j] = tmp[j];
            ln_relu6(h, g3 + bi * 6, be3 + bi * 6);
#pragma unroll
            for (int j = 0; j < HB; j++) {
                float s = b3[bi * HB + j];
#pragma unroll
                for (int i = 0; i < 6; i++) s += h[i] * w3[(bi * 6 + i) * HB + j];
                p[tid][j] = s;
            }
        }
        __syncthreads();
        for (int i = tid; i < HB * NWIN * NWIN; i += blockDim.x) {
            int hb = i >> 8;
            int nm = i & 255;
            biasb[bi * (HB * NWIN * NWIN) + i] = p[relidx[bi * 256 + nm]][hb];
        }
        return;
    }

    if (bid < BM_BLOCKS + X2H_BLOCKS) {
        size_t i = ((size_t)(bid - BM_BLOCKS) * 256 + tid) * 8;
        float4 a = *(const float4*)(x + i);
        float4 b = *(const float4*)(x + i + 4);
        *(uint4*)(xh + i) = make_uint4(pack_h2(a.x, a.y), pack_h2(a.z, a.w),
                                       pack_h2(b.x, b.y), pack_h2(b.z, b.w));
        return;
    }
    const float* in;  __half* out;  int R, Cc, bx, by;
    if (bid < BM_BLOCKS + X2H_BLOCKS + TQ_BLOCKS) {
        int t = bid - BM_BLOCKS - X2H_BLOCKS;
        in = wq; out = wqT; R = CDIM; Cc = QKV_N;
        bx = (t % 27) * 32; by = (t / 27) * 32;
    } else {
        int t = bid - BM_BLOCKS - X2H_BLOCKS - TQ_BLOCKS;
        in = wp; out = wpT; R = CDIM; Cc = CDIM;
        bx = (t % 9) * 32; by = (t / 9) * 32;
    }
    int xx = tid & 31, yy = tid >> 5;
#pragma unroll
    for (int j = 0; j < 4; j++)
        tt[yy + 8 * j][xx] = in[(size_t)(by + yy + 8 * j) * Cc + bx + xx];
    __syncthreads();
#pragma unroll
    for (int j = 0; j < 4; j++)
        out[(size_t)(bx + yy + 8 * j) * R + by + xx] = __float2half(tt[xx][yy + 8 * j]);
}

// ==================== GEMM1: cp.async 4-stage + ldmatrix ====================
#define G1_SMEM 71680

__global__ __launch_bounds__(256)
void gemm1_kernel(const __half* __restrict__ Aw, const __half* __restrict__ Bx,
                  __half* __restrict__ Ch, __half* __restrict__ vc) {
    extern __shared__ float smf[];
    const uint32_t smb = smem_u32_of(smf);
    const int tid = threadIdx.x, lane = tid & 31, warp = tid >> 5;
    const int qr = lane >> 2, qc = lane & 3;
    const int wm = warp & 1, wn = warp >> 1;
    const int n0 = blockIdx.x * 128;
    const int m0 = blockIdx.y * 96;
    const int bb = n0 >> 15;
    const int l0 = n0 & (L_TOT - 1);

    const int g8 = lane >> 3, lr = lane & 7;
    const int rowA = lr + (g8 & 1) * 8, colA = (g8 >> 1) * 16;
    const int rowB = lr + (g8 >> 1) * 8, colB = (g8 & 1) * 16;
    uint32_t aoff[3], boff[2];
#pragma unroll
    for (int mt = 0; mt < 3; mt++)
        aoff[mt] = (wm * 48 + mt * 16 + rowA) * 80 + colA;
#pragma unroll
    for (int p = 0; p < 2; p++)
        boff[p] = 7680 + (wn * 32 + p * 16 + rowB) * 80 + colB;

    float acc[3][4][4];
#pragma unroll
    for (int mt = 0; mt < 3; mt++)
#pragma unroll
        for (int nt = 0; nt < 4; nt++)
#pragma unroll
            for (int r = 0; r < 4; r++) acc[mt][nt][r] = 0.0f;

#define ISSUE(S, K0) do { \
    uint32_t base = smb + (S) * 17920; \
    { int r = tid >> 2, c = tid & 3; \
      CP16(base + r * 80 + c * 16, Aw + (size_t)(m0 + r) * CDIM + (K0) + c * 8); } \
    if (tid < 128) { int idx = tid + 256; \
      int r = idx >> 2, c = idx & 3; \
      CP16(base + r * 80 + c * 16, Aw + (size_t)(m0 + r) * CDIM + (K0) + c * 8); } \
    _Pragma("unroll") for (int i = 0; i < 2; i++) { \
      int idx = tid + i * 256; \
      int r = idx >> 2, c = idx & 3; \
      CP16(base + 7680 + r * 80 + c * 16, Bx + (size_t)(n0 + r) * CDIM + (K0) + c * 8); } \
    CP_COMMIT(); \
} while (0)

    ISSUE(0, 0);
    ISSUE(1, 32);
    ISSUE(2, 64);

#pragma unroll 1
    for (int ch = 0; ch < 9; ch++) {
        if (ch <= 6) { CP_WAIT2(); } else if (ch == 7) { CP_WAIT1(); } else { CP_WAIT0(); }
        __syncthreads();
        if (ch < 6) ISSUE((ch + 3) & 3, (ch + 3) * 32);

        const uint32_t sb = smb + (ch & 3) * 17920;
#pragma unroll
        for (int s = 0; s < 2; s++) {
            const int so = s * 32;
            uint32_t af[3][4], bf[2][4];
#pragma unroll
            for (int mt = 0; mt < 3; mt++)
                ldsm4(af[mt][0], af[mt][1], af[mt][2], af[mt][3], sb + aoff[mt] + so);
#pragma unroll
            for (int p = 0; p < 2; p++)
                ldsm4(bf[p][0], bf[p][1], bf[p][2], bf[p][3], sb + boff[p] + so);
#pragma unroll
            for (int mt = 0; mt < 3; mt++)
#pragma unroll
                for (int nt = 0; nt < 4; nt++)
                    mma16(acc[mt][nt], af[mt][0], af[mt][1], af[mt][2], af[mt][3],
                          bf[nt >> 1][(nt & 1) * 2], bf[nt >> 1][(nt & 1) * 2 + 1]);
        }
    }
#undef ISSUE
    __syncthreads();

    float* stg = smf;                  // [96][133]
#pragma unroll
    for (int mt = 0; mt < 3; mt++) {
        int r0 = wm * 48 + mt * 16 + qr;
#pragma unroll
        for (int nt = 0; nt < 4; nt++) {
            int c0 = wn * 32 + nt * 8 + 2 * qc;
            stg[r0 * 133 + c0]           = acc[mt][nt][0];
            stg[r0 * 133 + c0 + 1]       = acc[mt][nt][1];
            stg[(r0 + 8) * 133 + c0]     = acc[mt][nt][2];
            stg[(r0 + 8) * 133 + c0 + 1] = acc[mt][nt][3];
        }
    }
    __syncthreads();

#pragma unroll
    for (int i = 0; i < 6; i++) {
        int idx = tid + i * 256;
        int t = idx / 12, q = idx - t * 12;
        uint32_t u0 = pack_h2(stg[(q * 8 + 0) * 133 + t], stg[(q * 8 + 1) * 133 + t]);
        uint32_t u1 = pack_h2(stg[(q * 8 + 2) * 133 + t], stg[(q * 8 + 3) * 133 + t]);
        uint32_t u2 = pack_h2(stg[(q * 8 + 4) * 133 + t], stg[(q * 8 + 5) * 133 + t]);
        uint32_t u3 = pack_h2(stg[(q * 8 + 6) * 133 + t], stg[(q * 8 + 7) * 133 + t]);
        *(uint4*)(Ch + (size_t)(n0 + t) * QKV_N + m0 + q * 8) = make_uint4(u0, u1, u2, u3);
    }
    if (m0 >= 2 * CDIM) {
#pragma unroll
        for (int i = 0; i < 6; i++) {
            int idx = tid + i * 256;
            int m = idx >> 4, c8 = (idx & 15) * 8;
            uint32_t u0 = pack_h2(stg[m * 133 + c8 + 0], stg[m * 133 + c8 + 1]);
            uint32_t u1 = pack_h2(stg[m * 133 + c8 + 2], stg[m * 133 + c8 + 3]);
            uint32_t u2 = pack_h2(stg[m * 133 + c8 + 4], stg[m * 133 + c8 + 5]);
            uint32_t u3 = pack_h2(stg[m * 133 + c8 + 6], stg[m * 133 + c8 + 7]);
            *(uint4*)(vc + ((size_t)bb * CDIM + (m0 - 2 * CDIM) + m) * L_TOT + l0 + c8)
                = make_uint4(u0, u1, u2, u3);
        }
    }
}

// ==================== GEMM2: out = (y + lcm^T) @ w_proj + bias ====================
#define G2_SMEM 52736

__global__ __launch_bounds__(256)
void gemm2_kernel(const __half* __restrict__ Aw, const __half* __restrict__ By,
                  const __half* __restrict__ lcm, float* __restrict__ Cf,
                  const float* __restrict__ bias) {
    extern __shared__ float smf[];
    uint32_t* smh2 = (uint32_t*)smf;
    float* LS = smf + 8960;
    const uint32_t smb = smem_u32_of(smf);
    const int tid = threadIdx.x, lane = tid & 31, warp = tid >> 5;
    const int qr = lane >> 2, qc = lane & 3;
    const int wm = warp & 1, wn = warp >> 1;
    const int n0 = blockIdx.x * 128;
    const int m0 = blockIdx.y * 96;
    const int bb = n0 >> 15;
    const int l0 = n0 & (L_TOT - 1);

    const int g8 = lane >> 3, lr = lane & 7;
    const int rowA = lr + (g8 & 1) * 8, colA = (g8 >> 1) * 16;
    const int rowB = lr + (g8 >> 1) * 8, colB = (g8 & 1) * 16;
    uint32_t aoff[3], boff[2];
#pragma unroll
    for (int mt = 0; mt < 3; mt++)
        aoff[mt] = (wm * 48 + mt * 16 + rowA) * 80 + colA;
#pragma unroll
    for (int p = 0; p < 2; p++)
        boff[p] = 15360 + (wn * 32 + p * 16 + rowB) * 80 + colB;

    float acc[3][4][4];
#pragma unroll
    for (int mt = 0; mt < 3; mt++)
#pragma unroll
        for (int nt = 0; nt < 4; nt++)
#pragma unroll
            for (int r = 0; r < 4; r++) acc[mt][nt][r] = 0.0f;

    uint2 rA[3];
    uint4 rBy[2], rLc[2];

#define G_LOADS(K0) do { \
    _Pragma("unroll") for (int i = 0; i < 3; i++) { \
        int idx = tid + i * 256; int m = idx >> 3, q = idx & 7; \
        rA[i] = *(const uint2*)(Aw + (size_t)(m0 + m) * CDIM + (K0) + q * 4); } \
    _Pragma("unroll") for (int i = 0; i < 2; i++) { \
        int idx = tid + i * 256; int t = idx >> 2, k8 = (idx & 3) * 8; \
        rBy[i] = *(const uint4*)(By + (size_t)(n0 + t) * CDIM + (K0) + k8); } \
    _Pragma("unroll") for (int i = 0; i < 2; i++) { \
        int idx = tid + i * 256; int cc = idx >> 4, l8 = (idx & 15) * 8; \
        rLc[i] = *(const uint4*)(lcm + ((size_t)bb * CDIM + (K0) + cc) * L_TOT + l0 + l8); } \
} while (0)

#define S_STORES(BUF) do { \
    uint32_t* As_ = smh2 + ((BUF) ? 1920 : 0); \
    uint32_t* Bs_ = smh2 + ((BUF) ? 6400 : 3840); \
    _Pragma("unroll") for (int i = 0; i < 2; i++) { \
        int idx = tid + i * 256; int cc = idx >> 4, l8 = (idx & 15) * 8; \
        __half2* hh = (__half2*)&rLc[i]; \
        _Pragma("unroll") for (int e = 0; e < 4; e++) { \
            float2 f = __half22float2(hh[e]); \
            LS[(l8 + 2 * e) * 33 + cc]     = f.x; \
            LS[(l8 + 2 * e + 1) * 33 + cc] = f.y; } } \
    __syncthreads(); \
    _Pragma("unroll") for (int i = 0; i < 3; i++) { \
        int idx = tid + i * 256; int m = idx >> 3, q = idx & 7; \
        *(uint2*)(As_ + m * 20 + q * 2) = rA[i]; } \
    _Pragma("unroll") for (int i = 0; i < 2; i++) { \
        int idx = tid + i * 256; int t = idx >> 2, k8 = (idx & 3) * 8; \
        __half2* hh = (__half2*)&rBy[i]; \
        uint32_t u0, u1, u2, u3; \
        { float2 f = __half22float2(hh[0]); \
          u0 = pack_h2(f.x + LS[t * 33 + k8 + 0], f.y + LS[t * 33 + k8 + 1]); } \
        { float2 f = __half22float2(hh[1]); \
          u1 = pack_h2(f.x + LS[t * 33 + k8 + 2], f.y + LS[t * 33 + k8 + 3]); } \
        { float2 f = __half22float2(hh[2]); \
          u2 = pack_h2(f.x + LS[t * 33 + k8 + 4], f.y + LS[t * 33 + k8 + 5]); } \
        { float2 f = __half22float2(hh[3]); \
          u3 = pack_h2(f.x + LS[t * 33 + k8 + 6], f.y + LS[t * 33 + k8 + 7]); } \
        *(uint4*)(Bs_ + t * 20 + (k8 >> 1)) = make_uint4(u0, u1, u2, u3); } \
} while (0)

    G_LOADS(0);
    S_STORES(0);
    __syncthreads();

#pragma unroll 1
    for (int ch = 0; ch < 9; ch++) {
        const int cur = ch & 1;
        if (ch < 8) G_LOADS((ch + 1) * 32);

        const uint32_t abase = smb + (cur ? 7680 : 0);
        const uint32_t bbase = smb + (cur ? 10240 : 0);
#pragma unroll
        for (int s = 0; s < 2; s++) {
            const int so = s * 32;
            uint32_t af[3][4], bf[2][4];
#pragma unroll
            for (int mt = 0; mt < 3; mt++)
                ldsm4(af[mt][0], af[mt][1], af[mt][2], af[mt][3], abase + aoff[mt] + so);
#pragma unroll
            for (int p = 0; p < 2; p++)
                ldsm4(bf[p][0], bf[p][1], bf[p][2], bf[p][3], bbase + boff[p] + so);
#pragma unroll
            for (int mt = 0; mt < 3; mt++)
#pragma unroll
                for (int nt = 0; nt < 4; nt++)
                    mma16(acc[mt][nt], af[mt][0], af[mt][1], af[mt][2], af[mt][3],
                          bf[nt >> 1][(nt & 1) * 2], bf[nt >> 1][(nt & 1) * 2 + 1]);
        }

        if (ch < 8) {
            S_STORES(cur ^ 1);
            __syncthreads();
        }
    }
#undef G_LOADS
#undef S_STORES

    __syncthreads();
    float* stg = smf;
#pragma unroll
    for (int mt = 0; mt < 3; mt++) {
        int r0 = wm * 48 + mt * 16 + qr;
#pragma unroll
        for (int nt = 0; nt < 4; nt++) {
            int c0 = wn * 32 + nt * 8 + 2 * qc;
            stg[r0 * 133 + c0]           = acc[mt][nt][0];
            stg[r0 * 133 + c0 + 1]       = acc[mt][nt][1];
            stg[(r0 + 8) * 133 + c0]     = acc[mt][nt][2];
            stg[(r0 + 8) * 133 + c0 + 1] = acc[mt][nt][3];
        }
    }
    __syncthreads();

#pragma unroll
    for (int i = 0; i < 12; i++) {
        int idx = tid + i * 256;
        int t = idx / 24, q = idx - t * 24;
        float4 o;
        o.x = stg[(q * 4 + 0) * 133 + t] + bias[m0 + q * 4 + 0];
        o.y = stg[(q * 4 + 1) * 133 + t] + bias[m0 + q * 4 + 1];
        o.z = stg[(q * 4 + 2) * 133 + t] + bias[m0 + q * 4 + 2];
        o.w = stg[(q * 4 + 3) * 133 + t] + bias[m0 + q * 4 + 3];
        *(float4*)(Cf + (size_t)(n0 + t) * CDIM + m0 + q * 4) = o;
    }
}

// ==================== fused conv + attention ====================
// blocks [0, 1152): conv, (b,c) x d-half per 128-thread block
// blocks [1152, 1152+6144): attention, 2 windows per 128-thread block
#define CONV_BLOCKS (BATCH * CDIM * 2)        // 1152
#define ATTN_BLOCKS 6144
#define FUSE_BLOCKS (CONV_BLOCKS + ATTN_BLOCKS)

__global__ __launch_bounds__(128)
void attn_conv_kernel(const __half* __restrict__ qkv, const float* __restrict__ biasb,
                      __half* __restrict__ y, const __half* __restrict__ vc,
                      const float* __restrict__ cw, const float* __restrict__ cb,
                      __half* __restrict__ lcm) {
    __shared__ float shm[7168];
    const int tid = threadIdx.x;

    if (blockIdx.x >= CONV_BLOCKS) {
        // -------- attention: 2 windows, k/v fp32 smem stride 28, float4 loads --------
        const int abid = blockIdx.x - CONV_BLOCKS;
        const int bi = abid / 2048;
        const int rem = abid - bi * 2048;
        const int b = rem >> 10;
        const int pair = rem & 1023;
        const int Dsp = c_Dsp[bi], Hsp = c_Hsp[bi], Wsp = c_Wsp[bi];
        const int nH = RESV / Hsp, nW = RESV / Wsp;
        const int g  = tid >> 6;
        const int tl = tid & 63;
        int widx = pair * 2 + g;
        int wblk = widx % nW; int tmp = widx / nW;
        int hblk = tmp % nH;  int dblk = tmp / nH;

        const int hb = tl >> 4;
        const int n  = tl & 15;
        const int HW = Hsp * Wsp;
        int dd = n / HW; int r = n - dd * HW;
        int hh = r / Wsp; int ww = r - hh * Wsp;
        int l = ((dblk * Dsp + dd) * RESV + hblk * Hsp + hh) * RESV + wblk * Wsp + ww;

        size_t rowbase = ((size_t)b * L_TOT + l) * QKV_N + bi * 96 + hb * HDIM;

        float* skr = shm + g * 1792;          // [64][28]
        float* svr = shm + 3584 + g * 1792;   // [64][28]
        float q[HDIM];
        const float scale = 0.2041241452319315f;

        const uint4* qp = (const uint4*)(qkv + rowbase);
        const uint4* kp = (const uint4*)(qkv + rowbase + CDIM);
        const uint4* vp = (const uint4*)(qkv + rowbase + 2 * CDIM);
#pragma unroll
        for (int j = 0; j < 3; j++) {
            uint4 uq = qp[j], uk = kp[j], uv = vp[j];
            __half2* hq = (__half2*)&uq;
            __half2* hk = (__half2*)&uk;
            __half2* hv = (__half2*)&uv;
            float kk[8], vv[8];
#pragma unroll
            for (int e = 0; e < 4; e++) {
                float2 fq = __half22float2(hq[e]);
                q[8 * j + 2 * e]     = fq.x * scale;
                q[8 * j + 2 * e + 1] = fq.y * scale;
                float2 fk = __half22float2(hk[e]);
                kk[2 * e] = fk.x; kk[2 * e + 1] = fk.y;
                float2 fv = __half22float2(hv[e]);
                vv[2 * e] = fv.x; vv[2 * e + 1] = fv.y;
            }
            *(float4*)(skr + tl * 28 + 8 * j)     = make_float4(kk[0], kk[1], kk[2], kk[3]);
            *(float4*)(skr + tl * 28 + 8 * j + 4) = make_float4(kk[4], kk[5], kk[6], kk[7]);
            *(float4*)(svr + tl * 28 + 8 * j)     = make_float4(vv[0], vv[1], vv[2], vv[3]);
            *(float4*)(svr + tl * 28 + 8 * j + 4) = make_float4(vv[4], vv[5], vv[6], vv[7]);
        }
        __syncthreads();

        const float* brow = biasb + (((size_t)bi * HB + hb) * NWIN + n) * NWIN;
        float lg[NWIN];
        float mx = -1e30f;
#pragma unroll
        for (int m = 0; m < NWIN; m++) {
            float s = brow[m];
            const float4* kr = (const float4*)(skr + (hb * 16 + m) * 28);
#pragma unroll
            for (int e4 = 0; e4 < 6; e4++) {
                float4 kk = kr[e4];
                s = fmaf(q[4 * e4 + 0], kk.x, s);
                s = fmaf(q[4 * e4 + 1], kk.y, s);
                s = fmaf(q[4 * e4 + 2], kk.z, s);
                s = fmaf(q[4 * e4 + 3], kk.w, s);
            }
            lg[m] = s;
            mx = fmaxf(mx, s);
        }
        float sum = 0.f;
#pragma unroll
        for (int m = 0; m < NWIN; m++) { lg[m] = __expf(lg[m] - mx); sum += lg[m]; }
        float inv = 1.0f / sum;

        float o[HDIM];
#pragma unroll
        for (int e = 0; e < HDIM; e++) o[e] = 0.f;
#pragma unroll
        for (int m = 0; m < NWIN; m++) {
            float w = lg[m] * inv;
            const float4* vr = (const float4*)(svr + (hb * 16 + m) * 28);
#pragma unroll
            for (int e4 = 0; e4 < 6; e4++) {
                float4 vv = vr[e4];
                o[4 * e4 + 0] = fmaf(w, vv.x, o[4 * e4 + 0]);
                o[4 * e4 + 1] = fmaf(w, vv.y, o[4 * e4 + 1]);
                o[4 * e4 + 2] = fmaf(w, vv.z, o[4 * e4 + 2]);
                o[4 * e4 + 3] = fmaf(w, vv.w, o[4 * e4 + 3]);
            }
        }

        __half* yp = y + ((size_t)b * L_TOT + l) * CDIM + bi * 96 + hb * HDIM;
#pragma unroll
        for (int j = 0; j < 3; j++) {
            uint32_t u0 = pack_h2(o[8 * j + 0], o[8 * j + 1]);
            uint32_t u1 = pack_h2(o[8 * j + 2], o[8 * j + 3]);
            uint32_t u2 = pack_h2(o[8 * j + 4], o[8 * j + 5]);
            uint32_t u3 = pack_h2(o[8 * j + 6], o[8 * j + 7]);
            *(uint4*)(yp + 8 * j) = make_uint4(u0, u1, u2, u3);
        }
        return;
    }

    // -------- depthwise 3x3x3 conv, d split in halves --------
    const int bc  = blockIdx.x >> 1;             // b*288 + c
    const int dlo = (blockIdx.x & 1) * 16;
    const int dhi = dlo + 16;
    const int c = bc % CDIM;
    const __half* src = vc + (size_t)bc * L_TOT;
    __half* dst = lcm + (size_t)bc * L_TOT;

    float wt[27];
#pragma unroll
    for (int j = 0; j < 27; j++) wt[j] = cw[c * 27 + j];
    const float bias = cb[c];

    float* sp = shm;                             // [3][34][36]
    const int w = tid & 31;
    const int h0 = (tid >> 5) * 8;

    for (int i = tid; i < 3 * 34 * 36; i += 128) sp[i] = 0.f;
    __syncthreads();
    // preload planes dlo (and dlo-1 if any), dlo+1 into slots plane%3
    {
        float* s0 = sp + (dlo % 3) * 1224;
        float* s1 = sp + ((dlo + 1) % 3) * 1224;
#pragma unroll
        for (int jh = 0; jh < 8; jh++) {
            int h = h0 + jh;
            s0[(1 + h) * 36 + 1 + w] = __half2float(src[dlo * 1024 + h * 32 + w]);
            s1[(1 + h) * 36 + 1 + w] = __half2float(src[(dlo + 1) * 1024 + h * 32 + w]);
        }
        if (dlo > 0) {
            float* sm1 = sp + ((dlo + 2) % 3) * 1224;   // (dlo-1) % 3
#pragma unroll
            for (int jh = 0; jh < 8; jh++) {
                int h = h0 + jh;
                sm1[(1 + h) * 36 + 1 + w] = __half2float(src[(dlo - 1) * 1024 + h * 32 + w]);
            }
        }
    }
    __syncthreads();

#pragma unroll 1
    for (int d = dlo; d < dhi; d++) {
        const int bm = (d + 2) % 3;
        const int b0 = d % 3;
        const int bp = (d + 1) % 3;
        float acc[8];
#pragma unroll
        for (int jh = 0; jh < 8; jh++) acc[jh] = bias;

#define TAPS(BUF, KD) { \
        const float* P = sp + (BUF) * 1224; \
        _Pragma("unroll") \
        for (int rr = 0; rr < 10; rr++) { \
            float va = P[(h0 + rr) * 36 + w], vb = P[(h0 + rr) * 36 + w + 1], \
                  vcx = P[(h0 + rr) * 36 + w + 2]; \
            _Pragma("unroll") \
            for (int jh = 0; jh < 8; jh++) { \
                int kh = rr - jh; \
                if (kh >= 0 && kh < 3) { \
                    acc[jh] = fmaf(wt[(KD)*9 + kh*3 + 0], va, \
                              fmaf(wt[(KD)*9 + kh*3 + 1], vb, \
                              fmaf(wt[(KD)*9 + kh*3 + 2], vcx, acc[jh]))); \
                } \
            } \
        } }

        if (d > 0)  TAPS(bm, 0);
        TAPS(b0, 1);
        if (d < 31) TAPS(bp, 2);
#undef TAPS

#pragma unroll
        for (int jh = 0; jh < 8; jh++)
            dst[d * 1024 + (h0 + jh) * 32 + w] = __float2half(acc[jh]);

        __syncthreads();
        if (d + 2 <= dhi && d + 2 < 32 && d < dhi - 1) {
            const __half* s2 = src + (d + 2) * 1024;
            float* spn = sp + ((d + 2) % 3) * 1224;
#pragma unroll
            for (int jh = 0; jh < 8; jh++) {
                int h = h0 + jh;
                spn[(1 + h) * 36 + 1 + w] = __half2float(s2[h * 32 + w]);
            }
        }
        __syncthreads();
    }
}

// ==================== launch ====================
extern "C" void kernel_launch(void* const* d_in, const int* in_sizes, int n_in,
                              void* d_out, int out_size) {
    const float* x      = (const float*)d_in[0];
    const float* w_qkv  = (const float*)d_in[4];
    const float* w_proj = (const float*)d_in[5];
    const float* b_proj = (const float*)d_in[6];
    const float* conv_w = (const float*)d_in[7];
    const float* conv_b = (const float*)d_in[8];
    const float* pos_w  = (const float*)d_in[9];
    const float* pos_b  = (const float*)d_in[10];
    const float* ln1g   = (const float*)d_in[11];
    const float* ln1b   = (const float*)d_in[12];
    const float* lin1w  = (const float*)d_in[13];
    const float* lin1b  = (const float*)d_in[14];
    const float* ln2g   = (const float*)d_in[15];
    const float* ln2b   = (const float*)d_in[16];
    const float* lin2w  = (const float*)d_in[17];
    const float* lin2b  = (const float*)d_in[18];
    const float* ln3g   = (const float*)d_in[19];
    const float* ln3b   = (const float*)d_in[20];
    const float* lin3w  = (const float*)d_in[21];
    const float* lin3b  = (const float*)d_in[22];
    const float* rpe    = (const float*)d_in[23];
    const int*   relidx = (const int*)d_in[24];
    float* out = (float*)d_out;

    __half *xhp, *qkvp, *yp, *vcp, *lcmp, *wqkvT, *wprojT;
    float *bp;
    cudaGetSymbolAddress((void**)&xhp,    g_xh);
    cudaGetSymbolAddress((void**)&qkvp,   g_qkv);
    cudaGetSymbolAddress((void**)&yp,     g_y);
    cudaGetSymbolAddress((void**)&bp,     g_bias);
    cudaGetSymbolAddress((void**)&vcp,    g_vc);
    cudaGetSymbolAddress((void**)&lcmp,   g_lcm);
    cudaGetSymbolAddress((void**)&wqkvT,  g_wqkvT);
    cudaGetSymbolAddress((void**)&wprojT, g_wprojT);

    cudaFuncSetAttribute(gemm1_kernel, cudaFuncAttributeMaxDynamicSharedMemorySize, G1_SMEM);
    cudaFuncSetAttribute(gemm2_kernel, cudaFuncAttributeMaxDynamicSharedMemorySize, G2_SMEM);

    // 0) fused prep: biasmlp + x->half + weight transposes
    prep_kernel<<<PREP_BLOCKS, 256>>>(x, xhp, w_qkv, wqkvT, w_proj, wprojT,
                                      rpe, pos_w, pos_b,
                                      ln1g, ln1b, lin1w, lin1b,
                                      ln2g, ln2b, lin2w, lin2b,
                                      ln3g, ln3b, lin3w, lin3b,
                                      relidx, bp);

    // 1) qkv = xh @ w_qkv  (also writes v channel-major into vc)
    gemm1_kernel<<<dim3(NROWS / 128, QKV_N / 96), 256, G1_SMEM>>>(wqkvT, xhp, qkvp, vcp);

    // 2) fused conv (front) + attention
    attn_conv_kernel<<<FUSE_BLOCKS, 128>>>(qkvp, bp, yp, vcp, conv_w, conv_b, lcmp);

    // 3) out = (y + lcm^T) @ w_proj + b_proj   (launch index 3 -> ncu slot)
    gemm2_kernel<<<dim3(NROWS / 128, CDIM / 96), 256, G2_SMEM>>>(wprojT, yp, lcmp, out, b_proj);
}

// round 11
// speedup vs baseline: 4.7713x; 1.0618x over previous
#include <cuda_runtime.h>
#include <cuda_fp16.h>
#include <math.h>
#include <stdint.h>

// ---------------- problem constants ----------------
#define RESV   32
#define L_TOT  (RESV*RESV*RESV)      // 32768
#define BATCH  2
#define CDIM   288
#define QKV_N  (3*CDIM)              // 864
#define NROWS  (BATCH*L_TOT)         // 65536
#define HB     4
#define HDIM   24
#define NWIN   16
#define TBIAS  63

// scratch (no cudaMalloc allowed) — fp16 intermediates
__device__ __half g_xh  [(size_t)NROWS * CDIM];
__device__ __half g_qkv [(size_t)NROWS * QKV_N];
__device__ __half g_y   [(size_t)NROWS * CDIM];
__device__ __half g_vc  [(size_t)BATCH * CDIM * L_TOT];  // v, channel-major
__device__ __half g_lcm [(size_t)BATCH * CDIM * L_TOT];  // conv out, channel-major
__device__ __half g_wqkvT[(size_t)QKV_N * CDIM];
__device__ __half g_wprojT[(size_t)CDIM * CDIM];
__device__ float  g_bias[3 * HB * NWIN * NWIN];

__constant__ int c_Dsp[3] = {2, 2, 2};
__constant__ int c_Hsp[3] = {2, 2, 4};
__constant__ int c_Wsp[3] = {4, 4, 2};

// ==================== helpers ====================
__device__ __forceinline__ uint32_t smem_u32_of(const void* p) {
    uint32_t a;
    asm("{ .reg .u64 t; cvta.to.shared.u64 t, %1; cvt.u32.u64 %0, t; }" : "=r"(a) : "l"(p));
    return a;
}

__device__ __forceinline__ void mma16(float* d,
                                      uint32_t a0, uint32_t a1, uint32_t a2, uint32_t a3,
                                      uint32_t b0, uint32_t b1) {
    asm volatile("mma.sync.aligned.m16n8k16.row.col.f32.f16.f16.f32 "
                 "{%0,%1,%2,%3}, {%4,%5,%6,%7}, {%8,%9}, {%0,%1,%2,%3};"
                 : "+f"(d[0]), "+f"(d[1]), "+f"(d[2]), "+f"(d[3])
                 : "r"(a0), "r"(a1), "r"(a2), "r"(a3), "r"(b0), "r"(b1));
}

__device__ __forceinline__ void ldsm4(uint32_t& r0, uint32_t& r1, uint32_t& r2, uint32_t& r3,
                                      uint32_t addr) {
    asm volatile("ldmatrix.sync.aligned.m8n8.x4.shared.b16 {%0,%1,%2,%3}, [%4];"
                 : "=r"(r0), "=r"(r1), "=r"(r2), "=r"(r3) : "r"(addr));
}

__device__ __forceinline__ void ldsm4t(uint32_t& r0, uint32_t& r1, uint32_t& r2, uint32_t& r3,
                                       uint32_t addr) {
    asm volatile("ldmatrix.sync.aligned.m8n8.x4.trans.shared.b16 {%0,%1,%2,%3}, [%4];"
                 : "=r"(r0), "=r"(r1), "=r"(r2), "=r"(r3) : "r"(addr));
}

__device__ __forceinline__ uint32_t pack_h2(float x, float y) {
    __half2 h = __floats2half2_rn(x, y);
    return *(uint32_t*)&h;
}

#define CP16(dst, src) \
    asm volatile("cp.async.cg.shared.global [%0], [%1], 16;" :: "r"(dst), "l"(src))
#define CP_COMMIT() asm volatile("cp.async.commit_group;")
#define CP_WAIT2()  asm volatile("cp.async.wait_group 2;")
#define CP_WAIT1()  asm volatile("cp.async.wait_group 1;")
#define CP_WAIT0()  asm volatile("cp.async.wait_group 0;")

// ==================== RPE-bias MLP piece ====================
__device__ __forceinline__ void ln_relu6(float* h, const float* g, const float* b) {
    float m = 0.f;
#pragma unroll
    for (int j = 0; j < 6; j++) m += h[j];
    m *= (1.0f / 6.0f);
    float v = 0.f;
#pragma unroll
    for (int j = 0; j < 6; j++) { float d = h[j] - m; v += d * d; }
    v *= (1.0f / 6.0f);
    float inv = rsqrtf(v + 1e-5f);
#pragma unroll
    for (int j = 0; j < 6; j++) {
        float t = (h[j] - m) * inv * g[j] + b[j];
        h[j] = t > 0.f ? t : 0.f;
    }
}

// ==================== fused prep: biasmlp + x->half + weight transposes ====================
#define BM_BLOCKS  3
#define X2H_BLOCKS 9216
#define TQ_BLOCKS  (27 * 9)
#define TP_BLOCKS  (9 * 9)
#define PREP_BLOCKS (BM_BLOCKS + X2H_BLOCKS + TQ_BLOCKS + TP_BLOCKS)

__global__ __launch_bounds__(256)
void prep_kernel(const float* __restrict__ x, __half* __restrict__ xh,
                 const float* __restrict__ wq, __half* __restrict__ wqT,
                 const float* __restrict__ wp, __half* __restrict__ wpT,
                 const float* __restrict__ rpe,
                 const float* __restrict__ pw, const float* __restrict__ pb,
                 const float* __restrict__ g1, const float* __restrict__ be1,
                 const float* __restrict__ w1, const float* __restrict__ b1,
                 const float* __restrict__ g2, const float* __restrict__ be2,
                 const float* __restrict__ w2, const float* __restrict__ b2,
                 const float* __restrict__ g3, const float* __restrict__ be3,
                 const float* __restrict__ w3, const float* __restrict__ b3,
                 const int* __restrict__ relidx, float* __restrict__ biasb) {
    __shared__ float tt[32][33];
    __shared__ float p[TBIAS][HB];
    const int bid = blockIdx.x, tid = threadIdx.x;

    if (bid < BM_BLOCKS) {
        const int bi = bid;
        if (tid < TBIAS) {
            float h[6], tmp[6];
            const float* r = rpe + (bi * TBIAS + tid) * 3;
            float r0 = r[0], r1 = r[1], r2 = r[2];
#pragma unroll
            for (int j = 0; j < 6; j++)
                h[j] = pb[bi * 6 + j]
                     + r0 * pw[(bi * 3 + 0) * 6 + j]
                     + r1 * pw[(bi * 3 + 1) * 6 + j]
                     + r2 * pw[(bi * 3 + 2) * 6 + j];
            ln_relu6(h, g1 + bi * 6, be1 + bi * 6);
#pragma unroll
            for (int j = 0; j < 6; j++) {
                float s = b1[bi * 6 + j];
#pragma unroll
                for (int i = 0; i < 6; i++) s += h[i] * w1[(bi * 6 + i) * 6 + j];
                tmp[j] = s;
            }
#pragma unroll
            for (int j = 0; j < 6; j++) h[j] = tmp[j];
            ln_relu6(h, g2 + bi * 6, be2 + bi * 6);
#pragma unroll
            for (int j = 0; j < 6; j++) {
                float s = b2[bi * 6 + j];
#pragma unroll
                for (int i = 0; i < 6; i++) s += h[i] * w2[(bi * 6 + i) * 6 + j];
                tmp[j] = s;
            }
#pragma unroll
            for (int j = 0; j < 6; j++) h[j] = tmp[j];
            ln_relu6(h, g3 + bi * 6, be3 + bi * 6);
#pragma unroll
            for (int j = 0; j < HB; j++) {
                float s = b3[bi * HB + j];
#pragma unroll
                for (int i = 0; i < 6; i++) s += h[i] * w3[(bi * 6 + i) * HB + j];
                p[tid][j] = s;
            }
        }
        __syncthreads();
        for (int i = tid; i < HB * NWIN * NWIN; i += blockDim.x) {
            int hb = i >> 8;
            int nm = i & 255;
            biasb[bi * (HB * NWIN * NWIN) + i] = p[relidx[bi * 256 + nm]][hb];
        }
        return;
    }

    if (bid < BM_BLOCKS + X2H_BLOCKS) {
        size_t i = ((size_t)(bid - BM_BLOCKS) * 256 + tid) * 8;
        float4 a = *(const float4*)(x + i);
        float4 b = *(const float4*)(x + i + 4);
        *(uint4*)(xh + i) = make_uint4(pack_h2(a.x, a.y), pack_h2(a.z, a.w),
                                       pack_h2(b.x, b.y), pack_h2(b.z, b.w));
        return;
    }
    const float* in;  __half* out;  int R, Cc, bx, by;
    if (bid < BM_BLOCKS + X2H_BLOCKS + TQ_BLOCKS) {
        int t = bid - BM_BLOCKS - X2H_BLOCKS;
        in = wq; out = wqT; R = CDIM; Cc = QKV_N;
        bx = (t % 27) * 32; by = (t / 27) * 32;
    } else {
        int t = bid - BM_BLOCKS - X2H_BLOCKS - TQ_BLOCKS;
        in = wp; out = wpT; R = CDIM; Cc = CDIM;
        bx = (t % 9) * 32; by = (t / 9) * 32;
    }
    int xx = tid & 31, yy = tid >> 5;
#pragma unroll
    for (int j = 0; j < 4; j++)
        tt[yy + 8 * j][xx] = in[(size_t)(by + yy + 8 * j) * Cc + bx + xx];
    __syncthreads();
#pragma unroll
    for (int j = 0; j < 4; j++)
        out[(size_t)(bx + yy + 8 * j) * R + by + xx] = __float2half(tt[xx][yy + 8 * j]);
}

// ==================== GEMM1: cp.async 4-stage + ldmatrix ====================
#define G1_SMEM 71680

__global__ __launch_bounds__(256)
void gemm1_kernel(const __half* __restrict__ Aw, const __half* __restrict__ Bx,
                  __half* __restrict__ Ch, __half* __restrict__ vc) {
    extern __shared__ float smf[];
    const uint32_t smb = smem_u32_of(smf);
    const int tid = threadIdx.x, lane = tid & 31, warp = tid >> 5;
    const int qr = lane >> 2, qc = lane & 3;
    const int wm = warp & 1, wn = warp >> 1;
    const int n0 = blockIdx.x * 128;
    const int m0 = blockIdx.y * 96;
    const int bb = n0 >> 15;
    const int l0 = n0 & (L_TOT - 1);

    const int g8 = lane >> 3, lr = lane & 7;
    const int rowA = lr + (g8 & 1) * 8, colA = (g8 >> 1) * 16;
    const int rowB = lr + (g8 >> 1) * 8, colB = (g8 & 1) * 16;
    uint32_t aoff[3], boff[2];
#pragma unroll
    for (int mt = 0; mt < 3; mt++)
        aoff[mt] = (wm * 48 + mt * 16 + rowA) * 80 + colA;
#pragma unroll
    for (int p = 0; p < 2; p++)
        boff[p] = 7680 + (wn * 32 + p * 16 + rowB) * 80 + colB;

    float acc[3][4][4];
#pragma unroll
    for (int mt = 0; mt < 3; mt++)
#pragma unroll
        for (int nt = 0; nt < 4; nt++)
#pragma unroll
            for (int r = 0; r < 4; r++) acc[mt][nt][r] = 0.0f;

#define ISSUE(S, K0) do { \
    uint32_t base = smb + (S) * 17920; \
    { int r = tid >> 2, c = tid & 3; \
      CP16(base + r * 80 + c * 16, Aw + (size_t)(m0 + r) * CDIM + (K0) + c * 8); } \
    if (tid < 128) { int idx = tid + 256; \
      int r = idx >> 2, c = idx & 3; \
      CP16(base + r * 80 + c * 16, Aw + (size_t)(m0 + r) * CDIM + (K0) + c * 8); } \
    _Pragma("unroll") for (int i = 0; i < 2; i++) { \
      int idx = tid + i * 256; \
      int r = idx >> 2, c = idx & 3; \
      CP16(base + 7680 + r * 80 + c * 16, Bx + (size_t)(n0 + r) * CDIM + (K0) + c * 8); } \
    CP_COMMIT(); \
} while (0)

    ISSUE(0, 0);
    ISSUE(1, 32);
    ISSUE(2, 64);

#pragma unroll 1
    for (int ch = 0; ch < 9; ch++) {
        if (ch <= 6) { CP_WAIT2(); } else if (ch == 7) { CP_WAIT1(); } else { CP_WAIT0(); }
        __syncthreads();
        if (ch < 6) ISSUE((ch + 3) & 3, (ch + 3) * 32);

        const uint32_t sb = smb + (ch & 3) * 17920;
#pragma unroll
        for (int s = 0; s < 2; s++) {
            const int so = s * 32;
            uint32_t af[3][4], bf[2][4];
#pragma unroll
            for (int mt = 0; mt < 3; mt++)
                ldsm4(af[mt][0], af[mt][1], af[mt][2], af[mt][3], sb + aoff[mt] + so);
#pragma unroll
            for (int p = 0; p < 2; p++)
                ldsm4(bf[p][0], bf[p][1], bf[p][2], bf[p][3], sb + boff[p] + so);
#pragma unroll
            for (int mt = 0; mt < 3; mt++)
#pragma unroll
                for (int nt = 0; nt < 4; nt++)
                    mma16(acc[mt][nt], af[mt][0], af[mt][1], af[mt][2], af[mt][3],
                          bf[nt >> 1][(nt & 1) * 2], bf[nt >> 1][(nt & 1) * 2 + 1]);
        }
    }
#undef ISSUE
    __syncthreads();

    float* stg = smf;                  // [96][133]
#pragma unroll
    for (int mt = 0; mt < 3; mt++) {
        int r0 = wm * 48 + mt * 16 + qr;
#pragma unroll
        for (int nt = 0; nt < 4; nt++) {
            int c0 = wn * 32 + nt * 8 + 2 * qc;
            stg[r0 * 133 + c0]           = acc[mt][nt][0];
            stg[r0 * 133 + c0 + 1]       = acc[mt][nt][1];
            stg[(r0 + 8) * 133 + c0]     = acc[mt][nt][2];
            stg[(r0 + 8) * 133 + c0 + 1] = acc[mt][nt][3];
        }
    }
    __syncthreads();

#pragma unroll
    for (int i = 0; i < 6; i++) {
        int idx = tid + i * 256;
        int t = idx / 12, q = idx - t * 12;
        uint32_t u0 = pack_h2(stg[(q * 8 + 0) * 133 + t], stg[(q * 8 + 1) * 133 + t]);
        uint32_t u1 = pack_h2(stg[(q * 8 + 2) * 133 + t], stg[(q * 8 + 3) * 133 + t]);
        uint32_t u2 = pack_h2(stg[(q * 8 + 4) * 133 + t], stg[(q * 8 + 5) * 133 + t]);
        uint32_t u3 = pack_h2(stg[(q * 8 + 6) * 133 + t], stg[(q * 8 + 7) * 133 + t]);
        *(uint4*)(Ch + (size_t)(n0 + t) * QKV_N + m0 + q * 8) = make_uint4(u0, u1, u2, u3);
    }
    if (m0 >= 2 * CDIM) {
#pragma unroll
        for (int i = 0; i < 6; i++) {
            int idx = tid + i * 256;
            int m = idx >> 4, c8 = (idx & 15) * 8;
            uint32_t u0 = pack_h2(stg[m * 133 + c8 + 0], stg[m * 133 + c8 + 1]);
            uint32_t u1 = pack_h2(stg[m * 133 + c8 + 2], stg[m * 133 + c8 + 3]);
            uint32_t u2 = pack_h2(stg[m * 133 + c8 + 4], stg[m * 133 + c8 + 5]);
            uint32_t u3 = pack_h2(stg[m * 133 + c8 + 6], stg[m * 133 + c8 + 7]);
            *(uint4*)(vc + ((size_t)bb * CDIM + (m0 - 2 * CDIM) + m) * L_TOT + l0 + c8)
                = make_uint4(u0, u1, u2, u3);
        }
    }
}

// ==================== GEMM2: out = y @ Wp^T + lcm^T @ Wp^T + bias ====================
// cp.async 3-stage; per stage: A 96x32 (80B rows, 7680B), By 128x32 (80B rows, 10240B),
// Lc 32k x 128tok native channel-major (272B rows incl 16B pad, 8704B). Stage = 26624B.
// Lc read via ldmatrix.trans -> B fragment; dual-MMA accumulation (y + lcm^T in fp32).
#define G2_STAGE 26624
#define G2_SMEM  (3 * G2_STAGE)     // 79872

__global__ __launch_bounds__(256)
void gemm2_kernel(const __half* __restrict__ Aw, const __half* __restrict__ By,
                  const __half* __restrict__ lcm, float* __restrict__ Cf,
                  const float* __restrict__ bias) {
    extern __shared__ float smf[];
    const uint32_t smb = smem_u32_of(smf);
    const int tid = threadIdx.x, lane = tid & 31, warp = tid >> 5;
    const int qr = lane >> 2, qc = lane & 3;
    const int wm = warp & 1, wn = warp >> 1;
    const int n0 = blockIdx.x * 128;
    const int m0 = blockIdx.y * 96;
    const int bb = n0 >> 15;
    const int l0 = n0 & (L_TOT - 1);

    const int g8 = lane >> 3, lr = lane & 7;
    const int rowA = lr + (g8 & 1) * 8, colA = (g8 >> 1) * 16;
    const int rowB = lr + (g8 >> 1) * 8, colB = (g8 & 1) * 16;
    uint32_t aoff[3], byoff[2], lcoff[2];
#pragma unroll
    for (int mt = 0; mt < 3; mt++)
        aoff[mt] = (wm * 48 + mt * 16 + rowA) * 80 + colA;
#pragma unroll
    for (int p = 0; p < 2; p++) {
        byoff[p] = 7680 + (wn * 32 + p * 16 + rowB) * 80 + colB;
        // trans: mat rows are k (272B rows), col group = token offset
        lcoff[p] = 17920 + ((g8 & 1) * 8 + lr) * 272
                 + (wn * 32 + p * 16 + (g8 >> 1) * 8) * 2;
    }

    float acc[3][4][4];
#pragma unroll
    for (int mt = 0; mt < 3; mt++)
#pragma unroll
        for (int nt = 0; nt < 4; nt++)
#pragma unroll
            for (int r = 0; r < 4; r++) acc[mt][nt][r] = 0.0f;

#define ISSUE2(S, K0) do { \
    uint32_t base = smb + (S) * G2_STAGE; \
    { int r = tid >> 2, c = tid & 3; \
      CP16(base + r * 80 + c * 16, Aw + (size_t)(m0 + r) * CDIM + (K0) + c * 8); } \
    if (tid < 128) { int idx = tid + 256; \
      int r = idx >> 2, c = idx & 3; \
      CP16(base + r * 80 + c * 16, Aw + (size_t)(m0 + r) * CDIM + (K0) + c * 8); } \
    _Pragma("unroll") for (int i = 0; i < 2; i++) { \
      int idx = tid + i * 256; \
      int r = idx >> 2, c = idx & 3; \
      CP16(base + 7680 + r * 80 + c * 16, By + (size_t)(n0 + r) * CDIM + (K0) + c * 8); } \
    _Pragma("unroll") for (int i = 0; i < 2; i++) { \
      int idx = tid + i * 256; \
      int r = idx >> 4, c = idx & 15; \
      CP16(base + 17920 + r * 272 + c * 16, \
           lcm + ((size_t)bb * CDIM + (K0) + r) * L_TOT + l0 + c * 8); } \
    CP_COMMIT(); \
} while (0)

    ISSUE2(0, 0);
    ISSUE2(1, 32);

#pragma unroll 1
    for (int ch = 0; ch < 9; ch++) {
        if (ch <= 7) { CP_WAIT1(); } else { CP_WAIT0(); }
        __syncthreads();
        if (ch < 7) ISSUE2((ch + 2) % 3, (ch + 2) * 32);

        const uint32_t sb = smb + (ch % 3) * G2_STAGE;
#pragma unroll
        for (int s = 0; s < 2; s++) {
            uint32_t af[3][4], bfY[2][4], bfL[2][4];
#pragma unroll
            for (int mt = 0; mt < 3; mt++)
                ldsm4(af[mt][0], af[mt][1], af[mt][2], af[mt][3], sb + aoff[mt] + s * 32);
#pragma unroll
            for (int p = 0; p < 2; p++)
                ldsm4(bfY[p][0], bfY[p][1], bfY[p][2], bfY[p][3], sb + byoff[p] + s * 32);
#pragma unroll
            for (int p = 0; p < 2; p++)
                ldsm4t(bfL[p][0], bfL[p][1], bfL[p][2], bfL[p][3], sb + lcoff[p] + s * 4352);
#pragma unroll
            for (int mt = 0; mt < 3; mt++)
#pragma unroll
                for (int nt = 0; nt < 4; nt++) {
                    mma16(acc[mt][nt], af[mt][0], af[mt][1], af[mt][2], af[mt][3],
                          bfY[nt >> 1][(nt & 1) * 2], bfY[nt >> 1][(nt & 1) * 2 + 1]);
                    mma16(acc[mt][nt], af[mt][0], af[mt][1], af[mt][2], af[mt][3],
                          bfL[nt >> 1][(nt & 1) * 2], bfL[nt >> 1][(nt & 1) * 2 + 1]);
                }
        }
    }
#undef ISSUE2
    __syncthreads();

    float* stg = smf;                  // [96][133]
#pragma unroll
    for (int mt = 0; mt < 3; mt++) {
        int r0 = wm * 48 + mt * 16 + qr;
#pragma unroll
        for (int nt = 0; nt < 4; nt++) {
            int c0 = wn * 32 + nt * 8 + 2 * qc;
            stg[r0 * 133 + c0]           = acc[mt][nt][0];
            stg[r0 * 133 + c0 + 1]       = acc[mt][nt][1];
            stg[(r0 + 8) * 133 + c0]     = acc[mt][nt][2];
            stg[(r0 + 8) * 133 + c0 + 1] = acc[mt][nt][3];
        }
    }
    __syncthreads();

#pragma unroll
    for (int i = 0; i < 12; i++) {
        int idx = tid + i * 256;
        int t = idx / 24, q = idx - t * 24;
        float4 o;
        o.x = stg[(q * 4 + 0) * 133 + t] + bias[m0 + q * 4 + 0];
        o.y = stg[(q * 4 + 1) * 133 + t] + bias[m0 + q * 4 + 1];
        o.z = stg[(q * 4 + 2) * 133 + t] + bias[m0 + q * 4 + 2];
        o.w = stg[(q * 4 + 3) * 133 + t] + bias[m0 + q * 4 + 3];
        *(float4*)(Cf + (size_t)(n0 + t) * CDIM + m0 + q * 4) = o;
    }
}

// ==================== fused conv + attention ====================
#define CONV_BLOCKS (BATCH * CDIM * 2)        // 1152
#define ATTN_BLOCKS 6144
#define FUSE_BLOCKS (CONV_BLOCKS + ATTN_BLOCKS)

__global__ __launch_bounds__(128)
void attn_conv_kernel(const __half* __restrict__ qkv, const float* __restrict__ biasb,
                      __half* __restrict__ y, const __half* __restrict__ vc,
                      const float* __restrict__ cw, const float* __restrict__ cb,
                      __half* __restrict__ lcm) {
    __shared__ float shm[7168];
    const int tid = threadIdx.x;

    if (blockIdx.x >= CONV_BLOCKS) {
        const int abid = blockIdx.x - CONV_BLOCKS;
        const int bi = abid / 2048;
        const int rem = abid - bi * 2048;
        const int b = rem >> 10;
        const int pair = rem & 1023;
        const int Dsp = c_Dsp[bi], Hsp = c_Hsp[bi], Wsp = c_Wsp[bi];
        const int nH = RESV / Hsp, nW = RESV / Wsp;
        const int g  = tid >> 6;
        const int tl = tid & 63;
        int widx = pair * 2 + g;
        int wblk = widx % nW; int tmp = widx / nW;
        int hblk = tmp % nH;  int dblk = tmp / nH;

        const int hb = tl >> 4;
        const int n  = tl & 15;
        const int HW = Hsp * Wsp;
        int dd = n / HW; int r = n - dd * HW;
        int hh = r / Wsp; int ww = r - hh * Wsp;
        int l = ((dblk * Dsp + dd) * RESV + hblk * Hsp + hh) * RESV + wblk * Wsp + ww;

        size_t rowbase = ((size_t)b * L_TOT + l) * QKV_N + bi * 96 + hb * HDIM;

        float* skr = shm + g * 1792;          // [64][28]
        float* svr = shm + 3584 + g * 1792;
        float q[HDIM];
        const float scale = 0.2041241452319315f;

        const uint4* qp = (const uint4*)(qkv + rowbase);
        const uint4* kp = (const uint4*)(qkv + rowbase + CDIM);
        const uint4* vp = (const uint4*)(qkv + rowbase + 2 * CDIM);
#pragma unroll
        for (int j = 0; j < 3; j++) {
            uint4 uq = qp[j], uk = kp[j], uv = vp[j];
            __half2* hq = (__half2*)&uq;
            __half2* hk = (__half2*)&uk;
            __half2* hv = (__half2*)&uv;
            float kk[8], vv[8];
#pragma unroll
            for (int e = 0; e < 4; e++) {
                float2 fq = __half22float2(hq[e]);
                q[8 * j + 2 * e]     = fq.x * scale;
                q[8 * j + 2 * e + 1] = fq.y * scale;
                float2 fk = __half22float2(hk[e]);
                kk[2 * e] = fk.x; kk[2 * e + 1] = fk.y;
                float2 fv = __half22float2(hv[e]);
                vv[2 * e] = fv.x; vv[2 * e + 1] = fv.y;
            }
            *(float4*)(skr + tl * 28 + 8 * j)     = make_float4(kk[0], kk[1], kk[2], kk[3]);
            *(float4*)(skr + tl * 28 + 8 * j + 4) = make_float4(kk[4], kk[5], kk[6], kk[7]);
            *(float4*)(svr + tl * 28 + 8 * j)     = make_float4(vv[0], vv[1], vv[2], vv[3]);
            *(float4*)(svr + tl * 28 + 8 * j + 4) = make_float4(vv[4], vv[5], vv[6], vv[7]);
        }
        __syncthreads();

        const float* brow = biasb + (((size_t)bi * HB + hb) * NWIN + n) * NWIN;
        float lg[NWIN];
        float mx = -1e30f;
#pragma unroll
        for (int m = 0; m < NWIN; m++) {
            float s = brow[m];
            const float4* kr = (const float4*)(skr + (hb * 16 + m) * 28);
#pragma unroll
            for (int e4 = 0; e4 < 6; e4++) {
                float4 kk = kr[e4];
                s = fmaf(q[4 * e4 + 0], kk.x, s);
                s = fmaf(q[4 * e4 + 1], kk.y, s);
                s = fmaf(q[4 * e4 + 2], kk.z, s);
                s = fmaf(q[4 * e4 + 3], kk.w, s);
            }
            lg[m] = s;
            mx = fmaxf(mx, s);
        }
        float sum = 0.f;
#pragma unroll
        for (int m = 0; m < NWIN; m++) { lg[m] = __expf(lg[m] - mx); sum += lg[m]; }
        float inv = 1.0f / sum;

        float o[HDIM];
#pragma unroll
        for (int e = 0; e < HDIM; e++) o[e] = 0.f;
#pragma unroll
        for (int m = 0; m < NWIN; m++) {
            float w = lg[m] * inv;
            const float4* vr = (const float4*)(svr + (hb * 16 + m) * 28);
#pragma unroll
            for (int e4 = 0; e4 < 6; e4++) {
                float4 vv = vr[e4];
                o[4 * e4 + 0] = fmaf(w, vv.x, o[4 * e4 + 0]);
                o[4 * e4 + 1] = fmaf(w, vv.y, o[4 * e4 + 1]);
                o[4 * e4 + 2] = fmaf(w, vv.z, o[4 * e4 + 2]);
                o[4 * e4 + 3] = fmaf(w, vv.w, o[4 * e4 + 3]);
            }
        }

        __half* yp = y + ((size_t)b * L_TOT + l) * CDIM + bi * 96 + hb * HDIM;
#pragma unroll
        for (int j = 0; j < 3; j++) {
            uint32_t u0 = pack_h2(o[8 * j + 0], o[8 * j + 1]);
            uint32_t u1 = pack_h2(o[8 * j + 2], o[8 * j + 3]);
            uint32_t u2 = pack_h2(o[8 * j + 4], o[8 * j + 5]);
            uint32_t u3 = pack_h2(o[8 * j + 6], o[8 * j + 7]);
            *(uint4*)(yp + 8 * j) = make_uint4(u0, u1, u2, u3);
        }
        return;
    }

    // -------- depthwise 3x3x3 conv, d split in halves --------
    const int bc  = blockIdx.x >> 1;
    const int dlo = (blockIdx.x & 1) * 16;
    const int dhi = dlo + 16;
    const int c = bc % CDIM;
    const __half* src = vc + (size_t)bc * L_TOT;
    __half* dst = lcm + (size_t)bc * L_TOT;

    float wt[27];
#pragma unroll
    for (int j = 0; j < 27; j++) wt[j] = cw[c * 27 + j];
    const float bias = cb[c];

    float* sp = shm;
    const int w = tid & 31;
    const int h0 = (tid >> 5) * 8;

    for (int i = tid; i < 3 * 34 * 36; i += 128) sp[i] = 0.f;
    __syncthreads();
    {
        float* s0 = sp + (dlo % 3) * 1224;
        float* s1 = sp + ((dlo + 1) % 3) * 1224;
#pragma unroll
        for (int jh = 0; jh < 8; jh++) {
            int h = h0 + jh;
            s0[(1 + h) * 36 + 1 + w] = __half2float(src[dlo * 1024 + h * 32 + w]);
            s1[(1 + h) * 36 + 1 + w] = __half2float(src[(dlo + 1) * 1024 + h * 32 + w]);
        }
        if (dlo > 0) {
            float* sm1 = sp + ((dlo + 2) % 3) * 1224;
#pragma unroll
            for (int jh = 0; jh < 8; jh++) {
                int h = h0 + jh;
                sm1[(1 + h) * 36 + 1 + w] = __half2float(src[(dlo - 1) * 1024 + h * 32 + w]);
            }
        }
    }
    __syncthreads();

#pragma unroll 1
    for (int d = dlo; d < dhi; d++) {
        const int bm = (d + 2) % 3;
        const int b0 = d % 3;
        const int bp = (d + 1) % 3;
        float acc[8];
#pragma unroll
        for (int jh = 0; jh < 8; jh++) acc[jh] = bias;

#define TAPS(BUF, KD) { \
        const float* P = sp + (BUF) * 1224; \
        _Pragma("unroll") \
        for (int rr = 0; rr < 10; rr++) { \
            float va = P[(h0 + rr) * 36 + w], vb = P[(h0 + rr) * 36 + w + 1], \
                  vcx = P[(h0 + rr) * 36 + w + 2]; \
            _Pragma("unroll") \
            for (int jh = 0; jh < 8; jh++) { \
                int kh = rr - jh; \
                if (kh >= 0 && kh < 3) { \
                    acc[jh] = fmaf(wt[(KD)*9 + kh*3 + 0], va, \
                              fmaf(wt[(KD)*9 + kh*3 + 1], vb, \
                              fmaf(wt[(KD)*9 + kh*3 + 2], vcx, acc[jh]))); \
                } \
            } \
        } }

        if (d > 0)  TAPS(bm, 0);
        TAPS(b0, 1);
        if (d < 31) TAPS(bp, 2);
#undef TAPS

#pragma unroll
        for (int jh = 0; jh < 8; jh++)
            dst[d * 1024 + (h0 + jh) * 32 + w] = __float2half(acc[jh]);

        __syncthreads();
        if (d + 2 <= dhi && d + 2 < 32 && d < dhi - 1) {
            const __half* s2 = src + (d + 2) * 1024;
            float* spn = sp + ((d + 2) % 3) * 1224;
#pragma unroll
            for (int jh = 0; jh < 8; jh++) {
                int h = h0 + jh;
                spn[(1 + h) * 36 + 1 + w] = __half2float(s2[h * 32 + w]);
            }
        }
        __syncthreads();
    }
}

// ==================== launch ====================
extern "C" void kernel_launch(void* const* d_in, const int* in_sizes, int n_in,
                              void* d_out, int out_size) {
    const float* x      = (const float*)d_in[0];
    const float* w_qkv  = (const float*)d_in[4];
    const float* w_proj = (const float*)d_in[5];
    const float* b_proj = (const float*)d_in[6];
    const float* conv_w = (const float*)d_in[7];
    const float* conv_b = (const float*)d_in[8];
    const float* pos_w  = (const float*)d_in[9];
    const float* pos_b  = (const float*)d_in[10];
    const float* ln1g   = (const float*)d_in[11];
    const float* ln1b   = (const float*)d_in[12];
    const float* lin1w  = (const float*)d_in[13];
    const float* lin1b  = (const float*)d_in[14];
    const float* ln2g   = (const float*)d_in[15];
    const float* ln2b   = (const float*)d_in[16];
    const float* lin2w  = (const float*)d_in[17];
    const float* lin2b  = (const float*)d_in[18];
    const float* ln3g   = (const float*)d_in[19];
    const float* ln3b   = (const float*)d_in[20];
    const float* lin3w  = (const float*)d_in[21];
    const float* lin3b  = (const float*)d_in[22];
    const float* rpe    = (const float*)d_in[23];
    const int*   relidx = (const int*)d_in[24];
    float* out = (float*)d_out;

    __half *xhp, *qkvp, *yp, *vcp, *lcmp, *wqkvT, *wprojT;
    float *bp;
    cudaGetSymbolAddress((void**)&xhp,    g_xh);
    cudaGetSymbolAddress((void**)&qkvp,   g_qkv);
    cudaGetSymbolAddress((void**)&yp,     g_y);
    cudaGetSymbolAddress((void**)&bp,     g_bias);
    cudaGetSymbolAddress((void**)&vcp,    g_vc);
    cudaGetSymbolAddress((void**)&lcmp,   g_lcm);
    cudaGetSymbolAddress((void**)&wqkvT,  g_wqkvT);
    cudaGetSymbolAddress((void**)&wprojT, g_wprojT);

    cudaFuncSetAttribute(gemm1_kernel, cudaFuncAttributeMaxDynamicSharedMemorySize, G1_SMEM);
    cudaFuncSetAttribute(gemm2_kernel, cudaFuncAttributeMaxDynamicSharedMemorySize, G2_SMEM);

    // 0) fused prep: biasmlp + x->half + weight transposes
    prep_kernel<<<PREP_BLOCKS, 256>>>(x, xhp, w_qkv, wqkvT, w_proj, wprojT,
                                      rpe, pos_w, pos_b,
                                      ln1g, ln1b, lin1w, lin1b,
                                      ln2g, ln2b, lin2w, lin2b,
                                      ln3g, ln3b, lin3w, lin3b,
                                      relidx, bp);

    // 1) qkv = xh @ w_qkv  (also writes v channel-major into vc)
    gemm1_kernel<<<dim3(NROWS / 128, QKV_N / 96), 256, G1_SMEM>>>(wqkvT, xhp, qkvp, vcp);

    // 2) fused conv (front) + attention
    attn_conv_kernel<<<FUSE_BLOCKS, 128>>>(qkvp, bp, yp, vcp, conv_w, conv_b, lcmp);

    // 3) out = y @ Wp^T + lcm^T @ Wp^T + bias   (ncu slot)
    gemm2_kernel<<<dim3(NROWS / 128, CDIM / 96), 256, G2_SMEM>>>(wprojT, yp, lcmp, out, b_proj);
}

// round 12
// speedup vs baseline: 4.7969x; 1.0054x over previous
#include <cuda_runtime.h>
#include <cuda_fp16.h>
#include <math.h>
#include <stdint.h>

// ---------------- problem constants ----------------
#define RESV   32
#define L_TOT  (RESV*RESV*RESV)      // 32768
#define BATCH  2
#define CDIM   288
#define QKV_N  (3*CDIM)              // 864
#define NROWS  (BATCH*L_TOT)         // 65536
#define HB     4
#define HDIM   24
#define NWIN   16
#define TBIAS  63

// scratch (no cudaMalloc allowed) — fp16 intermediates
__device__ __half g_xh  [(size_t)NROWS * CDIM];
__device__ __half g_qkv [(size_t)NROWS * QKV_N];
__device__ __half g_y   [(size_t)NROWS * CDIM];
__device__ __half g_vc  [(size_t)BATCH * CDIM * L_TOT];  // v, channel-major
__device__ __half g_lcm [(size_t)BATCH * CDIM * L_TOT];  // conv out, channel-major
__device__ __half g_wqkvT[(size_t)QKV_N * CDIM];
__device__ __half g_wprojT[(size_t)CDIM * CDIM];
__device__ float  g_bias[3 * HB * NWIN * NWIN];

__constant__ int c_Dsp[3] = {2, 2, 2};
__constant__ int c_Hsp[3] = {2, 2, 4};
__constant__ int c_Wsp[3] = {4, 4, 2};

// ==================== helpers ====================
__device__ __forceinline__ uint32_t smem_u32_of(const void* p) {
    uint32_t a;
    asm("{ .reg .u64 t; cvta.to.shared.u64 t, %1; cvt.u32.u64 %0, t; }" : "=r"(a) : "l"(p));
    return a;
}

__device__ __forceinline__ void mma16(float* d,
                                      uint32_t a0, uint32_t a1, uint32_t a2, uint32_t a3,
                                      uint32_t b0, uint32_t b1) {
    asm volatile("mma.sync.aligned.m16n8k16.row.col.f32.f16.f16.f32 "
                 "{%0,%1,%2,%3}, {%4,%5,%6,%7}, {%8,%9}, {%0,%1,%2,%3};"
                 : "+f"(d[0]), "+f"(d[1]), "+f"(d[2]), "+f"(d[3])
                 : "r"(a0), "r"(a1), "r"(a2), "r"(a3), "r"(b0), "r"(b1));
}

__device__ __forceinline__ void ldsm4(uint32_t& r0, uint32_t& r1, uint32_t& r2, uint32_t& r3,
                                      uint32_t addr) {
    asm volatile("ldmatrix.sync.aligned.m8n8.x4.shared.b16 {%0,%1,%2,%3}, [%4];"
                 : "=r"(r0), "=r"(r1), "=r"(r2), "=r"(r3) : "r"(addr));
}

__device__ __forceinline__ void ldsm4t(uint32_t& r0, uint32_t& r1, uint32_t& r2, uint32_t& r3,
                                       uint32_t addr) {
    asm volatile("ldmatrix.sync.aligned.m8n8.x4.trans.shared.b16 {%0,%1,%2,%3}, [%4];"
                 : "=r"(r0), "=r"(r1), "=r"(r2), "=r"(r3) : "r"(addr));
}

__device__ __forceinline__ uint32_t pack_h2(float x, float y) {
    __half2 h = __floats2half2_rn(x, y);
    return *(uint32_t*)&h;
}

#define CP16(dst, src) \
    asm volatile("cp.async.cg.shared.global [%0], [%1], 16;" :: "r"(dst), "l"(src))
#define CP_COMMIT() asm volatile("cp.async.commit_group;")
#define CP_WAIT2()  asm volatile("cp.async.wait_group 2;")
#define CP_WAIT1()  asm volatile("cp.async.wait_group 1;")
#define CP_WAIT0()  asm volatile("cp.async.wait_group 0;")

// ==================== RPE-bias MLP piece ====================
__device__ __forceinline__ void ln_relu6(float* h, const float* g, const float* b) {
    float m = 0.f;
#pragma unroll
    for (int j = 0; j < 6; j++) m += h[j];
    m *= (1.0f / 6.0f);
    float v = 0.f;
#pragma unroll
    for (int j = 0; j < 6; j++) { float d = h[j] - m; v += d * d; }
    v *= (1.0f / 6.0f);
    float inv = rsqrtf(v + 1e-5f);
#pragma unroll
    for (int j = 0; j < 6; j++) {
        float t = (h[j] - m) * inv * g[j] + b[j];
        h[j] = t > 0.f ? t : 0.f;
    }
}

// ==================== fused prep: biasmlp + x->half + weight transposes ====================
#define BM_BLOCKS  3
#define X2H_BLOCKS 9216
#define TQ_BLOCKS  (27 * 9)
#define TP_BLOCKS  (9 * 9)
#define PREP_BLOCKS (BM_BLOCKS + X2H_BLOCKS + TQ_BLOCKS + TP_BLOCKS)

__global__ __launch_bounds__(256)
void prep_kernel(const float* __restrict__ x, __half* __restrict__ xh,
                 const float* __restrict__ wq, __half* __restrict__ wqT,
                 const float* __restrict__ wp, __half* __restrict__ wpT,
                 const float* __restrict__ rpe,
                 const float* __restrict__ pw, const float* __restrict__ pb,
                 const float* __restrict__ g1, const float* __restrict__ be1,
                 const float* __restrict__ w1, const float* __restrict__ b1,
                 const float* __restrict__ g2, const float* __restrict__ be2,
                 const float* __restrict__ w2, const float* __restrict__ b2,
                 const float* __restrict__ g3, const float* __restrict__ be3,
                 const float* __restrict__ w3, const float* __restrict__ b3,
                 const int* __restrict__ relidx, float* __restrict__ biasb) {
    __shared__ float tt[32][33];
    __shared__ float p[TBIAS][HB];
    const int bid = blockIdx.x, tid = threadIdx.x;

    if (bid < BM_BLOCKS) {
        const int bi = bid;
        if (tid < TBIAS) {
            float h[6], tmp[6];
            const float* r = rpe + (bi * TBIAS + tid) * 3;
            float r0 = r[0], r1 = r[1], r2 = r[2];
#pragma unroll
            for (int j = 0; j < 6; j++)
                h[j] = pb[bi * 6 + j]
                     + r0 * pw[(bi * 3 + 0) * 6 + j]
                     + r1 * pw[(bi * 3 + 1) * 6 + j]
                     + r2 * pw[(bi * 3 + 2) * 6 + j];
            ln_relu6(h, g1 + bi * 6, be1 + bi * 6);
#pragma unroll
            for (int j = 0; j < 6; j++) {
                float s = b1[bi * 6 + j];
#pragma unroll
                for (int i = 0; i < 6; i++) s += h[i] * w1[(bi * 6 + i) * 6 + j];
                tmp[j] = s;
            }
#pragma unroll
            for (int j = 0; j < 6; j++) h[j] = tmp[j];
            ln_relu6(h, g2 + bi * 6, be2 + bi * 6);
#pragma unroll
            for (int j = 0; j < 6; j++) {
                float s = b2[bi * 6 + j];
#pragma unroll
                for (int i = 0; i < 6; i++) s += h[i] * w2[(bi * 6 + i) * 6 + j];
                tmp[j] = s;
            }
#pragma unroll
            for (int j = 0; j < 6; j++) h[j] = tmp[j];
            ln_relu6(h, g3 + bi * 6, be3 + bi * 6);
#pragma unroll
            for (int j = 0; j < HB; j++) {
                float s = b3[bi * HB + j];
#pragma unroll
                for (int i = 0; i < 6; i++) s += h[i] * w3[(bi * 6 + i) * HB + j];
                p[tid][j] = s;
            }
        }
        __syncthreads();
        for (int i = tid; i < HB * NWIN * NWIN; i += blockDim.x) {
            int hb = i >> 8;
            int nm = i & 255;
            biasb[bi * (HB * NWIN * NWIN) + i] = p[relidx[bi * 256 + nm]][hb];
        }
        return;
    }

    if (bid < BM_BLOCKS + X2H_BLOCKS) {
        size_t i = ((size_t)(bid - BM_BLOCKS) * 256 + tid) * 8;
        float4 a = *(const float4*)(x + i);
        float4 b = *(const float4*)(x + i + 4);
        *(uint4*)(xh + i) = make_uint4(pack_h2(a.x, a.y), pack_h2(a.z, a.w),
                                       pack_h2(b.x, b.y), pack_h2(b.z, b.w));
        return;
    }
    const float* in;  __half* out;  int R, Cc, bx, by;
    if (bid < BM_BLOCKS + X2H_BLOCKS + TQ_BLOCKS) {
        int t = bid - BM_BLOCKS - X2H_BLOCKS;
        in = wq; out = wqT; R = CDIM; Cc = QKV_N;
        bx = (t % 27) * 32; by = (t / 27) * 32;
    } else {
        int t = bid - BM_BLOCKS - X2H_BLOCKS - TQ_BLOCKS;
        in = wp; out = wpT; R = CDIM; Cc = CDIM;
        bx = (t % 9) * 32; by = (t / 9) * 32;
    }
    int xx = tid & 31, yy = tid >> 5;
#pragma unroll
    for (int j = 0; j < 4; j++)
        tt[yy + 8 * j][xx] = in[(size_t)(by + yy + 8 * j) * Cc + bx + xx];
    __syncthreads();
#pragma unroll
    for (int j = 0; j < 4; j++)
        out[(size_t)(bx + yy + 8 * j) * R + by + xx] = __float2half(tt[xx][yy + 8 * j]);
}

// ==================== GEMM1: cp.async 4-stage + ldmatrix ====================
#define G1_SMEM 71680

__global__ __launch_bounds__(256)
void gemm1_kernel(const __half* __restrict__ Aw, const __half* __restrict__ Bx,
                  __half* __restrict__ Ch, __half* __restrict__ vc) {
    extern __shared__ float smf[];
    const uint32_t smb = smem_u32_of(smf);
    const int tid = threadIdx.x, lane = tid & 31, warp = tid >> 5;
    const int qr = lane >> 2, qc = lane & 3;
    const int wm = warp & 1, wn = warp >> 1;
    const int n0 = blockIdx.x * 128;
    const int m0 = blockIdx.y * 96;
    const int bb = n0 >> 15;
    const int l0 = n0 & (L_TOT - 1);

    const int g8 = lane >> 3, lr = lane & 7;
    const int rowA = lr + (g8 & 1) * 8, colA = (g8 >> 1) * 16;
    const int rowB = lr + (g8 >> 1) * 8, colB = (g8 & 1) * 16;
    uint32_t aoff[3], boff[2];
#pragma unroll
    for (int mt = 0; mt < 3; mt++)
        aoff[mt] = (wm * 48 + mt * 16 + rowA) * 80 + colA;
#pragma unroll
    for (int p = 0; p < 2; p++)
        boff[p] = 7680 + (wn * 32 + p * 16 + rowB) * 80 + colB;

    float acc[3][4][4];
#pragma unroll
    for (int mt = 0; mt < 3; mt++)
#pragma unroll
        for (int nt = 0; nt < 4; nt++)
#pragma unroll
            for (int r = 0; r < 4; r++) acc[mt][nt][r] = 0.0f;

#define ISSUE(S, K0) do { \
    uint32_t base = smb + (S) * 17920; \
    { int r = tid >> 2, c = tid & 3; \
      CP16(base + r * 80 + c * 16, Aw + (size_t)(m0 + r) * CDIM + (K0) + c * 8); } \
    if (tid < 128) { int idx = tid + 256; \
      int r = idx >> 2, c = idx & 3; \
      CP16(base + r * 80 + c * 16, Aw + (size_t)(m0 + r) * CDIM + (K0) + c * 8); } \
    _Pragma("unroll") for (int i = 0; i < 2; i++) { \
      int idx = tid + i * 256; \
      int r = idx >> 2, c = idx & 3; \
      CP16(base + 7680 + r * 80 + c * 16, Bx + (size_t)(n0 + r) * CDIM + (K0) + c * 8); } \
    CP_COMMIT(); \
} while (0)

    ISSUE(0, 0);
    ISSUE(1, 32);
    ISSUE(2, 64);

#pragma unroll 1
    for (int ch = 0; ch < 9; ch++) {
        if (ch <= 6) { CP_WAIT2(); } else if (ch == 7) { CP_WAIT1(); } else { CP_WAIT0(); }
        __syncthreads();
        if (ch < 6) ISSUE((ch + 3) & 3, (ch + 3) * 32);

        const uint32_t sb = smb + (ch & 3) * 17920;
#pragma unroll
        for (int s = 0; s < 2; s++) {
            const int so = s * 32;
            uint32_t af[3][4], bf[2][4];
#pragma unroll
            for (int mt = 0; mt < 3; mt++)
                ldsm4(af[mt][0], af[mt][1], af[mt][2], af[mt][3], sb + aoff[mt] + so);
#pragma unroll
            for (int p = 0; p < 2; p++)
                ldsm4(bf[p][0], bf[p][1], bf[p][2], bf[p][3], sb + boff[p] + so);
#pragma unroll
            for (int mt = 0; mt < 3; mt++)
#pragma unroll
                for (int nt = 0; nt < 4; nt++)
                    mma16(acc[mt][nt], af[mt][0], af[mt][1], af[mt][2], af[mt][3],
                          bf[nt >> 1][(nt & 1) * 2], bf[nt >> 1][(nt & 1) * 2 + 1]);
        }
    }
#undef ISSUE
    __syncthreads();

    float* stg = smf;                  // [96][133]
#pragma unroll
    for (int mt = 0; mt < 3; mt++) {
        int r0 = wm * 48 + mt * 16 + qr;
#pragma unroll
        for (int nt = 0; nt < 4; nt++) {
            int c0 = wn * 32 + nt * 8 + 2 * qc;
            stg[r0 * 133 + c0]           = acc[mt][nt][0];
            stg[r0 * 133 + c0 + 1]       = acc[mt][nt][1];
            stg[(r0 + 8) * 133 + c0]     = acc[mt][nt][2];
            stg[(r0 + 8) * 133 + c0 + 1] = acc[mt][nt][3];
        }
    }
    __syncthreads();

#pragma unroll
    for (int i = 0; i < 6; i++) {
        int idx = tid + i * 256;
        int t = idx / 12, q = idx - t * 12;
        uint32_t u0 = pack_h2(stg[(q * 8 + 0) * 133 + t], stg[(q * 8 + 1) * 133 + t]);
        uint32_t u1 = pack_h2(stg[(q * 8 + 2) * 133 + t], stg[(q * 8 + 3) * 133 + t]);
        uint32_t u2 = pack_h2(stg[(q * 8 + 4) * 133 + t], stg[(q * 8 + 5) * 133 + t]);
        uint32_t u3 = pack_h2(stg[(q * 8 + 6) * 133 + t], stg[(q * 8 + 7) * 133 + t]);
        *(uint4*)(Ch + (size_t)(n0 + t) * QKV_N + m0 + q * 8) = make_uint4(u0, u1, u2, u3);
    }
    if (m0 >= 2 * CDIM) {
#pragma unroll
        for (int i = 0; i < 6; i++) {
            int idx = tid + i * 256;
            int m = idx >> 4, c8 = (idx & 15) * 8;
            uint32_t u0 = pack_h2(stg[m * 133 + c8 + 0], stg[m * 133 + c8 + 1]);
            uint32_t u1 = pack_h2(stg[m * 133 + c8 + 2], stg[m * 133 + c8 + 3]);
            uint32_t u2 = pack_h2(stg[m * 133 + c8 + 4], stg[m * 133 + c8 + 5]);
            uint32_t u3 = pack_h2(stg[m * 133 + c8 + 6], stg[m * 133 + c8 + 7]);
            *(uint4*)(vc + ((size_t)bb * CDIM + (m0 - 2 * CDIM) + m) * L_TOT + l0 + c8)
                = make_uint4(u0, u1, u2, u3);
        }
    }
}

// ==================== GEMM2: out = y @ Wp^T + lcm^T @ Wp^T + bias ====================
// cp.async 2-stage (3 CTAs/SM); per stage: A 96x32 (7680B), By 128x32 (10240B),
// Lc 32k x 128tok channel-major (272B rows, 8704B). Stage = 26624B.
#define G2_STAGE 26624
#define G2_SMEM  (2 * G2_STAGE)     // 53248

__global__ __launch_bounds__(256)
void gemm2_kernel(const __half* __restrict__ Aw, const __half* __restrict__ By,
                  const __half* __restrict__ lcm, float* __restrict__ Cf,
                  const float* __restrict__ bias) {
    extern __shared__ float smf[];
    const uint32_t smb = smem_u32_of(smf);
    const int tid = threadIdx.x, lane = tid & 31, warp = tid >> 5;
    const int qr = lane >> 2, qc = lane & 3;
    const int wm = warp & 1, wn = warp >> 1;
    const int n0 = blockIdx.x * 128;
    const int m0 = blockIdx.y * 96;
    const int bb = n0 >> 15;
    const int l0 = n0 & (L_TOT - 1);

    const int g8 = lane >> 3, lr = lane & 7;
    const int rowA = lr + (g8 & 1) * 8, colA = (g8 >> 1) * 16;
    const int rowB = lr + (g8 >> 1) * 8, colB = (g8 & 1) * 16;
    uint32_t aoff[3], byoff[2], lcoff[2];
#pragma unroll
    for (int mt = 0; mt < 3; mt++)
        aoff[mt] = (wm * 48 + mt * 16 + rowA) * 80 + colA;
#pragma unroll
    for (int p = 0; p < 2; p++) {
        byoff[p] = 7680 + (wn * 32 + p * 16 + rowB) * 80 + colB;
        lcoff[p] = 17920 + ((g8 & 1) * 8 + lr) * 272
                 + (wn * 32 + p * 16 + (g8 >> 1) * 8) * 2;
    }

    float acc[3][4][4];
#pragma unroll
    for (int mt = 0; mt < 3; mt++)
#pragma unroll
        for (int nt = 0; nt < 4; nt++)
#pragma unroll
            for (int r = 0; r < 4; r++) acc[mt][nt][r] = 0.0f;

#define ISSUE2(S, K0) do { \
    uint32_t base = smb + (S) * G2_STAGE; \
    { int r = tid >> 2, c = tid & 3; \
      CP16(base + r * 80 + c * 16, Aw + (size_t)(m0 + r) * CDIM + (K0) + c * 8); } \
    if (tid < 128) { int idx = tid + 256; \
      int r = idx >> 2, c = idx & 3; \
      CP16(base + r * 80 + c * 16, Aw + (size_t)(m0 + r) * CDIM + (K0) + c * 8); } \
    _Pragma("unroll") for (int i = 0; i < 2; i++) { \
      int idx = tid + i * 256; \
      int r = idx >> 2, c = idx & 3; \
      CP16(base + 7680 + r * 80 + c * 16, By + (size_t)(n0 + r) * CDIM + (K0) + c * 8); } \
    _Pragma("unroll") for (int i = 0; i < 2; i++) { \
      int idx = tid + i * 256; \
      int r = idx >> 4, c = idx & 15; \
      CP16(base + 17920 + r * 272 + c * 16, \
           lcm + ((size_t)bb * CDIM + (K0) + r) * L_TOT + l0 + c * 8); } \
    CP_COMMIT(); \
} while (0)

    ISSUE2(0, 0);
    ISSUE2(1, 32);

#pragma unroll 1
    for (int ch = 0; ch < 9; ch++) {
        if (ch < 8) { CP_WAIT1(); } else { CP_WAIT0(); }
        __syncthreads();

        const uint32_t sb = smb + (ch & 1) * G2_STAGE;
#pragma unroll
        for (int s = 0; s < 2; s++) {
            uint32_t af[3][4], bfY[2][4], bfL[2][4];
#pragma unroll
            for (int mt = 0; mt < 3; mt++)
                ldsm4(af[mt][0], af[mt][1], af[mt][2], af[mt][3], sb + aoff[mt] + s * 32);
#pragma unroll
            for (int p = 0; p < 2; p++)
                ldsm4(bfY[p][0], bfY[p][1], bfY[p][2], bfY[p][3], sb + byoff[p] + s * 32);
#pragma unroll
            for (int p = 0; p < 2; p++)
                ldsm4t(bfL[p][0], bfL[p][1], bfL[p][2], bfL[p][3], sb + lcoff[p] + s * 4352);
#pragma unroll
            for (int mt = 0; mt < 3; mt++)
#pragma unroll
                for (int nt = 0; nt < 4; nt++) {
                    mma16(acc[mt][nt], af[mt][0], af[mt][1], af[mt][2], af[mt][3],
                          bfY[nt >> 1][(nt & 1) * 2], bfY[nt >> 1][(nt & 1) * 2 + 1]);
                    mma16(acc[mt][nt], af[mt][0], af[mt][1], af[mt][2], af[mt][3],
                          bfL[nt >> 1][(nt & 1) * 2], bfL[nt >> 1][(nt & 1) * 2 + 1]);
                }
        }

        if (ch < 7) {
            __syncthreads();                 // stage (ch&1) free for refill
            ISSUE2(ch & 1, (ch + 2) * 32);
        }
    }
#undef ISSUE2
    __syncthreads();

    float* stg = smf;                  // [96][133]
#pragma unroll
    for (int mt = 0; mt < 3; mt++) {
        int r0 = wm * 48 + mt * 16 + qr;
#pragma unroll
        for (int nt = 0; nt < 4; nt++) {
            int c0 = wn * 32 + nt * 8 + 2 * qc;
            stg[r0 * 133 + c0]           = acc[mt][nt][0];
            stg[r0 * 133 + c0 + 1]       = acc[mt][nt][1];
            stg[(r0 + 8) * 133 + c0]     = acc[mt][nt][2];
            stg[(r0 + 8) * 133 + c0 + 1] = acc[mt][nt][3];
        }
    }
    __syncthreads();

#pragma unroll
    for (int i = 0; i < 12; i++) {
        int idx = tid + i * 256;
        int t = idx / 24, q = idx - t * 24;
        float4 o;
        o.x = stg[(q * 4 + 0) * 133 + t] + bias[m0 + q * 4 + 0];
        o.y = stg[(q * 4 + 1) * 133 + t] + bias[m0 + q * 4 + 1];
        o.z = stg[(q * 4 + 2) * 133 + t] + bias[m0 + q * 4 + 2];
        o.w = stg[(q * 4 + 3) * 133 + t] + bias[m0 + q * 4 + 3];
        *(float4*)(Cf + (size_t)(n0 + t) * CDIM + m0 + q * 4) = o;
    }
}

// ==================== fused conv + attention ====================
#define CONV_BLOCKS (BATCH * CDIM * 2)        // 1152
#define ATTN_BLOCKS 6144
#define FUSE_BLOCKS (CONV_BLOCKS + ATTN_BLOCKS)

__global__ __launch_bounds__(128)
void attn_conv_kernel(const __half* __restrict__ qkv, const float* __restrict__ biasb,
                      __half* __restrict__ y, const __half* __restrict__ vc,
                      const float* __restrict__ cw, const float* __restrict__ cb,
                      __half* __restrict__ lcm) {
    __shared__ float shm[7168];
    const int tid = threadIdx.x;

    if (blockIdx.x >= CONV_BLOCKS) {
        const int abid = blockIdx.x - CONV_BLOCKS;
        const int bi = abid / 2048;
        const int rem = abid - bi * 2048;
        const int b = rem >> 10;
        const int pair = rem & 1023;
        const int Dsp = c_Dsp[bi], Hsp = c_Hsp[bi], Wsp = c_Wsp[bi];
        const int nH = RESV / Hsp, nW = RESV / Wsp;
        const int g  = tid >> 6;
        const int tl = tid & 63;
        int widx = pair * 2 + g;
        int wblk = widx % nW; int tmp = widx / nW;
        int hblk = tmp % nH;  int dblk = tmp / nH;

        const int hb = tl >> 4;
        const int n  = tl & 15;
        const int HW = Hsp * Wsp;
        int dd = n / HW; int r = n - dd * HW;
        int hh = r / Wsp; int ww = r - hh * Wsp;
        int l = ((dblk * Dsp + dd) * RESV + hblk * Hsp + hh) * RESV + wblk * Wsp + ww;

        size_t rowbase = ((size_t)b * L_TOT + l) * QKV_N + bi * 96 + hb * HDIM;

        float* skr = shm + g * 1792;          // [64][28]
        float* svr = shm + 3584 + g * 1792;
        float q[HDIM];
        const float scale = 0.2041241452319315f;

        const uint4* qp = (const uint4*)(qkv + rowbase);
        const uint4* kp = (const uint4*)(qkv + rowbase + CDIM);
        const uint4* vp = (const uint4*)(qkv + rowbase + 2 * CDIM);
#pragma unroll
        for (int j = 0; j < 3; j++) {
            uint4 uq = qp[j], uk = kp[j], uv = vp[j];
            __half2* hq = (__half2*)&uq;
            __half2* hk = (__half2*)&uk;
            __half2* hv = (__half2*)&uv;
            float kk[8], vv[8];
#pragma unroll
            for (int e = 0; e < 4; e++) {
                float2 fq = __half22float2(hq[e]);
                q[8 * j + 2 * e]     = fq.x * scale;
                q[8 * j + 2 * e + 1] = fq.y * scale;
                float2 fk = __half22float2(hk[e]);
                kk[2 * e] = fk.x; kk[2 * e + 1] = fk.y;
                float2 fv = __half22float2(hv[e]);
                vv[2 * e] = fv.x; vv[2 * e + 1] = fv.y;
            }
            *(float4*)(skr + tl * 28 + 8 * j)     = make_float4(kk[0], kk[1], kk[2], kk[3]);
            *(float4*)(skr + tl * 28 + 8 * j + 4) = make_float4(kk[4], kk[5], kk[6], kk[7]);
            *(float4*)(svr + tl * 28 + 8 * j)     = make_float4(vv[0], vv[1], vv[2], vv[3]);
            *(float4*)(svr + tl * 28 + 8 * j + 4) = make_float4(vv[4], vv[5], vv[6], vv[7]);
        }
        __syncthreads();

        const float* brow = biasb + (((size_t)bi * HB + hb) * NWIN + n) * NWIN;
        float lg[NWIN];
        float mx = -1e30f;
#pragma unroll
        for (int m = 0; m < NWIN; m++) {
            float s = brow[m];
            const float4* kr = (const float4*)(skr + (hb * 16 + m) * 28);
#pragma unroll
            for (int e4 = 0; e4 < 6; e4++) {
                float4 kk = kr[e4];
                s = fmaf(q[4 * e4 + 0], kk.x, s);
                s = fmaf(q[4 * e4 + 1], kk.y, s);
                s = fmaf(q[4 * e4 + 2], kk.z, s);
                s = fmaf(q[4 * e4 + 3], kk.w, s);
            }
            lg[m] = s;
            mx = fmaxf(mx, s);
        }
        float sum = 0.f;
#pragma unroll
        for (int m = 0; m < NWIN; m++) { lg[m] = __expf(lg[m] - mx); sum += lg[m]; }
        float inv = 1.0f / sum;

        float o[HDIM];
#pragma unroll
        for (int e = 0; e < HDIM; e++) o[e] = 0.f;
#pragma unroll
        for (int m = 0; m < NWIN; m++) {
            float w = lg[m] * inv;
            const float4* vr = (const float4*)(svr + (hb * 16 + m) * 28);
#pragma unroll
            for (int e4 = 0; e4 < 6; e4++) {
                float4 vv = vr[e4];
                o[4 * e4 + 0] = fmaf(w, vv.x, o[4 * e4 + 0]);
                o[4 * e4 + 1] = fmaf(w, vv.y, o[4 * e4 + 1]);
                o[4 * e4 + 2] = fmaf(w, vv.z, o[4 * e4 + 2]);
                o[4 * e4 + 3] = fmaf(w, vv.w, o[4 * e4 + 3]);
            }
        }

        __half* yp = y + ((size_t)b * L_TOT + l) * CDIM + bi * 96 + hb * HDIM;
#pragma unroll
        for (int j = 0; j < 3; j++) {
            uint32_t u0 = pack_h2(o[8 * j + 0], o[8 * j + 1]);
            uint32_t u1 = pack_h2(o[8 * j + 2], o[8 * j + 3]);
            uint32_t u2 = pack_h2(o[8 * j + 4], o[8 * j + 5]);
            uint32_t u3 = pack_h2(o[8 * j + 6], o[8 * j + 7]);
            *(uint4*)(yp + 8 * j) = make_uint4(u0, u1, u2, u3);
        }
        return;
    }

    // -------- depthwise 3x3x3 conv, d split in halves --------
    const int bc  = blockIdx.x >> 1;
    const int dlo = (blockIdx.x & 1) * 16;
    const int dhi = dlo + 16;
    const int c = bc % CDIM;
    const __half* src = vc + (size_t)bc * L_TOT;
    __half* dst = lcm + (size_t)bc * L_TOT;

    float wt[27];
#pragma unroll
    for (int j = 0; j < 27; j++) wt[j] = cw[c * 27 + j];
    const float bias = cb[c];

    float* sp = shm;
    const int w = tid & 31;
    const int h0 = (tid >> 5) * 8;

    for (int i = tid; i < 3 * 34 * 36; i += 128) sp[i] = 0.f;
    __syncthreads();
    {
        float* s0 = sp + (dlo % 3) * 1224;
        float* s1 = sp + ((dlo + 1) % 3) * 1224;
#pragma unroll
        for (int jh = 0; jh < 8; jh++) {
            int h = h0 + jh;
            s0[(1 + h) * 36 + 1 + w] = __half2float(src[dlo * 1024 + h * 32 + w]);
            s1[(1 + h) * 36 + 1 + w] = __half2float(src[(dlo + 1) * 1024 + h * 32 + w]);
        }
        if (dlo > 0) {
            float* sm1 = sp + ((dlo + 2) % 3) * 1224;
#pragma unroll
            for (int jh = 0; jh < 8; jh++) {
                int h = h0 + jh;
                sm1[(1 + h) * 36 + 1 + w] = __half2float(src[(dlo - 1) * 1024 + h * 32 + w]);
            }
        }
    }
    __syncthreads();

#pragma unroll 1
    for (int d = dlo; d < dhi; d++) {
        const int bm = (d + 2) % 3;
        const int b0 = d % 3;
        const int bp = (d + 1) % 3;
        float acc[8];
#pragma unroll
        for (int jh = 0; jh < 8; jh++) acc[jh] = bias;

#define TAPS(BUF, KD) { \
        const float* P = sp + (BUF) * 1224; \
        _Pragma("unroll") \
        for (int rr = 0; rr < 10; rr++) { \
            float va = P[(h0 + rr) * 36 + w], vb = P[(h0 + rr) * 36 + w + 1], \
                  vcx = P[(h0 + rr) * 36 + w + 2]; \
            _Pragma("unroll") \
            for (int jh = 0; jh < 8; jh++) { \
                int kh = rr - jh; \
                if (kh >= 0 && kh < 3) { \
                    acc[jh] = fmaf(wt[(KD)*9 + kh*3 + 0], va, \
                              fmaf(wt[(KD)*9 + kh*3 + 1], vb, \
                              fmaf(wt[(KD)*9 + kh*3 + 2], vcx, acc[jh]))); \
                } \
            } \
        } }

        if (d > 0)  TAPS(bm, 0);
        TAPS(b0, 1);
        if (d < 31) TAPS(bp, 2);
#undef TAPS

#pragma unroll
        for (int jh = 0; jh < 8; jh++)
            dst[d * 1024 + (h0 + jh) * 32 + w] = __float2half(acc[jh]);

        __syncthreads();
        if (d + 2 <= dhi && d + 2 < 32 && d < dhi - 1) {
            const __half* s2 = src + (d + 2) * 1024;
            float* spn = sp + ((d + 2) % 3) * 1224;
#pragma unroll
            for (int jh = 0; jh < 8; jh++) {
                int h = h0 + jh;
                spn[(1 + h) * 36 + 1 + w] = __half2float(s2[h * 32 + w]);
            }
        }
        __syncthreads();
    }
}

// ==================== launch ====================
extern "C" void kernel_launch(void* const* d_in, const int* in_sizes, int n_in,
                              void* d_out, int out_size) {
    const float* x      = (const float*)d_in[0];
    const float* w_qkv  = (const float*)d_in[4];
    const float* w_proj = (const float*)d_in[5];
    const float* b_proj = (const float*)d_in[6];
    const float* conv_w = (const float*)d_in[7];
    const float* conv_b = (const float*)d_in[8];
    const float* pos_w  = (const float*)d_in[9];
    const float* pos_b  = (const float*)d_in[10];
    const float* ln1g   = (const float*)d_in[11];
    const float* ln1b   = (const float*)d_in[12];
    const float* lin1w  = (const float*)d_in[13];
    const float* lin1b  = (const float*)d_in[14];
    const float* ln2g   = (const float*)d_in[15];
    const float* ln2b   = (const float*)d_in[16];
    const float* lin2w  = (const float*)d_in[17];
    const float* lin2b  = (const float*)d_in[18];
    const float* ln3g   = (const float*)d_in[19];
    const float* ln3b   = (const float*)d_in[20];
    const float* lin3w  = (const float*)d_in[21];
    const float* lin3b  = (const float*)d_in[22];
    const float* rpe    = (const float*)d_in[23];
    const int*   relidx = (const int*)d_in[24];
    float* out = (float*)d_out;

    __half *xhp, *qkvp, *yp, *vcp, *lcmp, *wqkvT, *wprojT;
    float *bp;
    cudaGetSymbolAddress((void**)&xhp,    g_xh);
    cudaGetSymbolAddress((void**)&qkvp,   g_qkv);
    cudaGetSymbolAddress((void**)&yp,     g_y);
    cudaGetSymbolAddress((void**)&bp,     g_bias);
    cudaGetSymbolAddress((void**)&vcp,    g_vc);
    cudaGetSymbolAddress((void**)&lcmp,   g_lcm);
    cudaGetSymbolAddress((void**)&wqkvT,  g_wqkvT);
    cudaGetSymbolAddress((void**)&wprojT, g_wprojT);

    cudaFuncSetAttribute(gemm1_kernel, cudaFuncAttributeMaxDynamicSharedMemorySize, G1_SMEM);
    cudaFuncSetAttribute(gemm2_kernel, cudaFuncAttributeMaxDynamicSharedMemorySize, G2_SMEM);

    // 0) fused prep: biasmlp + x->half + weight transposes
    prep_kernel<<<PREP_BLOCKS, 256>>>(x, xhp, w_qkv, wqkvT, w_proj, wprojT,
                                      rpe, pos_w, pos_b,
                                      ln1g, ln1b, lin1w, lin1b,
                                      ln2g, ln2b, lin2w, lin2b,
                                      ln3g, ln3b, lin3w, lin3b,
                                      relidx, bp);

    // 1) qkv = xh @ w_qkv  (also writes v channel-major into vc)
    gemm1_kernel<<<dim3(NROWS / 128, QKV_N / 96), 256, G1_SMEM>>>(wqkvT, xhp, qkvp, vcp);

    // 2) fused conv (front) + attention
    attn_conv_kernel<<<FUSE_BLOCKS, 128>>>(qkvp, bp, yp, vcp, conv_w, conv_b, lcmp);

    // 3) out = y @ Wp^T + lcm^T @ Wp^T + bias   (ncu slot)
    gemm2_kernel<<<dim3(NROWS / 128, CDIM / 96), 256, G2_SMEM>>>(wprojT, yp, lcmp, out, b_proj);
}